// round 1
// baseline (speedup 1.0000x reference)
#include <cuda_runtime.h>
#include <math.h>

// ---- problem constants ----
#define T_TOK 4096      // B*S
#define SEQ   2048
#define BATCH 2
#define HDIM  768
#define NHEADS 12
#define HEADD 64
#define IDIM  2048
#define NEXP  8

// ---- scratch (static __device__, allocation-free) ----
__device__ float g_xn  [T_TOK*HDIM];
__device__ float g_q   [T_TOK*HDIM];
__device__ float g_k   [T_TOK*HDIM];
__device__ float g_v   [T_TOK*HDIM];
__device__ float g_qr  [T_TOK*HDIM];
__device__ float g_kr  [T_TOK*HDIM];
__device__ float g_vr  [T_TOK*HDIM];
__device__ float g_attn[T_TOK*HDIM];
__device__ float g_x1  [T_TOK*HDIM];
__device__ float g_x1n [T_TOK*HDIM];
__device__ float g_cos [SEQ*32];
__device__ float g_sin [SEQ*32];
__device__ float g_lse2[T_TOK];
__device__ int   g_cnt [NEXP];
__device__ int   g_rows[NEXP*T_TOK];
__device__ float g_rwt [NEXP*T_TOK];
__device__ float g_xg  [T_TOK*HDIM];
__device__ float g_hg  [T_TOK*IDIM];
__device__ float g_hu  [T_TOK*IDIM];
__device__ float g_dg  [T_TOK*HDIM];

// ---------------- RMSNorm ----------------
__global__ void rmsnorm_kernel(const float* __restrict__ x, const float* __restrict__ w,
                               float* __restrict__ out) {
    int row = blockIdx.x;
    const float* xr = x + (size_t)row * HDIM;
    float s = 0.f;
    for (int c = threadIdx.x; c < HDIM; c += 256) { float v = xr[c]; s += v * v; }
    __shared__ float red[8];
    for (int o = 16; o; o >>= 1) s += __shfl_xor_sync(0xffffffffu, s, o);
    if ((threadIdx.x & 31) == 0) red[threadIdx.x >> 5] = s;
    __syncthreads();
    if (threadIdx.x < 8) {
        float v = red[threadIdx.x];
        for (int o = 4; o; o >>= 1) v += __shfl_xor_sync(0xffu, v, o);
        if (threadIdx.x == 0) red[0] = v;
    }
    __syncthreads();
    float scale = rsqrtf(red[0] / (float)HDIM + 1e-6f);
    for (int c = threadIdx.x; c < HDIM; c += 256)
        out[(size_t)row * HDIM + c] = w[c] * xr[c] * scale;
}

// ---------------- generic SGEMM: C[M,N] = A[M,K] @ B[K,N] (+Cadd) ----------------
// BM=BN=128, BK=8, 256 threads, 8x8 microtile. M can come from device (*Mptr).
__global__ __launch_bounds__(256) void sgemm_kernel(
    const float* __restrict__ A, const float* __restrict__ B, float* __restrict__ C,
    int M, const int* __restrict__ Mptr, int N, int K, const float* __restrict__ Cadd)
{
    int m = Mptr ? *Mptr : M;
    int row0 = blockIdx.y * 128;
    if (row0 >= m) return;
    int col0 = blockIdx.x * 128;

    __shared__ float As[8][128];
    __shared__ float Bs[8][128];

    int tid = threadIdx.x;
    int arow = tid >> 1, acol = (tid & 1) << 2;
    int brow = tid >> 5, bcol = (tid & 31) << 2;
    const float* Ap = A + (size_t)(row0 + arow) * K + acol;
    const float* Bp = B + (size_t)brow * N + col0 + bcol;
    bool aval = (row0 + arow) < m;

    float acc[8][8];
#pragma unroll
    for (int i = 0; i < 8; i++)
#pragma unroll
        for (int j = 0; j < 8; j++) acc[i][j] = 0.f;

    int ty = tid >> 4, tx = tid & 15;

    for (int k0 = 0; k0 < K; k0 += 8) {
        float4 av = aval ? *(const float4*)Ap : make_float4(0.f, 0.f, 0.f, 0.f);
        As[acol + 0][arow] = av.x; As[acol + 1][arow] = av.y;
        As[acol + 2][arow] = av.z; As[acol + 3][arow] = av.w;
        *(float4*)&Bs[brow][bcol] = *(const float4*)Bp;
        __syncthreads();
#pragma unroll
        for (int kk = 0; kk < 8; kk++) {
            float4 a0 = *(const float4*)&As[kk][ty * 8];
            float4 a1 = *(const float4*)&As[kk][ty * 8 + 4];
            float4 b0 = *(const float4*)&Bs[kk][tx * 8];
            float4 b1 = *(const float4*)&Bs[kk][tx * 8 + 4];
            float ra[8] = {a0.x, a0.y, a0.z, a0.w, a1.x, a1.y, a1.z, a1.w};
            float rb[8] = {b0.x, b0.y, b0.z, b0.w, b1.x, b1.y, b1.z, b1.w};
#pragma unroll
            for (int i = 0; i < 8; i++)
#pragma unroll
                for (int j = 0; j < 8; j++) acc[i][j] += ra[i] * rb[j];
        }
        __syncthreads();
        Ap += 8; Bp += (size_t)8 * N;
    }

#pragma unroll
    for (int i = 0; i < 8; i++) {
        int r = row0 + ty * 8 + i;
        if (r >= m) break;
        float* cp = C + (size_t)r * N + col0 + tx * 8;
        if (Cadd) {
            const float* ap = Cadd + (size_t)r * N + col0 + tx * 8;
            float4 c0 = *(const float4*)ap, c1 = *(const float4*)(ap + 4);
            float4 o0 = make_float4(acc[i][0] + c0.x, acc[i][1] + c0.y, acc[i][2] + c0.z, acc[i][3] + c0.w);
            float4 o1 = make_float4(acc[i][4] + c1.x, acc[i][5] + c1.y, acc[i][6] + c1.z, acc[i][7] + c1.w);
            *(float4*)cp = o0; *(float4*)(cp + 4) = o1;
        } else {
            float4 o0 = make_float4(acc[i][0], acc[i][1], acc[i][2], acc[i][3]);
            float4 o1 = make_float4(acc[i][4], acc[i][5], acc[i][6], acc[i][7]);
            *(float4*)cp = o0; *(float4*)(cp + 4) = o1;
        }
    }
}

// ---------------- RoPE ----------------
__global__ void rope_table_kernel() {
    int idx = blockIdx.x * blockDim.x + threadIdx.x;
    if (idx >= SEQ * 32) return;
    int i = idx & 31, s = idx >> 5;
    float inv = powf(10000.0f, -(float)i / 32.0f);
    float ang = (float)s * inv;
    g_cos[idx] = cosf(ang);
    g_sin[idx] = sinf(ang);
}

// q,k: [T,H] -> roped [B,NH,S,HD]; v: transpose copy
__global__ void rope_kernel() {
    int s = blockIdx.x, h = blockIdx.y, b = blockIdx.z, d = threadIdx.x;
    int t = b * SEQ + s;
    int src  = t * HDIM + h * HEADD + d;
    int psrc = t * HDIM + h * HEADD + (d < 32 ? d + 32 : d - 32);
    int dst  = ((b * NHEADS + h) * SEQ + s) * HEADD + d;
    float cs = g_cos[s * 32 + (d & 31)], sn = g_sin[s * 32 + (d & 31)];
    float sgn = (d < 32) ? -1.f : 1.f;
    g_qr[dst] = g_q[src] * cs + sgn * g_q[psrc] * sn;
    g_kr[dst] = g_k[src] * cs + sgn * g_k[psrc] * sn;
    g_vr[dst] = g_v[src];
}

// ---------------- flash attention (causal, fp32, HD=64) ----------------
// grid (S/64, NH, B), 128 threads. Each thread: 4 rows x 8 cols.
__global__ __launch_bounds__(128) void flash_kernel(float* __restrict__ O) {
    int qt = blockIdx.x, h = blockIdx.y, b = blockIdx.z;
    __shared__ float sQT[64][64];   // [d][row]
    __shared__ float sKP[64][64];   // K^T [d][key], reused as P^T [key][row]
    __shared__ float sV [64][64];   // [key][d]

    int tid = threadIdx.x;
    const float* Qb = g_qr + (size_t)((b * NHEADS + h) * SEQ) * HEADD;
    const float* Kb = g_kr + (size_t)((b * NHEADS + h) * SEQ) * HEADD;
    const float* Vb = g_vr + (size_t)((b * NHEADS + h) * SEQ) * HEADD;

    {   // load Q tile transposed
        int d4 = (tid & 15) * 4, i0 = tid >> 4;
        for (int i = i0; i < 64; i += 8) {
            float4 v = *(const float4*)(Qb + (size_t)(qt * 64 + i) * 64 + d4);
            sQT[d4 + 0][i] = v.x; sQT[d4 + 1][i] = v.y;
            sQT[d4 + 2][i] = v.z; sQT[d4 + 3][i] = v.w;
        }
    }

    int c  = tid & 7;    // col group (8 keys / 8 dims)
    int rq = tid >> 3;   // row group (4 rows)
    float m[4], l[4], o[4][8];
#pragma unroll
    for (int u = 0; u < 4; u++) {
        m[u] = -INFINITY; l[u] = 0.f;
#pragma unroll
        for (int j = 0; j < 8; j++) o[u][j] = 0.f;
    }
    const float scale = 0.125f;  // 1/sqrt(64)
    int rbase = qt * 64 + rq * 4;

    for (int kt = 0; kt <= qt; kt++) {
        __syncthreads();  // prior-iter reads of sKP/sV done; also guards sQT on first iter
        {   // load K^T and V for this tile
            int d4 = (tid & 15) * 4, i0 = tid >> 4;
            for (int i = i0; i < 64; i += 8) {
                float4 kv = *(const float4*)(Kb + (size_t)(kt * 64 + i) * 64 + d4);
                sKP[d4 + 0][i] = kv.x; sKP[d4 + 1][i] = kv.y;
                sKP[d4 + 2][i] = kv.z; sKP[d4 + 3][i] = kv.w;
                float4 vv = *(const float4*)(Vb + (size_t)(kt * 64 + i) * 64 + d4);
                *(float4*)&sV[i][d4] = vv;
            }
        }
        __syncthreads();

        float sc[4][8];
#pragma unroll
        for (int u = 0; u < 4; u++)
#pragma unroll
            for (int j = 0; j < 8; j++) sc[u][j] = 0.f;

#pragma unroll 8
        for (int kk = 0; kk < 64; kk++) {
            float4 q4  = *(const float4*)&sQT[kk][rq * 4];
            float4 k40 = *(const float4*)&sKP[kk][c * 8];
            float4 k41 = *(const float4*)&sKP[kk][c * 8 + 4];
            float qa[4] = {q4.x, q4.y, q4.z, q4.w};
            float kb8[8] = {k40.x, k40.y, k40.z, k40.w, k41.x, k41.y, k41.z, k41.w};
#pragma unroll
            for (int u = 0; u < 4; u++)
#pragma unroll
                for (int j = 0; j < 8; j++) sc[u][j] += qa[u] * kb8[j];
        }

        int kbase = kt * 64 + c * 8;
#pragma unroll
        for (int u = 0; u < 4; u++) {
#pragma unroll
            for (int j = 0; j < 8; j++)
                sc[u][j] = (kbase + j <= rbase + u) ? sc[u][j] * scale : -1e30f;
            float mt = sc[u][0];
#pragma unroll
            for (int j = 1; j < 8; j++) mt = fmaxf(mt, sc[u][j]);
            for (int ox = 1; ox < 8; ox <<= 1)
                mt = fmaxf(mt, __shfl_xor_sync(0xffffffffu, mt, ox));
            float mn = fmaxf(m[u], mt);
            float alpha = expf(m[u] - mn);
            float ps = 0.f;
#pragma unroll
            for (int j = 0; j < 8; j++) { float p = expf(sc[u][j] - mn); sc[u][j] = p; ps += p; }
            for (int ox = 1; ox < 8; ox <<= 1)
                ps += __shfl_xor_sync(0xffffffffu, ps, ox);
            l[u] = l[u] * alpha + ps;
            m[u] = mn;
#pragma unroll
            for (int j = 0; j < 8; j++) o[u][j] *= alpha;
        }

        __syncthreads();  // all score reads of sKP done before overwriting with P^T
#pragma unroll
        for (int j = 0; j < 8; j++) {
            float4 pv = make_float4(sc[0][j], sc[1][j], sc[2][j], sc[3][j]);
            *(float4*)&sKP[c * 8 + j][rq * 4] = pv;
        }
        __syncthreads();

#pragma unroll 8
        for (int k = 0; k < 64; k++) {
            float4 p4 = *(const float4*)&sKP[k][rq * 4];
            float4 v0 = *(const float4*)&sV[k][c * 8];
            float4 v1 = *(const float4*)&sV[k][c * 8 + 4];
            float pu[4] = {p4.x, p4.y, p4.z, p4.w};
            float vj[8] = {v0.x, v0.y, v0.z, v0.w, v1.x, v1.y, v1.z, v1.w};
#pragma unroll
            for (int u = 0; u < 4; u++)
#pragma unroll
                for (int j = 0; j < 8; j++) o[u][j] += pu[u] * vj[j];
        }
    }

#pragma unroll
    for (int u = 0; u < 4; u++) {
        float inv = 1.0f / l[u];
        int row = rbase + u;
        float* op = O + (size_t)(b * SEQ + row) * HDIM + h * HEADD + c * 8;
        float4 o0 = make_float4(o[u][0] * inv, o[u][1] * inv, o[u][2] * inv, o[u][3] * inv);
        float4 o1 = make_float4(o[u][4] * inv, o[u][5] * inv, o[u][6] * inv, o[u][7] * inv);
        *(float4*)op = o0; *(float4*)(op + 4) = o1;
    }
}

// ---------------- MoE gating: logits, lse^2, top-2, token->expert assignment ----------------
__global__ void zero_cnt_kernel() { if (threadIdx.x < NEXP) g_cnt[threadIdx.x] = 0; }

__global__ void gate_kernel(const float* __restrict__ gw) {
    int t = blockIdx.x * 8 + (threadIdx.x >> 5);
    int lane = threadIdx.x & 31;
    const float* xr = g_x1n + (size_t)t * HDIM;
    float acc[8] = {0, 0, 0, 0, 0, 0, 0, 0};
    for (int j = lane; j < HDIM; j += 32) {
        float xv = xr[j];
        const float* gr = gw + j * 8;
        float4 g0 = *(const float4*)gr, g1 = *(const float4*)(gr + 4);
        acc[0] += xv * g0.x; acc[1] += xv * g0.y; acc[2] += xv * g0.z; acc[3] += xv * g0.w;
        acc[4] += xv * g1.x; acc[5] += xv * g1.y; acc[6] += xv * g1.z; acc[7] += xv * g1.w;
    }
#pragma unroll
    for (int e = 0; e < 8; e++)
        for (int o = 16; o; o >>= 1) acc[e] += __shfl_xor_sync(0xffffffffu, acc[e], o);
    if (lane == 0) {
        float mx = acc[0];
#pragma unroll
        for (int e = 1; e < 8; e++) mx = fmaxf(mx, acc[e]);
        float se = 0.f;
#pragma unroll
        for (int e = 0; e < 8; e++) se += expf(acc[e] - mx);
        float lse = mx + logf(se);
        g_lse2[t] = lse * lse;
        int i0 = 0; float v0 = acc[0];
#pragma unroll
        for (int e = 1; e < 8; e++) if (acc[e] > v0) { v0 = acc[e]; i0 = e; }
        int i1 = -1; float v1 = -INFINITY;
#pragma unroll
        for (int e = 0; e < 8; e++) if (e != i0 && acc[e] > v1) { v1 = acc[e]; i1 = e; }
        float w0 = 1.f / (1.f + expf(v1 - v0));
        float w1 = 1.f - w0;
        int p0 = atomicAdd(&g_cnt[i0], 1);
        g_rows[i0 * T_TOK + p0] = t; g_rwt[i0 * T_TOK + p0] = w0;
        int p1 = atomicAdd(&g_cnt[i1], 1);
        g_rows[i1 * T_TOK + p1] = t; g_rwt[i1 * T_TOK + p1] = w1;
    }
}

// deterministic aux reduction
__global__ void aux_kernel(float* __restrict__ out) {
    __shared__ float red[32];
    float s = 0.f;
    for (int i = threadIdx.x; i < T_TOK; i += 1024) s += g_lse2[i];
    for (int o = 16; o; o >>= 1) s += __shfl_xor_sync(0xffffffffu, s, o);
    if ((threadIdx.x & 31) == 0) red[threadIdx.x >> 5] = s;
    __syncthreads();
    if (threadIdx.x < 32) {
        float v = red[threadIdx.x];
        for (int o = 16; o; o >>= 1) v += __shfl_xor_sync(0xffffffffu, v, o);
        if (threadIdx.x == 0) out[(size_t)T_TOK * HDIM] = 0.001f * v / (float)T_TOK;
    }
}

__global__ void copyres_kernel(float* __restrict__ out) {
    int i = blockIdx.x * 256 + threadIdx.x;
    ((float4*)out)[i] = ((const float4*)g_x1)[i];
}

__global__ void gather_kernel(int e) {
    int r = blockIdx.x;
    if (r >= g_cnt[e]) return;
    int t = g_rows[e * T_TOK + r];
    ((float4*)(g_xg + (size_t)r * HDIM))[threadIdx.x] =
        ((const float4*)(g_x1n + (size_t)t * HDIM))[threadIdx.x];
}

__global__ void silu_kernel(int e) {
    int r = blockIdx.x;
    if (r >= g_cnt[e]) return;
    float4* hg4 = (float4*)(g_hg + (size_t)r * IDIM);
    const float4* hu4 = (const float4*)(g_hu + (size_t)r * IDIM);
    for (int i = threadIdx.x; i < IDIM / 4; i += 256) {
        float4 a = hg4[i], b = hu4[i];
        a.x = a.x / (1.f + expf(-a.x)) * b.x;
        a.y = a.y / (1.f + expf(-a.y)) * b.y;
        a.z = a.z / (1.f + expf(-a.z)) * b.z;
        a.w = a.w / (1.f + expf(-a.w)) * b.w;
        hg4[i] = a;
    }
}

__global__ void scatter_kernel(int e, float* __restrict__ out) {
    int r = blockIdx.x;
    if (r >= g_cnt[e]) return;
    int t = g_rows[e * T_TOK + r];
    float w = g_rwt[e * T_TOK + r];
    float4* o = (float4*)(out + (size_t)t * HDIM);
    const float4* d = (const float4*)(g_dg + (size_t)r * HDIM);
    float4 ov = o[threadIdx.x], dv = d[threadIdx.x];
    ov.x += w * dv.x; ov.y += w * dv.y; ov.z += w * dv.z; ov.w += w * dv.w;
    o[threadIdx.x] = ov;
}

// ---------------- launch ----------------
extern "C" void kernel_launch(void* const* d_in, const int* in_sizes, int n_in,
                              void* d_out, int out_size) {
    const float* hidden = (const float*)d_in[0];
    // d_in[1] = attention_mask (pure causal; reproduced analytically)
    const float* wq    = (const float*)d_in[2];
    const float* wk    = (const float*)d_in[3];
    const float* wv    = (const float*)d_in[4];
    const float* wo    = (const float*)d_in[5];
    const float* ln1   = (const float*)d_in[6];
    const float* ln2   = (const float*)d_in[7];
    const float* gw    = (const float*)d_in[8];
    const float* wgate = (const float*)d_in[9];
    const float* wup   = (const float*)d_in[10];
    const float* wdown = (const float*)d_in[11];
    float* out = (float*)d_out;

    float *xn, *q, *k, *v, *attn, *x1, *x1n, *xg, *hg, *hu, *dg;
    int* cnt;
    cudaGetSymbolAddress((void**)&xn,  g_xn);
    cudaGetSymbolAddress((void**)&q,   g_q);
    cudaGetSymbolAddress((void**)&k,   g_k);
    cudaGetSymbolAddress((void**)&v,   g_v);
    cudaGetSymbolAddress((void**)&attn,g_attn);
    cudaGetSymbolAddress((void**)&x1,  g_x1);
    cudaGetSymbolAddress((void**)&x1n, g_x1n);
    cudaGetSymbolAddress((void**)&xg,  g_xg);
    cudaGetSymbolAddress((void**)&hg,  g_hg);
    cudaGetSymbolAddress((void**)&hu,  g_hu);
    cudaGetSymbolAddress((void**)&dg,  g_dg);
    cudaGetSymbolAddress((void**)&cnt, g_cnt);

    // 1. pre-attention RMSNorm
    rmsnorm_kernel<<<T_TOK, 256>>>(hidden, ln1, xn);

    // 2. QKV projections
    dim3 g77(HDIM / 128, T_TOK / 128);
    sgemm_kernel<<<g77, 256>>>(xn, wq, q, T_TOK, nullptr, HDIM, HDIM, nullptr);
    sgemm_kernel<<<g77, 256>>>(xn, wk, k, T_TOK, nullptr, HDIM, HDIM, nullptr);
    sgemm_kernel<<<g77, 256>>>(xn, wv, v, T_TOK, nullptr, HDIM, HDIM, nullptr);

    // 3. RoPE
    rope_table_kernel<<<(SEQ * 32 + 255) / 256, 256>>>();
    rope_kernel<<<dim3(SEQ, NHEADS, BATCH), 64>>>();

    // 4. causal flash attention -> [T,H]
    flash_kernel<<<dim3(SEQ / 64, NHEADS, BATCH), 128>>>(attn);

    // 5. output projection + residual
    sgemm_kernel<<<g77, 256>>>(attn, wo, x1, T_TOK, nullptr, HDIM, HDIM, hidden);

    // 6. post-attention RMSNorm
    rmsnorm_kernel<<<T_TOK, 256>>>(x1, ln2, x1n);

    // 7. gating + assignment + aux
    zero_cnt_kernel<<<1, 32>>>();
    gate_kernel<<<T_TOK / 8, 256>>>(gw);
    aux_kernel<<<1, 1024>>>(out);

    // 8. output := residual (x1); experts scatter-add on top
    copyres_kernel<<<(T_TOK * HDIM / 4) / 256, 256>>>(out);

    // 9. sparse MoE experts
    dim3 ggu(IDIM / 128, T_TOK / 128);
    dim3 ggd(HDIM / 128, T_TOK / 128);
    for (int e = 0; e < NEXP; e++) {
        gather_kernel<<<T_TOK, HDIM / 4>>>(e);
        sgemm_kernel<<<ggu, 256>>>(xg, wgate + (size_t)e * HDIM * IDIM, hg, 0, cnt + e, IDIM, HDIM, nullptr);
        sgemm_kernel<<<ggu, 256>>>(xg, wup   + (size_t)e * HDIM * IDIM, hu, 0, cnt + e, IDIM, HDIM, nullptr);
        silu_kernel<<<T_TOK, 256>>>(e);
        sgemm_kernel<<<ggd, 256>>>(hg, wdown + (size_t)e * IDIM * HDIM, dg, 0, cnt + e, HDIM, IDIM, nullptr);
        scatter_kernel<<<T_TOK, HDIM / 4>>>(e, out);
    }
}

// round 3
// speedup vs baseline: 2.4922x; 2.4922x over previous
#include <cuda_runtime.h>
#include <cuda_bf16.h>
#include <math.h>
#include <stdint.h>

// ---- problem constants ----
#define T_TOK 4096      // B*S
#define SEQ   2048
#define BATCH 2
#define HDIM  768
#define NHEADS 12
#define HEADD 64
#define IDIM  2048
#define NEXP  8

// ---- fp32 scratch ----
__device__ __align__(128) float g_q   [T_TOK*HDIM];
__device__ __align__(128) float g_k   [T_TOK*HDIM];
__device__ __align__(128) float g_v   [T_TOK*HDIM];
__device__ __align__(128) float g_qr  [T_TOK*HDIM];
__device__ __align__(128) float g_kr  [T_TOK*HDIM];
__device__ __align__(128) float g_vr  [T_TOK*HDIM];
__device__ __align__(128) float g_x1  [T_TOK*HDIM];
__device__ __align__(128) float g_x1n [T_TOK*HDIM];
__device__ __align__(128) float g_hg  [T_TOK*IDIM];
__device__ __align__(128) float g_hu  [T_TOK*IDIM];
__device__ __align__(128) float g_dg  [T_TOK*HDIM];
__device__ float g_cos [SEQ*32];
__device__ float g_sin [SEQ*32];
__device__ float g_lse2[T_TOK];
__device__ int   g_cnt [NEXP];
__device__ int   g_rows[NEXP*T_TOK];
__device__ float g_rwt [NEXP*T_TOK];

// ---- bf16 hi/lo scratch (activations) ----
__device__ __align__(128) __nv_bfloat16 g_ah [T_TOK*HDIM];
__device__ __align__(128) __nv_bfloat16 g_al [T_TOK*HDIM];
__device__ __align__(128) __nv_bfloat16 g_oh [T_TOK*HDIM];
__device__ __align__(128) __nv_bfloat16 g_ol [T_TOK*HDIM];
__device__ __align__(128) __nv_bfloat16 g_xgh[T_TOK*HDIM];
__device__ __align__(128) __nv_bfloat16 g_xgl[T_TOK*HDIM];
__device__ __align__(128) __nv_bfloat16 g_hgh[T_TOK*IDIM];
__device__ __align__(128) __nv_bfloat16 g_hgl[T_TOK*IDIM];

// ---- bf16 hi/lo weights (transposed to [N,K] K-major) ----
__device__ __align__(128) __nv_bfloat16 g_wqh[HDIM*HDIM];
__device__ __align__(128) __nv_bfloat16 g_wql[HDIM*HDIM];
__device__ __align__(128) __nv_bfloat16 g_wkh[HDIM*HDIM];
__device__ __align__(128) __nv_bfloat16 g_wkl[HDIM*HDIM];
__device__ __align__(128) __nv_bfloat16 g_wvh[HDIM*HDIM];
__device__ __align__(128) __nv_bfloat16 g_wvl[HDIM*HDIM];
__device__ __align__(128) __nv_bfloat16 g_woh[HDIM*HDIM];
__device__ __align__(128) __nv_bfloat16 g_wol[HDIM*HDIM];
__device__ __align__(128) __nv_bfloat16 g_wgth[NEXP*HDIM*IDIM];
__device__ __align__(128) __nv_bfloat16 g_wgtl[NEXP*HDIM*IDIM];
__device__ __align__(128) __nv_bfloat16 g_wuph[NEXP*HDIM*IDIM];
__device__ __align__(128) __nv_bfloat16 g_wupl[NEXP*HDIM*IDIM];
__device__ __align__(128) __nv_bfloat16 g_wdnh[NEXP*IDIM*HDIM];
__device__ __align__(128) __nv_bfloat16 g_wdnl[NEXP*IDIM*HDIM];

// ================= helpers =================
__device__ __forceinline__ uint32_t s2u(const void* p) {
    uint32_t a;
    asm("{ .reg .u64 t; cvta.to.shared.u64 t, %1; cvt.u32.u64 %0, t; }" : "=r"(a) : "l"(p));
    return a;
}
__device__ __forceinline__ void split1(float v, __nv_bfloat16* hp, __nv_bfloat16* lp) {
    __nv_bfloat16 h = __float2bfloat16(v);
    *hp = h;
    *lp = __float2bfloat16(v - __bfloat162float(h));
}

#define LDSM4(r, a) \
    asm volatile("ldmatrix.sync.aligned.m8n8.x4.shared.b16 {%0,%1,%2,%3}, [%4];" \
        : "=r"((r)[0]), "=r"((r)[1]), "=r"((r)[2]), "=r"((r)[3]) : "r"(a))
#define LDSM2(r, a) \
    asm volatile("ldmatrix.sync.aligned.m8n8.x2.shared.b16 {%0,%1}, [%2];" \
        : "=r"((r)[0]), "=r"((r)[1]) : "r"(a))
#define MMA_BF16(c, a, b) \
    asm volatile("mma.sync.aligned.m16n8k16.row.col.f32.bf16.bf16.f32 " \
        "{%0,%1,%2,%3}, {%4,%5,%6,%7}, {%8,%9}, {%0,%1,%2,%3};" \
        : "+f"((c)[0]), "+f"((c)[1]), "+f"((c)[2]), "+f"((c)[3]) \
        : "r"((a)[0]), "r"((a)[1]), "r"((a)[2]), "r"((a)[3]), "r"((b)[0]), "r"((b)[1]))
#define CP_ASYNC16(dst, src) \
    asm volatile("cp.async.cg.shared.global [%0], [%1], 16;" :: "r"(dst), "l"(src))

// ================= weight transpose + hi/lo split =================
__global__ void wconv_kernel(const float* __restrict__ W, __nv_bfloat16* __restrict__ oh,
                             __nv_bfloat16* __restrict__ ol, int K, int N) {
    W  += (size_t)blockIdx.z * K * N;
    oh += (size_t)blockIdx.z * K * N;
    ol += (size_t)blockIdx.z * K * N;
    __shared__ float t[32][33];
    int n0 = blockIdx.x * 32, k0 = blockIdx.y * 32;
    int tx = threadIdx.x, ty = threadIdx.y;
    for (int i = ty; i < 32; i += 8)
        t[i][tx] = W[(size_t)(k0 + i) * N + n0 + tx];
    __syncthreads();
    for (int i = ty; i < 32; i += 8) {
        float v = t[tx][i];
        size_t o = (size_t)(n0 + i) * K + k0 + tx;
        split1(v, &oh[o], &ol[o]);
    }
}

// ================= mma.sync split-bf16 GEMM =================
// C[M,N](fp32) = A@B^T.  A hi/lo: [M,K] bf16 K-major; B hi/lo: [N,K] bf16 K-major.
// Tile 128x128, K-chunk 32, cp.async double-buffer, 8 warps each 64x32.
// smem per stage: 4 tiles x (128 rows x 80B) = 40960; 2 stages = 81920 bytes.
#define TMMA_SMEM 81920

__global__ __launch_bounds__(256) void tmma_kernel(
    const __nv_bfloat16* __restrict__ Ah, const __nv_bfloat16* __restrict__ Al,
    const __nv_bfloat16* __restrict__ Bh, const __nv_bfloat16* __restrict__ Bl,
    float* __restrict__ C, int M, const int* __restrict__ Mptr,
    int N, int K, const float* __restrict__ Cadd)
{
    int m = Mptr ? *Mptr : M;
    int row0 = blockIdx.y * 128;
    if (row0 >= m) return;
    int col0 = blockIdx.x * 128;

    extern __shared__ char sm[];
    uint32_t sbase = s2u(sm);
    int tid = threadIdx.x, lane = tid & 31, wid = tid >> 5;
    int wm = wid & 1, wn = wid >> 1;   // warp tile: rows wm*64, cols wn*32

    const __nv_bfloat16* sp[4];
    sp[0] = Ah + (size_t)row0 * K;
    sp[1] = Al + (size_t)row0 * K;
    sp[2] = Bh + (size_t)col0 * K;
    sp[3] = Bl + (size_t)col0 * K;

    float acc[4][4][4];
#pragma unroll
    for (int a = 0; a < 4; a++)
#pragma unroll
        for (int b = 0; b < 4; b++)
#pragma unroll
            for (int c = 0; c < 4; c++) acc[a][b][c] = 0.f;

    int NC = K >> 5;

    // ---- stage loader: 4 tiles x 512 16B-chunks, 2 chunks/thread/tile ----
    // tile row stride in smem = 80B (32 bf16 + 16B pad) -> conflict-free ldmatrix
#define LOAD_STAGE(cc, ss) do { \
    uint32_t _db = sbase + (ss) * 40960; \
    _Pragma("unroll") \
    for (int _t = 0; _t < 4; _t++) { \
        _Pragma("unroll") \
        for (int _i = 0; _i < 2; _i++) { \
            int _idx = tid + _i * 256; \
            int _r = _idx >> 2, _ch = _idx & 3; \
            uint32_t _dst = _db + _t * 10240 + _r * 80 + _ch * 16; \
            const void* _src = sp[_t] + (size_t)_r * K + (cc) * 32 + _ch * 8; \
            CP_ASYNC16(_dst, _src); \
        } \
    } \
    asm volatile("cp.async.commit_group;"); \
} while (0)

    LOAD_STAGE(0, 0);

    for (int c = 0; c < NC; c++) {
        if (c + 1 < NC) {
            LOAD_STAGE(c + 1, (c + 1) & 1);
            asm volatile("cp.async.wait_group 1;");
        } else {
            asm volatile("cp.async.wait_group 0;");
        }
        __syncthreads();

        uint32_t db = sbase + (c & 1) * 40960;
        uint32_t aH = db, aL = db + 10240, bH = db + 20480, bL = db + 30720;
#pragma unroll
        for (int ks = 0; ks < 2; ks++) {
            uint32_t ah[4][4], al[4][4], bh[4][2], bl[4][2];
            uint32_t aoff = (uint32_t)(wm * 64 + (lane & 15)) * 80 + ks * 32 + (lane >> 4) * 16;
            uint32_t boff = (uint32_t)(wn * 32 + (lane & 7)) * 80 + ks * 32 + ((lane >> 3) & 1) * 16;
#pragma unroll
            for (int mt = 0; mt < 4; mt++) {
                LDSM4(ah[mt], aH + aoff + mt * 1280);
                LDSM4(al[mt], aL + aoff + mt * 1280);
            }
#pragma unroll
            for (int nt = 0; nt < 4; nt++) {
                LDSM2(bh[nt], bH + boff + nt * 640);
                LDSM2(bl[nt], bL + boff + nt * 640);
            }
#pragma unroll
            for (int mt = 0; mt < 4; mt++)
#pragma unroll
                for (int nt = 0; nt < 4; nt++) {
                    MMA_BF16(acc[mt][nt], ah[mt], bh[nt]);
                    MMA_BF16(acc[mt][nt], ah[mt], bl[nt]);
                    MMA_BF16(acc[mt][nt], al[mt], bh[nt]);
                }
        }
        __syncthreads();
    }

    // ---- epilogue ----
#pragma unroll
    for (int mt = 0; mt < 4; mt++) {
        int rbase = row0 + wm * 64 + mt * 16 + (lane >> 2);
#pragma unroll
        for (int half = 0; half < 2; half++) {
            int rr = rbase + half * 8;
            if (rr < m) {
                size_t o = (size_t)rr * N + col0 + wn * 32 + (lane & 3) * 2;
#pragma unroll
                for (int nt = 0; nt < 4; nt++) {
                    float v0 = acc[mt][nt][half * 2 + 0];
                    float v1 = acc[mt][nt][half * 2 + 1];
                    size_t oo = o + nt * 8;
                    if (Cadd) {
                        float2 ad = *(const float2*)(Cadd + oo);
                        v0 += ad.x; v1 += ad.y;
                    }
                    float2 st; st.x = v0; st.y = v1;
                    *(float2*)(C + oo) = st;
                }
            }
        }
    }
}

// ================= RMSNorm variants =================
__device__ __forceinline__ float block_rms(const float* xr, int tid) {
    float s = 0.f;
    for (int c = tid; c < HDIM; c += 256) { float v = xr[c]; s += v * v; }
    __shared__ float red[8];
    for (int o = 16; o; o >>= 1) s += __shfl_xor_sync(0xffffffffu, s, o);
    if ((tid & 31) == 0) red[tid >> 5] = s;
    __syncthreads();
    if (tid < 8) {
        float v = red[tid];
        for (int o = 4; o; o >>= 1) v += __shfl_xor_sync(0xffu, v, o);
        if (tid == 0) red[0] = v;
    }
    __syncthreads();
    return rsqrtf(red[0] / (float)HDIM + 1e-6f);
}

__global__ void rmsnorm_bf16_kernel(const float* __restrict__ x, const float* __restrict__ w,
                                    __nv_bfloat16* __restrict__ oh, __nv_bfloat16* __restrict__ ol) {
    int row = blockIdx.x;
    const float* xr = x + (size_t)row * HDIM;
    float scale = block_rms(xr, threadIdx.x);
    for (int c = threadIdx.x; c < HDIM; c += 256) {
        float v = w[c] * xr[c] * scale;
        split1(v, &oh[(size_t)row * HDIM + c], &ol[(size_t)row * HDIM + c]);
    }
}

__global__ void rmsnorm_f32_kernel(const float* __restrict__ x, const float* __restrict__ w,
                                   float* __restrict__ out) {
    int row = blockIdx.x;
    const float* xr = x + (size_t)row * HDIM;
    float scale = block_rms(xr, threadIdx.x);
    for (int c = threadIdx.x; c < HDIM; c += 256)
        out[(size_t)row * HDIM + c] = w[c] * xr[c] * scale;
}

// ================= RoPE =================
__global__ void rope_table_kernel() {
    int idx = blockIdx.x * blockDim.x + threadIdx.x;
    if (idx >= SEQ * 32) return;
    int i = idx & 31, s = idx >> 5;
    float inv = powf(10000.0f, -(float)i / 32.0f);
    float ang = (float)s * inv;
    g_cos[idx] = cosf(ang);
    g_sin[idx] = sinf(ang);
}

__global__ void rope_kernel() {
    int s = blockIdx.x, hh = blockIdx.y, bb = blockIdx.z, d = threadIdx.x;
    int t = bb * SEQ + s;
    int src  = t * HDIM + hh * HEADD + d;
    int psrc = t * HDIM + hh * HEADD + (d < 32 ? d + 32 : d - 32);
    int dst  = ((bb * NHEADS + hh) * SEQ + s) * HEADD + d;
    float cs = g_cos[s * 32 + (d & 31)], sn = g_sin[s * 32 + (d & 31)];
    float sgn = (d < 32) ? -1.f : 1.f;
    g_qr[dst] = g_q[src] * cs + sgn * g_q[psrc] * sn;
    g_kr[dst] = g_k[src] * cs + sgn * g_k[psrc] * sn;
    g_vr[dst] = g_v[src];
}

// ================= flash attention (causal, fp32, HD=64) -> bf16 hi/lo out ===========
__global__ __launch_bounds__(128) void flash_kernel() {
    int qt = blockIdx.x, hh = blockIdx.y, bb = blockIdx.z;
    __shared__ float sQT[64][64];
    __shared__ float sKP[64][64];
    __shared__ float sV [64][64];

    int tid = threadIdx.x;
    const float* Qb = g_qr + (size_t)((bb * NHEADS + hh) * SEQ) * HEADD;
    const float* Kb = g_kr + (size_t)((bb * NHEADS + hh) * SEQ) * HEADD;
    const float* Vb = g_vr + (size_t)((bb * NHEADS + hh) * SEQ) * HEADD;

    {
        int d4 = (tid & 15) * 4, i0 = tid >> 4;
        for (int i = i0; i < 64; i += 8) {
            float4 v = *(const float4*)(Qb + (size_t)(qt * 64 + i) * 64 + d4);
            sQT[d4 + 0][i] = v.x; sQT[d4 + 1][i] = v.y;
            sQT[d4 + 2][i] = v.z; sQT[d4 + 3][i] = v.w;
        }
    }

    int c  = tid & 7;
    int rq = tid >> 3;
    float m[4], l[4], o[4][8];
#pragma unroll
    for (int u = 0; u < 4; u++) {
        m[u] = -INFINITY; l[u] = 0.f;
#pragma unroll
        for (int j = 0; j < 8; j++) o[u][j] = 0.f;
    }
    const float scale = 0.125f;
    int rbase = qt * 64 + rq * 4;

    for (int kt = 0; kt <= qt; kt++) {
        __syncthreads();
        {
            int d4 = (tid & 15) * 4, i0 = tid >> 4;
            for (int i = i0; i < 64; i += 8) {
                float4 kv = *(const float4*)(Kb + (size_t)(kt * 64 + i) * 64 + d4);
                sKP[d4 + 0][i] = kv.x; sKP[d4 + 1][i] = kv.y;
                sKP[d4 + 2][i] = kv.z; sKP[d4 + 3][i] = kv.w;
                float4 vv = *(const float4*)(Vb + (size_t)(kt * 64 + i) * 64 + d4);
                *(float4*)&sV[i][d4] = vv;
            }
        }
        __syncthreads();

        float sc[4][8];
#pragma unroll
        for (int u = 0; u < 4; u++)
#pragma unroll
            for (int j = 0; j < 8; j++) sc[u][j] = 0.f;

#pragma unroll 8
        for (int kk = 0; kk < 64; kk++) {
            float4 q4  = *(const float4*)&sQT[kk][rq * 4];
            float4 k40 = *(const float4*)&sKP[kk][c * 8];
            float4 k41 = *(const float4*)&sKP[kk][c * 8 + 4];
            float qa[4] = {q4.x, q4.y, q4.z, q4.w};
            float kb8[8] = {k40.x, k40.y, k40.z, k40.w, k41.x, k41.y, k41.z, k41.w};
#pragma unroll
            for (int u = 0; u < 4; u++)
#pragma unroll
                for (int j = 0; j < 8; j++) sc[u][j] += qa[u] * kb8[j];
        }

        int kbase = kt * 64 + c * 8;
#pragma unroll
        for (int u = 0; u < 4; u++) {
#pragma unroll
            for (int j = 0; j < 8; j++)
                sc[u][j] = (kbase + j <= rbase + u) ? sc[u][j] * scale : -1e30f;
            float mt = sc[u][0];
#pragma unroll
            for (int j = 1; j < 8; j++) mt = fmaxf(mt, sc[u][j]);
            for (int ox = 1; ox < 8; ox <<= 1)
                mt = fmaxf(mt, __shfl_xor_sync(0xffffffffu, mt, ox));
            float mn = fmaxf(m[u], mt);
            float alpha = expf(m[u] - mn);
            float ps = 0.f;
#pragma unroll
            for (int j = 0; j < 8; j++) { float p = expf(sc[u][j] - mn); sc[u][j] = p; ps += p; }
            for (int ox = 1; ox < 8; ox <<= 1)
                ps += __shfl_xor_sync(0xffffffffu, ps, ox);
            l[u] = l[u] * alpha + ps;
            m[u] = mn;
#pragma unroll
            for (int j = 0; j < 8; j++) o[u][j] *= alpha;
        }

        __syncthreads();
#pragma unroll
        for (int j = 0; j < 8; j++) {
            float4 pv = make_float4(sc[0][j], sc[1][j], sc[2][j], sc[3][j]);
            *(float4*)&sKP[c * 8 + j][rq * 4] = pv;
        }
        __syncthreads();

#pragma unroll 8
        for (int k = 0; k < 64; k++) {
            float4 p4 = *(const float4*)&sKP[k][rq * 4];
            float4 v0 = *(const float4*)&sV[k][c * 8];
            float4 v1 = *(const float4*)&sV[k][c * 8 + 4];
            float pu[4] = {p4.x, p4.y, p4.z, p4.w};
            float vj[8] = {v0.x, v0.y, v0.z, v0.w, v1.x, v1.y, v1.z, v1.w};
#pragma unroll
            for (int u = 0; u < 4; u++)
#pragma unroll
                for (int j = 0; j < 8; j++) o[u][j] += pu[u] * vj[j];
        }
    }

#pragma unroll
    for (int u = 0; u < 4; u++) {
        float inv = 1.0f / l[u];
        int row = rbase + u;
        size_t ob = (size_t)(bb * SEQ + row) * HDIM + hh * HEADD + c * 8;
#pragma unroll
        for (int j = 0; j < 8; j++) {
            float val = o[u][j] * inv;
            split1(val, &g_oh[ob + j], &g_ol[ob + j]);
        }
    }
}

// ================= MoE gating =================
__global__ void zero_cnt_kernel() { if (threadIdx.x < NEXP) g_cnt[threadIdx.x] = 0; }

__global__ void gate_kernel(const float* __restrict__ gw) {
    int t = blockIdx.x * 8 + (threadIdx.x >> 5);
    int lane = threadIdx.x & 31;
    const float* xr = g_x1n + (size_t)t * HDIM;
    float acc[8] = {0, 0, 0, 0, 0, 0, 0, 0};
    for (int j = lane; j < HDIM; j += 32) {
        float xv = xr[j];
        const float* gr = gw + j * 8;
        float4 g0 = *(const float4*)gr, g1 = *(const float4*)(gr + 4);
        acc[0] += xv * g0.x; acc[1] += xv * g0.y; acc[2] += xv * g0.z; acc[3] += xv * g0.w;
        acc[4] += xv * g1.x; acc[5] += xv * g1.y; acc[6] += xv * g1.z; acc[7] += xv * g1.w;
    }
#pragma unroll
    for (int e = 0; e < 8; e++)
        for (int o = 16; o; o >>= 1) acc[e] += __shfl_xor_sync(0xffffffffu, acc[e], o);
    if (lane == 0) {
        float mx = acc[0];
#pragma unroll
        for (int e = 1; e < 8; e++) mx = fmaxf(mx, acc[e]);
        float se = 0.f;
#pragma unroll
        for (int e = 0; e < 8; e++) se += expf(acc[e] - mx);
        float lse = mx + logf(se);
        g_lse2[t] = lse * lse;
        int i0 = 0; float v0 = acc[0];
#pragma unroll
        for (int e = 1; e < 8; e++) if (acc[e] > v0) { v0 = acc[e]; i0 = e; }
        int i1 = -1; float v1 = -INFINITY;
#pragma unroll
        for (int e = 0; e < 8; e++) if (e != i0 && acc[e] > v1) { v1 = acc[e]; i1 = e; }
        float w0 = 1.f / (1.f + expf(v1 - v0));
        float w1 = 1.f - w0;
        int p0 = atomicAdd(&g_cnt[i0], 1);
        g_rows[i0 * T_TOK + p0] = t; g_rwt[i0 * T_TOK + p0] = w0;
        int p1 = atomicAdd(&g_cnt[i1], 1);
        g_rows[i1 * T_TOK + p1] = t; g_rwt[i1 * T_TOK + p1] = w1;
    }
}

__global__ void aux_kernel(float* __restrict__ out) {
    __shared__ float red[32];
    float s = 0.f;
    for (int i = threadIdx.x; i < T_TOK; i += 1024) s += g_lse2[i];
    for (int o = 16; o; o >>= 1) s += __shfl_xor_sync(0xffffffffu, s, o);
    if ((threadIdx.x & 31) == 0) red[threadIdx.x >> 5] = s;
    __syncthreads();
    if (threadIdx.x < 32) {
        float v = red[threadIdx.x];
        for (int o = 16; o; o >>= 1) v += __shfl_xor_sync(0xffffffffu, v, o);
        if (threadIdx.x == 0) out[(size_t)T_TOK * HDIM] = 0.001f * v / (float)T_TOK;
    }
}

__global__ void copyres_kernel(float* __restrict__ out) {
    int i = blockIdx.x * 256 + threadIdx.x;
    ((float4*)out)[i] = ((const float4*)g_x1)[i];
}

__global__ void gather_kernel(int e) {
    int r = blockIdx.x;
    if (r >= g_cnt[e]) return;
    int t = g_rows[e * T_TOK + r];
    float4 v = ((const float4*)(g_x1n + (size_t)t * HDIM))[threadIdx.x];
    size_t o = (size_t)r * HDIM + threadIdx.x * 4;
    split1(v.x, &g_xgh[o + 0], &g_xgl[o + 0]);
    split1(v.y, &g_xgh[o + 1], &g_xgl[o + 1]);
    split1(v.z, &g_xgh[o + 2], &g_xgl[o + 2]);
    split1(v.w, &g_xgh[o + 3], &g_xgl[o + 3]);
}

__global__ void silu_kernel(int e) {
    int r = blockIdx.x;
    if (r >= g_cnt[e]) return;
    const float4* hg4 = (const float4*)(g_hg + (size_t)r * IDIM);
    const float4* hu4 = (const float4*)(g_hu + (size_t)r * IDIM);
    for (int i = threadIdx.x; i < IDIM / 4; i += 256) {
        float4 a = hg4[i], b = hu4[i];
        float f0 = a.x / (1.f + expf(-a.x)) * b.x;
        float f1 = a.y / (1.f + expf(-a.y)) * b.y;
        float f2 = a.z / (1.f + expf(-a.z)) * b.z;
        float f3 = a.w / (1.f + expf(-a.w)) * b.w;
        size_t o = (size_t)r * IDIM + i * 4;
        split1(f0, &g_hgh[o + 0], &g_hgl[o + 0]);
        split1(f1, &g_hgh[o + 1], &g_hgl[o + 1]);
        split1(f2, &g_hgh[o + 2], &g_hgl[o + 2]);
        split1(f3, &g_hgh[o + 3], &g_hgl[o + 3]);
    }
}

__global__ void scatter_kernel(int e, float* __restrict__ out) {
    int r = blockIdx.x;
    if (r >= g_cnt[e]) return;
    int t = g_rows[e * T_TOK + r];
    float w = g_rwt[e * T_TOK + r];
    float4* o = (float4*)(out + (size_t)t * HDIM);
    const float4* d = (const float4*)(g_dg + (size_t)r * HDIM);
    float4 ov = o[threadIdx.x], dv = d[threadIdx.x];
    ov.x += w * dv.x; ov.y += w * dv.y; ov.z += w * dv.z; ov.w += w * dv.w;
    o[threadIdx.x] = ov;
}

// ================= launch =================
#define GSA(var, sym) do { void* _p; cudaGetSymbolAddress(&_p, sym); var = (decltype(var))_p; } while (0)

extern "C" void kernel_launch(void* const* d_in, const int* in_sizes, int n_in,
                              void* d_out, int out_size) {
    const float* hidden = (const float*)d_in[0];
    const float* wq    = (const float*)d_in[2];
    const float* wk    = (const float*)d_in[3];
    const float* wv    = (const float*)d_in[4];
    const float* wo    = (const float*)d_in[5];
    const float* ln1   = (const float*)d_in[6];
    const float* ln2   = (const float*)d_in[7];
    const float* gw    = (const float*)d_in[8];
    const float* wgate = (const float*)d_in[9];
    const float* wup   = (const float*)d_in[10];
    const float* wdown = (const float*)d_in[11];
    float* out = (float*)d_out;

    float *q, *k, *v, *x1, *x1n, *hg, *hu, *dg;
    int* cnt;
    __nv_bfloat16 *ah, *al, *oh, *ol, *xgh, *xgl, *hgh, *hgl;
    __nv_bfloat16 *wqh, *wql, *wkh, *wkl, *wvh, *wvl, *woh, *wol;
    __nv_bfloat16 *wgth, *wgtl, *wuph, *wupl, *wdnh, *wdnl;
    GSA(q, g_q); GSA(k, g_k); GSA(v, g_v);
    GSA(x1, g_x1); GSA(x1n, g_x1n);
    GSA(hg, g_hg); GSA(hu, g_hu); GSA(dg, g_dg);
    GSA(cnt, g_cnt);
    GSA(ah, g_ah); GSA(al, g_al); GSA(oh, g_oh); GSA(ol, g_ol);
    GSA(xgh, g_xgh); GSA(xgl, g_xgl); GSA(hgh, g_hgh); GSA(hgl, g_hgl);
    GSA(wqh, g_wqh); GSA(wql, g_wql); GSA(wkh, g_wkh); GSA(wkl, g_wkl);
    GSA(wvh, g_wvh); GSA(wvl, g_wvl); GSA(woh, g_woh); GSA(wol, g_wol);
    GSA(wgth, g_wgth); GSA(wgtl, g_wgtl); GSA(wuph, g_wuph); GSA(wupl, g_wupl);
    GSA(wdnh, g_wdnh); GSA(wdnl, g_wdnl);

    cudaFuncSetAttribute((const void*)tmma_kernel,
                         cudaFuncAttributeMaxDynamicSharedMemorySize, TMMA_SMEM);

    dim3 cb(32, 8);
    // weight transpose + split
    wconv_kernel<<<dim3(HDIM/32, HDIM/32, 1), cb>>>(wq, wqh, wql, HDIM, HDIM);
    wconv_kernel<<<dim3(HDIM/32, HDIM/32, 1), cb>>>(wk, wkh, wkl, HDIM, HDIM);
    wconv_kernel<<<dim3(HDIM/32, HDIM/32, 1), cb>>>(wv, wvh, wvl, HDIM, HDIM);
    wconv_kernel<<<dim3(HDIM/32, HDIM/32, 1), cb>>>(wo, woh, wol, HDIM, HDIM);
    wconv_kernel<<<dim3(IDIM/32, HDIM/32, NEXP), cb>>>(wgate, wgth, wgtl, HDIM, IDIM);
    wconv_kernel<<<dim3(IDIM/32, HDIM/32, NEXP), cb>>>(wup,   wuph, wupl, HDIM, IDIM);
    wconv_kernel<<<dim3(HDIM/32, IDIM/32, NEXP), cb>>>(wdown, wdnh, wdnl, IDIM, HDIM);

    // 1. pre-attention RMSNorm -> bf16 hi/lo
    rmsnorm_bf16_kernel<<<T_TOK, 256>>>(hidden, ln1, ah, al);

    // 2. QKV projections (mma.sync tensor)
    dim3 gqkv(HDIM / 128, T_TOK / 128);
    tmma_kernel<<<gqkv, 256, TMMA_SMEM>>>(ah, al, wqh, wql, q, T_TOK, nullptr, HDIM, HDIM, nullptr);
    tmma_kernel<<<gqkv, 256, TMMA_SMEM>>>(ah, al, wkh, wkl, k, T_TOK, nullptr, HDIM, HDIM, nullptr);
    tmma_kernel<<<gqkv, 256, TMMA_SMEM>>>(ah, al, wvh, wvl, v, T_TOK, nullptr, HDIM, HDIM, nullptr);

    // 3. RoPE
    rope_table_kernel<<<(SEQ * 32 + 255) / 256, 256>>>();
    rope_kernel<<<dim3(SEQ, NHEADS, BATCH), 64>>>();

    // 4. causal flash attention -> bf16 hi/lo
    flash_kernel<<<dim3(SEQ / 64, NHEADS, BATCH), 128>>>();

    // 5. output projection + residual
    tmma_kernel<<<gqkv, 256, TMMA_SMEM>>>(oh, ol, woh, wol, x1, T_TOK, nullptr, HDIM, HDIM, hidden);

    // 6. post-attention RMSNorm (fp32 for gating/gather)
    rmsnorm_f32_kernel<<<T_TOK, 256>>>(x1, ln2, x1n);

    // 7. gating + aux
    zero_cnt_kernel<<<1, 32>>>();
    gate_kernel<<<T_TOK / 8, 256>>>(gw);
    aux_kernel<<<1, 1024>>>(out);

    // 8. out := residual
    copyres_kernel<<<(T_TOK * HDIM / 4) / 256, 256>>>(out);

    // 9. sparse MoE experts (tensor GEMMs)
    dim3 ggu(IDIM / 128, T_TOK / 128);
    dim3 ggd(HDIM / 128, T_TOK / 128);
    for (int e = 0; e < NEXP; e++) {
        gather_kernel<<<T_TOK, HDIM / 4>>>(e);
        tmma_kernel<<<ggu, 256, TMMA_SMEM>>>(xgh, xgl, wgth + (size_t)e * HDIM * IDIM, wgtl + (size_t)e * HDIM * IDIM,
                                             hg, 0, cnt + e, IDIM, HDIM, nullptr);
        tmma_kernel<<<ggu, 256, TMMA_SMEM>>>(xgh, xgl, wuph + (size_t)e * HDIM * IDIM, wupl + (size_t)e * HDIM * IDIM,
                                             hu, 0, cnt + e, IDIM, HDIM, nullptr);
        silu_kernel<<<T_TOK, 256>>>(e);
        tmma_kernel<<<ggd, 256, TMMA_SMEM>>>(hgh, hgl, wdnh + (size_t)e * IDIM * HDIM, wdnl + (size_t)e * IDIM * HDIM,
                                             dg, 0, cnt + e, HDIM, IDIM, nullptr);
        scatter_kernel<<<T_TOK, HDIM / 4>>>(e, out);
    }
}

// round 4
// speedup vs baseline: 3.3208x; 1.3325x over previous
#include <cuda_runtime.h>
#include <cuda_bf16.h>
#include <math.h>
#include <stdint.h>

// ---- problem constants ----
#define T_TOK 4096      // B*S
#define SEQ   2048
#define BATCH 2
#define HDIM  768
#define NHEADS 12
#define HEADD 64
#define IDIM  2048
#define NEXP  8

// ---- fp32 scratch ----
__device__ __align__(128) float g_qkv [T_TOK*2304];
__device__ __align__(128) float g_x1  [T_TOK*HDIM];
__device__ __align__(128) float g_x1n [T_TOK*HDIM];
__device__ __align__(128) float g_h   [(size_t)NEXP*T_TOK*2*IDIM];   // gate|up per expert
__device__ __align__(128) float g_dg  [(size_t)NEXP*T_TOK*HDIM];
__device__ float g_cos [SEQ*32];
__device__ float g_sin [SEQ*32];
__device__ float g_lse2[T_TOK];
__device__ int   g_cnt [NEXP];
__device__ int   g_rows[NEXP*T_TOK];
__device__ int   g_ie  [2*T_TOK];
__device__ int   g_islot[2*T_TOK];
__device__ float g_iw  [2*T_TOK];

// ---- bf16 hi/lo activations ----
__device__ __align__(128) __nv_bfloat16 g_ah [T_TOK*HDIM];
__device__ __align__(128) __nv_bfloat16 g_al [T_TOK*HDIM];
__device__ __align__(128) __nv_bfloat16 g_qh [T_TOK*HDIM];  // [b,h,s,d]
__device__ __align__(128) __nv_bfloat16 g_ql [T_TOK*HDIM];
__device__ __align__(128) __nv_bfloat16 g_kh [T_TOK*HDIM];
__device__ __align__(128) __nv_bfloat16 g_kl [T_TOK*HDIM];
__device__ __align__(128) __nv_bfloat16 g_vth[T_TOK*HDIM];  // [b,h,d,s] transposed
__device__ __align__(128) __nv_bfloat16 g_vtl[T_TOK*HDIM];
__device__ __align__(128) __nv_bfloat16 g_oh [T_TOK*HDIM];
__device__ __align__(128) __nv_bfloat16 g_ol [T_TOK*HDIM];
__device__ __align__(128) __nv_bfloat16 g_xgh[(size_t)NEXP*T_TOK*HDIM];
__device__ __align__(128) __nv_bfloat16 g_xgl[(size_t)NEXP*T_TOK*HDIM];
__device__ __align__(128) __nv_bfloat16 g_hgh[(size_t)NEXP*T_TOK*IDIM];
__device__ __align__(128) __nv_bfloat16 g_hgl[(size_t)NEXP*T_TOK*IDIM];

// ---- bf16 hi/lo weights ([N,K] K-major) ----
__device__ __align__(128) __nv_bfloat16 g_wqkvh[2304*HDIM];
__device__ __align__(128) __nv_bfloat16 g_wqkvl[2304*HDIM];
__device__ __align__(128) __nv_bfloat16 g_woh[HDIM*HDIM];
__device__ __align__(128) __nv_bfloat16 g_wol[HDIM*HDIM];
__device__ __align__(128) __nv_bfloat16 g_wguh[(size_t)NEXP*2*IDIM*HDIM];  // [e][4096][768]
__device__ __align__(128) __nv_bfloat16 g_wgul[(size_t)NEXP*2*IDIM*HDIM];
__device__ __align__(128) __nv_bfloat16 g_wdnh[(size_t)NEXP*HDIM*IDIM];    // [e][768][2048]
__device__ __align__(128) __nv_bfloat16 g_wdnl[(size_t)NEXP*HDIM*IDIM];

// ================= helpers =================
__device__ __forceinline__ uint32_t s2u(const void* p) {
    uint32_t a;
    asm("{ .reg .u64 t; cvta.to.shared.u64 t, %1; cvt.u32.u64 %0, t; }" : "=r"(a) : "l"(p));
    return a;
}
__device__ __forceinline__ void split1(float v, __nv_bfloat16* hp, __nv_bfloat16* lp) {
    __nv_bfloat16 h = __float2bfloat16(v);
    *hp = h;
    *lp = __float2bfloat16(v - __bfloat162float(h));
}
__device__ __forceinline__ void packsplit(float a, float b, uint32_t* hi, uint32_t* lo) {
    __nv_bfloat16 ah = __float2bfloat16(a), bh = __float2bfloat16(b);
    __nv_bfloat16 alr = __float2bfloat16(a - __bfloat162float(ah));
    __nv_bfloat16 blr = __float2bfloat16(b - __bfloat162float(bh));
    __nv_bfloat162 h2; h2.x = ah; h2.y = bh;
    __nv_bfloat162 l2; l2.x = alr; l2.y = blr;
    *hi = *(uint32_t*)&h2; *lo = *(uint32_t*)&l2;
}

#define LDSM4(r, a) \
    asm volatile("ldmatrix.sync.aligned.m8n8.x4.shared.b16 {%0,%1,%2,%3}, [%4];" \
        : "=r"((r)[0]), "=r"((r)[1]), "=r"((r)[2]), "=r"((r)[3]) : "r"(a))
#define LDSM2(r, a) \
    asm volatile("ldmatrix.sync.aligned.m8n8.x2.shared.b16 {%0,%1}, [%2];" \
        : "=r"((r)[0]), "=r"((r)[1]) : "r"(a))
#define MMA_BF16(c, a, b) \
    asm volatile("mma.sync.aligned.m16n8k16.row.col.f32.bf16.bf16.f32 " \
        "{%0,%1,%2,%3}, {%4,%5,%6,%7}, {%8,%9}, {%0,%1,%2,%3};" \
        : "+f"((c)[0]), "+f"((c)[1]), "+f"((c)[2]), "+f"((c)[3]) \
        : "r"((a)[0]), "r"((a)[1]), "r"((a)[2]), "r"((a)[3]), "r"((b)[0]), "r"((b)[1]))
#define CP_ASYNC16(dst, src) \
    asm volatile("cp.async.cg.shared.global [%0], [%1], 16;" :: "r"(dst), "l"(src))

// ================= weight transpose + hi/lo split =================
__global__ void wconv_kernel(const float* __restrict__ W, __nv_bfloat16* __restrict__ oh,
                             __nv_bfloat16* __restrict__ ol, int K, int N,
                             size_t inZ, size_t outZ) {
    W  += (size_t)blockIdx.z * inZ;
    oh += (size_t)blockIdx.z * outZ;
    ol += (size_t)blockIdx.z * outZ;
    __shared__ float t[32][33];
    int n0 = blockIdx.x * 32, k0 = blockIdx.y * 32;
    int tx = threadIdx.x, ty = threadIdx.y;
    for (int i = ty; i < 32; i += 8)
        t[i][tx] = W[(size_t)(k0 + i) * N + n0 + tx];
    __syncthreads();
    for (int i = ty; i < 32; i += 8) {
        float v = t[tx][i];
        size_t o = (size_t)(n0 + i) * K + k0 + tx;
        split1(v, &oh[o], &ol[o]);
    }
}

// ================= mma.sync split-bf16 GEMM (batched over z) =================
#define TMMA_SMEM 81920

__global__ __launch_bounds__(256) void tmma_kernel(
    const __nv_bfloat16* __restrict__ Ah, const __nv_bfloat16* __restrict__ Al,
    const __nv_bfloat16* __restrict__ Bh, const __nv_bfloat16* __restrict__ Bl,
    float* __restrict__ C, int M, const int* __restrict__ cntArr,
    int N, int K, const float* __restrict__ Cadd,
    size_t zsA, size_t zsB, size_t zsC)
{
    int z = blockIdx.z;
    int m = cntArr ? cntArr[z] : M;
    int row0 = blockIdx.y * 128;
    if (row0 >= m) return;
    int col0 = blockIdx.x * 128;
    Ah += zsA * z; Al += zsA * z; Bh += zsB * z; Bl += zsB * z; C += zsC * z;

    extern __shared__ char sm[];
    uint32_t sbase = s2u(sm);
    int tid = threadIdx.x, lane = tid & 31, wid = tid >> 5;
    int wm = wid & 1, wn = wid >> 1;

    const __nv_bfloat16* sp[4];
    sp[0] = Ah + (size_t)row0 * K;
    sp[1] = Al + (size_t)row0 * K;
    sp[2] = Bh + (size_t)col0 * K;
    sp[3] = Bl + (size_t)col0 * K;

    float acc[4][4][4];
#pragma unroll
    for (int a = 0; a < 4; a++)
#pragma unroll
        for (int b = 0; b < 4; b++)
#pragma unroll
            for (int c = 0; c < 4; c++) acc[a][b][c] = 0.f;

    int NC = K >> 5;

#define LOAD_STAGE(cc, ss) do { \
    uint32_t _db = sbase + (ss) * 40960; \
    _Pragma("unroll") \
    for (int _t = 0; _t < 4; _t++) { \
        _Pragma("unroll") \
        for (int _i = 0; _i < 2; _i++) { \
            int _idx = tid + _i * 256; \
            int _r = _idx >> 2, _ch = _idx & 3; \
            uint32_t _dst = _db + _t * 10240 + _r * 80 + _ch * 16; \
            const void* _src = sp[_t] + (size_t)_r * K + (cc) * 32 + _ch * 8; \
            CP_ASYNC16(_dst, _src); \
        } \
    } \
    asm volatile("cp.async.commit_group;"); \
} while (0)

    LOAD_STAGE(0, 0);

    for (int c = 0; c < NC; c++) {
        if (c + 1 < NC) {
            LOAD_STAGE(c + 1, (c + 1) & 1);
            asm volatile("cp.async.wait_group 1;");
        } else {
            asm volatile("cp.async.wait_group 0;");
        }
        __syncthreads();

        uint32_t db = sbase + (c & 1) * 40960;
        uint32_t aH = db, aL = db + 10240, bH = db + 20480, bL = db + 30720;
#pragma unroll
        for (int ks = 0; ks < 2; ks++) {
            uint32_t ah[4][4], al[4][4], bh[4][2], bl[4][2];
            uint32_t aoff = (uint32_t)(wm * 64 + (lane & 15)) * 80 + ks * 32 + (lane >> 4) * 16;
            uint32_t boff = (uint32_t)(wn * 32 + (lane & 7)) * 80 + ks * 32 + ((lane >> 3) & 1) * 16;
#pragma unroll
            for (int mt = 0; mt < 4; mt++) {
                LDSM4(ah[mt], aH + aoff + mt * 1280);
                LDSM4(al[mt], aL + aoff + mt * 1280);
            }
#pragma unroll
            for (int nt = 0; nt < 4; nt++) {
                LDSM2(bh[nt], bH + boff + nt * 640);
                LDSM2(bl[nt], bL + boff + nt * 640);
            }
#pragma unroll
            for (int mt = 0; mt < 4; mt++)
#pragma unroll
                for (int nt = 0; nt < 4; nt++) {
                    MMA_BF16(acc[mt][nt], ah[mt], bh[nt]);
                    MMA_BF16(acc[mt][nt], ah[mt], bl[nt]);
                    MMA_BF16(acc[mt][nt], al[mt], bh[nt]);
                }
        }
        __syncthreads();
    }

#pragma unroll
    for (int mt = 0; mt < 4; mt++) {
        int rbase = row0 + wm * 64 + mt * 16 + (lane >> 2);
#pragma unroll
        for (int half = 0; half < 2; half++) {
            int rr = rbase + half * 8;
            if (rr < m) {
                size_t o = (size_t)rr * N + col0 + wn * 32 + (lane & 3) * 2;
#pragma unroll
                for (int nt = 0; nt < 4; nt++) {
                    float v0 = acc[mt][nt][half * 2 + 0];
                    float v1 = acc[mt][nt][half * 2 + 1];
                    size_t oo = o + nt * 8;
                    if (Cadd) {
                        float2 ad = *(const float2*)(Cadd + oo);
                        v0 += ad.x; v1 += ad.y;
                    }
                    float2 st; st.x = v0; st.y = v1;
                    *(float2*)(C + oo) = st;
                }
            }
        }
    }
}

// ================= RMSNorm =================
__device__ __forceinline__ float block_rms(const float* xr, int tid) {
    float s = 0.f;
    for (int c = tid; c < HDIM; c += 256) { float v = xr[c]; s += v * v; }
    __shared__ float red[8];
    for (int o = 16; o; o >>= 1) s += __shfl_xor_sync(0xffffffffu, s, o);
    if ((tid & 31) == 0) red[tid >> 5] = s;
    __syncthreads();
    if (tid < 8) {
        float v = red[tid];
        for (int o = 4; o; o >>= 1) v += __shfl_xor_sync(0xffu, v, o);
        if (tid == 0) red[0] = v;
    }
    __syncthreads();
    return rsqrtf(red[0] / (float)HDIM + 1e-6f);
}

__global__ void rmsnorm_bf16_kernel(const float* __restrict__ x, const float* __restrict__ w,
                                    __nv_bfloat16* __restrict__ oh, __nv_bfloat16* __restrict__ ol) {
    int row = blockIdx.x;
    const float* xr = x + (size_t)row * HDIM;
    float scale = block_rms(xr, threadIdx.x);
    for (int c = threadIdx.x; c < HDIM; c += 256) {
        float v = w[c] * xr[c] * scale;
        split1(v, &oh[(size_t)row * HDIM + c], &ol[(size_t)row * HDIM + c]);
    }
}

__global__ void rmsnorm_f32_kernel(const float* __restrict__ x, const float* __restrict__ w,
                                   float* __restrict__ out) {
    int row = blockIdx.x;
    const float* xr = x + (size_t)row * HDIM;
    float scale = block_rms(xr, threadIdx.x);
    for (int c = threadIdx.x; c < HDIM; c += 256)
        out[(size_t)row * HDIM + c] = w[c] * xr[c] * scale;
}

// ================= RoPE =================
__global__ void rope_table_kernel() {
    int idx = blockIdx.x * blockDim.x + threadIdx.x;
    if (idx >= SEQ * 32) return;
    int i = idx & 31, s = idx >> 5;
    float inv = powf(10000.0f, -(float)i / 32.0f);
    float ang = (float)s * inv;
    g_cos[idx] = cosf(ang);
    g_sin[idx] = sinf(ang);
}

// read qkv [T,2304]; write q,k roped bf16 hi/lo [b,h,s,d]; v transposed [b,h,d,s]
__global__ void rope_kernel() {
    int s = blockIdx.x, hh = blockIdx.y, bb = blockIdx.z, d = threadIdx.x;
    int t = bb * SEQ + s;
    const float* qkv = g_qkv + (size_t)t * 2304;
    int col  = hh * HEADD + d;
    int pcol = hh * HEADD + (d < 32 ? d + 32 : d - 32);
    float qv = qkv[col], kv = qkv[768 + col], vv = qkv[1536 + col];
    float qp = qkv[pcol], kp = qkv[768 + pcol];
    float cs = g_cos[s * 32 + (d & 31)], sn = g_sin[s * 32 + (d & 31)];
    float sgn = (d < 32) ? -1.f : 1.f;
    float qr = qv * cs + sgn * qp * sn;
    float kr = kv * cs + sgn * kp * sn;
    size_t dst = (((size_t)bb * NHEADS + hh) * SEQ + s) * HEADD + d;
    split1(qr, &g_qh[dst], &g_ql[dst]);
    split1(kr, &g_kh[dst], &g_kl[dst]);
    size_t vdst = (((size_t)bb * NHEADS + hh) * HEADD + d) * SEQ + s;
    split1(vv, &g_vth[vdst], &g_vtl[vdst]);
}

// ================= tensor-core flash attention =================
// 64x64 tiles, 4 warps (16 q-rows each), bf16 hi/lo split QK^T and PV, fp32 accum.
// smem: sQh,sQl,sKh,sKl,sVh,sVl each [64][72] bf16 (144B row stride).
#define FROW 144
#define FTILE 9216
#define FLASH_SMEM (6*FTILE)

__global__ __launch_bounds__(128) void flashmma_kernel() {
    int qt = 31 - (int)blockIdx.x;     // heavy blocks first
    int hh = blockIdx.y, bb = blockIdx.z;
    extern __shared__ char fsm[];
    uint32_t sb = s2u(fsm);
    uint32_t sQh = sb, sQl = sb + FTILE, sKh = sb + 2*FTILE, sKl = sb + 3*FTILE;
    uint32_t sVh = sb + 4*FTILE, sVl = sb + 5*FTILE;
    __nv_bfloat16* pQh = (__nv_bfloat16*)fsm;

    int tid = threadIdx.x, lane = tid & 31, w = tid >> 5;
    size_t hb = (size_t)bb * NHEADS + hh;
    const __nv_bfloat16* Qh = g_qh + hb * SEQ * HEADD;
    const __nv_bfloat16* Ql = g_ql + hb * SEQ * HEADD;
    const __nv_bfloat16* Kh = g_kh + hb * SEQ * HEADD;
    const __nv_bfloat16* Kl = g_kl + hb * SEQ * HEADD;
    const __nv_bfloat16* Vh = g_vth + hb * HEADD * SEQ;
    const __nv_bfloat16* Vl = g_vtl + hb * HEADD * SEQ;

    // load Q tile
    for (int i = tid; i < 512; i += 128) {
        int r = i >> 3, ch = i & 7;
        *(uint4*)((char*)pQh + r * FROW + ch * 16) =
            *(const uint4*)(Qh + (size_t)(qt * 64 + r) * HEADD + ch * 8);
        *(uint4*)((char*)pQh + FTILE + r * FROW + ch * 16) =
            *(const uint4*)(Ql + (size_t)(qt * 64 + r) * HEADD + ch * 8);
    }
    __syncthreads();

    // preload Q fragments (4 k-steps over HD=64)
    uint32_t qfh[4][4], qfl[4][4];
#pragma unroll
    for (int ks = 0; ks < 4; ks++) {
        uint32_t ao = (uint32_t)(w * 16 + (lane & 15)) * FROW + ks * 32 + (lane >> 4) * 16;
        LDSM4(qfh[ks], sQh + ao);
        LDSM4(qfl[ks], sQl + ao);
    }

    float accO[8][4];
#pragma unroll
    for (int i = 0; i < 8; i++)
#pragma unroll
        for (int j = 0; j < 4; j++) accO[i][j] = 0.f;
    float mrow0 = -INFINITY, mrow1 = -INFINITY, lrow0 = 0.f, lrow1 = 0.f;
    const float SC = 0.125f * 1.44269504f;   // scale * log2(e)

    for (int kt = 0; kt <= qt; kt++) {
        __syncthreads();
        for (int i = tid; i < 512; i += 128) {
            int r = i >> 3, ch = i & 7;
            *(uint4*)((char*)pQh + 2*FTILE + r * FROW + ch * 16) =
                *(const uint4*)(Kh + (size_t)(kt * 64 + r) * HEADD + ch * 8);
            *(uint4*)((char*)pQh + 3*FTILE + r * FROW + ch * 16) =
                *(const uint4*)(Kl + (size_t)(kt * 64 + r) * HEADD + ch * 8);
            *(uint4*)((char*)pQh + 4*FTILE + r * FROW + ch * 16) =
                *(const uint4*)(Vh + (size_t)r * SEQ + kt * 64 + ch * 8);
            *(uint4*)((char*)pQh + 5*FTILE + r * FROW + ch * 16) =
                *(const uint4*)(Vl + (size_t)r * SEQ + kt * 64 + ch * 8);
        }
        __syncthreads();

        // S = Q K^T  (8 key n-tiles)
        float sacc[8][4];
#pragma unroll
        for (int nt = 0; nt < 8; nt++)
#pragma unroll
            for (int j = 0; j < 4; j++) sacc[nt][j] = 0.f;
#pragma unroll
        for (int ks = 0; ks < 4; ks++) {
#pragma unroll
            for (int nt = 0; nt < 8; nt++) {
                uint32_t kh2[2], kl2[2];
                uint32_t bo = (uint32_t)(nt * 8 + (lane & 7)) * FROW + ks * 32 + ((lane >> 3) & 1) * 16;
                LDSM2(kh2, sKh + bo);
                LDSM2(kl2, sKl + bo);
                MMA_BF16(sacc[nt], qfh[ks], kh2);
                MMA_BF16(sacc[nt], qfh[ks], kl2);
                MMA_BF16(sacc[nt], qfl[ks], kh2);
            }
        }

        int grow = qt * 64 + w * 16 + (lane >> 2);
        if (kt == qt) {
#pragma unroll
            for (int nt = 0; nt < 8; nt++) {
                int cbase = kt * 64 + nt * 8 + (lane & 3) * 2;
                sacc[nt][0] = (cbase     <= grow    ) ? sacc[nt][0] * SC : -1e30f;
                sacc[nt][1] = (cbase + 1 <= grow    ) ? sacc[nt][1] * SC : -1e30f;
                sacc[nt][2] = (cbase     <= grow + 8) ? sacc[nt][2] * SC : -1e30f;
                sacc[nt][3] = (cbase + 1 <= grow + 8) ? sacc[nt][3] * SC : -1e30f;
            }
        } else {
#pragma unroll
            for (int nt = 0; nt < 8; nt++)
#pragma unroll
                for (int j = 0; j < 4; j++) sacc[nt][j] *= SC;
        }

        // row max (base-2 domain)
        float mx0 = -INFINITY, mx1 = -INFINITY;
#pragma unroll
        for (int nt = 0; nt < 8; nt++) {
            mx0 = fmaxf(mx0, fmaxf(sacc[nt][0], sacc[nt][1]));
            mx1 = fmaxf(mx1, fmaxf(sacc[nt][2], sacc[nt][3]));
        }
        mx0 = fmaxf(mx0, __shfl_xor_sync(0xffffffffu, mx0, 1));
        mx0 = fmaxf(mx0, __shfl_xor_sync(0xffffffffu, mx0, 2));
        mx1 = fmaxf(mx1, __shfl_xor_sync(0xffffffffu, mx1, 1));
        mx1 = fmaxf(mx1, __shfl_xor_sync(0xffffffffu, mx1, 2));
        float mn0 = fmaxf(mrow0, mx0), mn1 = fmaxf(mrow1, mx1);
        float al0 = exp2f(mrow0 - mn0), al1 = exp2f(mrow1 - mn1);
        mrow0 = mn0; mrow1 = mn1;
#pragma unroll
        for (int nt = 0; nt < 8; nt++) {
            accO[nt][0] *= al0; accO[nt][1] *= al0;
            accO[nt][2] *= al1; accO[nt][3] *= al1;
        }
        lrow0 *= al0; lrow1 *= al1;

        float sum0 = 0.f, sum1 = 0.f;
#pragma unroll
        for (int ks = 0; ks < 4; ks++) {   // 16 keys per step = tiles 2ks, 2ks+1
            float p[2][4];
#pragma unroll
            for (int h2 = 0; h2 < 2; h2++) {
                int nt = ks * 2 + h2;
                p[h2][0] = exp2f(sacc[nt][0] - mn0);
                p[h2][1] = exp2f(sacc[nt][1] - mn0);
                p[h2][2] = exp2f(sacc[nt][2] - mn1);
                p[h2][3] = exp2f(sacc[nt][3] - mn1);
                sum0 += p[h2][0] + p[h2][1];
                sum1 += p[h2][2] + p[h2][3];
            }
            uint32_t pfh[4], pfl[4];
            packsplit(p[0][0], p[0][1], &pfh[0], &pfl[0]);
            packsplit(p[0][2], p[0][3], &pfh[1], &pfl[1]);
            packsplit(p[1][0], p[1][1], &pfh[2], &pfl[2]);
            packsplit(p[1][2], p[1][3], &pfh[3], &pfl[3]);
#pragma unroll
            for (int ntd = 0; ntd < 8; ntd++) {
                uint32_t vh2[2], vl2[2];
                uint32_t vo = (uint32_t)(ntd * 8 + (lane & 7)) * FROW + ks * 32 + ((lane >> 3) & 1) * 16;
                LDSM2(vh2, sVh + vo);
                LDSM2(vl2, sVl + vo);
                MMA_BF16(accO[ntd], pfh, vh2);
                MMA_BF16(accO[ntd], pfh, vl2);
                MMA_BF16(accO[ntd], pfl, vh2);
            }
        }
        sum0 += __shfl_xor_sync(0xffffffffu, sum0, 1);
        sum0 += __shfl_xor_sync(0xffffffffu, sum0, 2);
        sum1 += __shfl_xor_sync(0xffffffffu, sum1, 1);
        sum1 += __shfl_xor_sync(0xffffffffu, sum1, 2);
        lrow0 += sum0; lrow1 += sum1;
    }

    float inv0 = 1.f / lrow0, inv1 = 1.f / lrow1;
    int row0 = qt * 64 + w * 16 + (lane >> 2);
    size_t rb = ((size_t)bb * SEQ + row0) * HDIM + hh * HEADD + (lane & 3) * 2;
#pragma unroll
    for (int ntd = 0; ntd < 8; ntd++) {
        uint32_t h, l;
        packsplit(accO[ntd][0] * inv0, accO[ntd][1] * inv0, &h, &l);
        *(uint32_t*)(g_oh + rb + ntd * 8) = h;
        *(uint32_t*)(g_ol + rb + ntd * 8) = l;
        packsplit(accO[ntd][2] * inv1, accO[ntd][3] * inv1, &h, &l);
        *(uint32_t*)(g_oh + rb + 8 * HDIM + ntd * 8) = h;
        *(uint32_t*)(g_ol + rb + 8 * HDIM + ntd * 8) = l;
    }
}

// ================= MoE gating =================
__global__ void zero_cnt_kernel() { if (threadIdx.x < NEXP) g_cnt[threadIdx.x] = 0; }

__global__ void gate_kernel(const float* __restrict__ gw) {
    int t = blockIdx.x * 8 + (threadIdx.x >> 5);
    int lane = threadIdx.x & 31;
    const float* xr = g_x1n + (size_t)t * HDIM;
    float acc[8] = {0, 0, 0, 0, 0, 0, 0, 0};
    for (int j = lane; j < HDIM; j += 32) {
        float xv = xr[j];
        const float* gr = gw + j * 8;
        float4 g0 = *(const float4*)gr, g1 = *(const float4*)(gr + 4);
        acc[0] += xv * g0.x; acc[1] += xv * g0.y; acc[2] += xv * g0.z; acc[3] += xv * g0.w;
        acc[4] += xv * g1.x; acc[5] += xv * g1.y; acc[6] += xv * g1.z; acc[7] += xv * g1.w;
    }
#pragma unroll
    for (int e = 0; e < 8; e++)
        for (int o = 16; o; o >>= 1) acc[e] += __shfl_xor_sync(0xffffffffu, acc[e], o);
    if (lane == 0) {
        float mx = acc[0];
#pragma unroll
        for (int e = 1; e < 8; e++) mx = fmaxf(mx, acc[e]);
        float se = 0.f;
#pragma unroll
        for (int e = 0; e < 8; e++) se += expf(acc[e] - mx);
        float lse = mx + logf(se);
        g_lse2[t] = lse * lse;
        int i0 = 0; float v0 = acc[0];
#pragma unroll
        for (int e = 1; e < 8; e++) if (acc[e] > v0) { v0 = acc[e]; i0 = e; }
        int i1 = -1; float v1 = -INFINITY;
#pragma unroll
        for (int e = 0; e < 8; e++) if (e != i0 && acc[e] > v1) { v1 = acc[e]; i1 = e; }
        float w0 = 1.f / (1.f + expf(v1 - v0));
        float w1 = 1.f - w0;
        int p0 = atomicAdd(&g_cnt[i0], 1);
        g_rows[i0 * T_TOK + p0] = t;
        int p1 = atomicAdd(&g_cnt[i1], 1);
        g_rows[i1 * T_TOK + p1] = t;
        g_ie[2*t] = i0; g_islot[2*t] = p0; g_iw[2*t] = w0;
        g_ie[2*t+1] = i1; g_islot[2*t+1] = p1; g_iw[2*t+1] = w1;
    }
}

__global__ void aux_kernel(float* __restrict__ out) {
    __shared__ float red[32];
    float s = 0.f;
    for (int i = threadIdx.x; i < T_TOK; i += 1024) s += g_lse2[i];
    for (int o = 16; o; o >>= 1) s += __shfl_xor_sync(0xffffffffu, s, o);
    if ((threadIdx.x & 31) == 0) red[threadIdx.x >> 5] = s;
    __syncthreads();
    if (threadIdx.x < 32) {
        float v = red[threadIdx.x];
        for (int o = 16; o; o >>= 1) v += __shfl_xor_sync(0xffffffffu, v, o);
        if (threadIdx.x == 0) out[(size_t)T_TOK * HDIM] = 0.001f * v / (float)T_TOK;
    }
}

// batched gather: grid (T_TOK, NEXP), 192 threads
__global__ void gather_kernel() {
    int e = blockIdx.y, r = blockIdx.x;
    if (r >= g_cnt[e]) return;
    int t = g_rows[e * T_TOK + r];
    float4 v = ((const float4*)(g_x1n + (size_t)t * HDIM))[threadIdx.x];
    size_t o = ((size_t)e * T_TOK + r) * HDIM + threadIdx.x * 4;
    split1(v.x, &g_xgh[o + 0], &g_xgl[o + 0]);
    split1(v.y, &g_xgh[o + 1], &g_xgl[o + 1]);
    split1(v.z, &g_xgh[o + 2], &g_xgl[o + 2]);
    split1(v.w, &g_xgh[o + 3], &g_xgl[o + 3]);
}

// batched silu: grid (T_TOK, NEXP), 256 threads; reads g_h [e][r][gate|up]
__global__ void silu_kernel() {
    int e = blockIdx.y, r = blockIdx.x;
    if (r >= g_cnt[e]) return;
    const float* hrow = g_h + ((size_t)e * T_TOK + r) * (2 * IDIM);
    const float4* hg4 = (const float4*)hrow;
    const float4* hu4 = (const float4*)(hrow + IDIM);
    size_t ob = ((size_t)e * T_TOK + r) * IDIM;
    for (int i = threadIdx.x; i < IDIM / 4; i += 256) {
        float4 a = hg4[i], b = hu4[i];
        float f0 = a.x / (1.f + expf(-a.x)) * b.x;
        float f1 = a.y / (1.f + expf(-a.y)) * b.y;
        float f2 = a.z / (1.f + expf(-a.z)) * b.z;
        float f3 = a.w / (1.f + expf(-a.w)) * b.w;
        size_t o = ob + i * 4;
        split1(f0, &g_hgh[o + 0], &g_hgl[o + 0]);
        split1(f1, &g_hgh[o + 1], &g_hgl[o + 1]);
        split1(f2, &g_hgh[o + 2], &g_hgl[o + 2]);
        split1(f3, &g_hgh[o + 3], &g_hgl[o + 3]);
    }
}

// deterministic combine: out = x1 + w0*dg[e0][slot0] + w1*dg[e1][slot1]
__global__ void combine_kernel(float* __restrict__ out) {
    int t = blockIdx.x;
    int i0 = g_ie[2*t], i1 = g_ie[2*t+1];
    int p0 = g_islot[2*t], p1 = g_islot[2*t+1];
    float w0 = g_iw[2*t], w1 = g_iw[2*t+1];
    const float4* d0 = (const float4*)(g_dg + ((size_t)i0 * T_TOK + p0) * HDIM);
    const float4* d1 = (const float4*)(g_dg + ((size_t)i1 * T_TOK + p1) * HDIM);
    const float4* xr = (const float4*)(g_x1 + (size_t)t * HDIM);
    float4* o = (float4*)(out + (size_t)t * HDIM);
    int c = threadIdx.x;
    float4 a = xr[c], b0 = d0[c], b1 = d1[c];
    a.x += w0 * b0.x + w1 * b1.x;
    a.y += w0 * b0.y + w1 * b1.y;
    a.z += w0 * b0.z + w1 * b1.z;
    a.w += w0 * b0.w + w1 * b1.w;
    o[c] = a;
}

// ================= launch =================
#define GSA(var, sym) do { void* _p; cudaGetSymbolAddress(&_p, sym); var = (decltype(var))_p; } while (0)

extern "C" void kernel_launch(void* const* d_in, const int* in_sizes, int n_in,
                              void* d_out, int out_size) {
    const float* hidden = (const float*)d_in[0];
    const float* wq    = (const float*)d_in[2];
    const float* wk    = (const float*)d_in[3];
    const float* wv    = (const float*)d_in[4];
    const float* wo    = (const float*)d_in[5];
    const float* ln1   = (const float*)d_in[6];
    const float* ln2   = (const float*)d_in[7];
    const float* gw    = (const float*)d_in[8];
    const float* wgate = (const float*)d_in[9];
    const float* wup   = (const float*)d_in[10];
    const float* wdown = (const float*)d_in[11];
    float* out = (float*)d_out;

    float *qkv, *x1, *x1n, *hbuf, *dg;
    int* cnt;
    __nv_bfloat16 *ah, *al, *oh, *ol, *xgh, *xgl, *hgh, *hgl;
    __nv_bfloat16 *wqkvh, *wqkvl, *woh, *wol, *wguh, *wgul, *wdnh, *wdnl;
    GSA(qkv, g_qkv); GSA(x1, g_x1); GSA(x1n, g_x1n);
    GSA(hbuf, g_h); GSA(dg, g_dg); GSA(cnt, g_cnt);
    GSA(ah, g_ah); GSA(al, g_al); GSA(oh, g_oh); GSA(ol, g_ol);
    GSA(xgh, g_xgh); GSA(xgl, g_xgl); GSA(hgh, g_hgh); GSA(hgl, g_hgl);
    GSA(wqkvh, g_wqkvh); GSA(wqkvl, g_wqkvl); GSA(woh, g_woh); GSA(wol, g_wol);
    GSA(wguh, g_wguh); GSA(wgul, g_wgul); GSA(wdnh, g_wdnh); GSA(wdnl, g_wdnl);

    cudaFuncSetAttribute((const void*)tmma_kernel,
                         cudaFuncAttributeMaxDynamicSharedMemorySize, TMMA_SMEM);
    cudaFuncSetAttribute((const void*)flashmma_kernel,
                         cudaFuncAttributeMaxDynamicSharedMemorySize, FLASH_SMEM);

    dim3 cb(32, 8);
    // weight conversion
    wconv_kernel<<<dim3(24, 24, 1), cb>>>(wq, wqkvh,            wqkvl,            HDIM, HDIM, 0, 0);
    wconv_kernel<<<dim3(24, 24, 1), cb>>>(wk, wqkvh + 768*768,  wqkvl + 768*768,  HDIM, HDIM, 0, 0);
    wconv_kernel<<<dim3(24, 24, 1), cb>>>(wv, wqkvh + 1536*768, wqkvl + 1536*768, HDIM, HDIM, 0, 0);
    wconv_kernel<<<dim3(24, 24, 1), cb>>>(wo, woh, wol, HDIM, HDIM, 0, 0);
    wconv_kernel<<<dim3(64, 24, NEXP), cb>>>(wgate, wguh,            wgul,            HDIM, IDIM,
                                             (size_t)HDIM*IDIM, (size_t)2*IDIM*HDIM);
    wconv_kernel<<<dim3(64, 24, NEXP), cb>>>(wup,   wguh + 2048*768, wgul + 2048*768, HDIM, IDIM,
                                             (size_t)HDIM*IDIM, (size_t)2*IDIM*HDIM);
    wconv_kernel<<<dim3(24, 64, NEXP), cb>>>(wdown, wdnh, wdnl, IDIM, HDIM,
                                             (size_t)IDIM*HDIM, (size_t)HDIM*IDIM);

    // 1. RMSNorm -> bf16 hi/lo
    rmsnorm_bf16_kernel<<<T_TOK, 256>>>(hidden, ln1, ah, al);

    // 2. fused QKV projection (N=2304)
    tmma_kernel<<<dim3(18, 32, 1), 256, TMMA_SMEM>>>(ah, al, wqkvh, wqkvl, qkv,
                                                     T_TOK, nullptr, 2304, HDIM, nullptr, 0, 0, 0);

    // 3. RoPE (+ V transpose + splits)
    rope_table_kernel<<<(SEQ * 32 + 255) / 256, 256>>>();
    rope_kernel<<<dim3(SEQ, NHEADS, BATCH), 64>>>();

    // 4. tensor-core causal flash attention
    flashmma_kernel<<<dim3(32, NHEADS, BATCH), 128, FLASH_SMEM>>>();

    // 5. output projection + residual
    tmma_kernel<<<dim3(6, 32, 1), 256, TMMA_SMEM>>>(oh, ol, woh, wol, x1,
                                                    T_TOK, nullptr, HDIM, HDIM, hidden, 0, 0, 0);

    // 6. post-attention RMSNorm
    rmsnorm_f32_kernel<<<T_TOK, 256>>>(x1, ln2, x1n);

    // 7. gating + aux
    zero_cnt_kernel<<<1, 32>>>();
    gate_kernel<<<T_TOK / 8, 256>>>(gw);
    aux_kernel<<<1, 1024>>>(out);

    // 8. batched MoE
    gather_kernel<<<dim3(T_TOK, NEXP), 192>>>();
    tmma_kernel<<<dim3(32, 32, NEXP), 256, TMMA_SMEM>>>(xgh, xgl, wguh, wgul, hbuf,
        0, cnt, 2 * IDIM, HDIM, nullptr,
        (size_t)T_TOK * HDIM, (size_t)2 * IDIM * HDIM, (size_t)T_TOK * 2 * IDIM);
    silu_kernel<<<dim3(T_TOK, NEXP), 256>>>();
    tmma_kernel<<<dim3(6, 32, NEXP), 256, TMMA_SMEM>>>(hgh, hgl, wdnh, wdnl, dg,
        0, cnt, HDIM, IDIM, nullptr,
        (size_t)T_TOK * IDIM, (size_t)HDIM * IDIM, (size_t)T_TOK * HDIM);

    // 9. deterministic combine (residual + weighted expert outputs)
    combine_kernel<<<T_TOK, 192>>>(out);
}

// round 5
// speedup vs baseline: 3.4210x; 1.0302x over previous
#include <cuda_runtime.h>
#include <cuda_bf16.h>
#include <math.h>
#include <stdint.h>

// ---- problem constants ----
#define T_TOK 4096      // B*S
#define SEQ   2048
#define BATCH 2
#define HDIM  768
#define NHEADS 12
#define HEADD 64
#define IDIM  2048
#define NEXP  8

// ---- fp32 scratch ----
__device__ __align__(128) float g_qkv [T_TOK*2304];
__device__ __align__(128) float g_x1  [T_TOK*HDIM];
__device__ __align__(128) float g_x1n [T_TOK*HDIM];
__device__ __align__(128) float g_dg  [(size_t)NEXP*T_TOK*HDIM];
__device__ float g_cos [SEQ*32];
__device__ float g_sin [SEQ*32];
__device__ float g_lse2[T_TOK];
__device__ int   g_cnt [NEXP];
__device__ int   g_rows[NEXP*T_TOK];
__device__ int   g_ie  [2*T_TOK];
__device__ int   g_islot[2*T_TOK];
__device__ float g_iw  [2*T_TOK];

// ---- bf16 hi/lo activations ----
__device__ __align__(128) __nv_bfloat16 g_ah [T_TOK*HDIM];
__device__ __align__(128) __nv_bfloat16 g_al [T_TOK*HDIM];
__device__ __align__(128) __nv_bfloat16 g_qh [T_TOK*HDIM];  // [b,h,s,d]
__device__ __align__(128) __nv_bfloat16 g_ql [T_TOK*HDIM];
__device__ __align__(128) __nv_bfloat16 g_kh [T_TOK*HDIM];
__device__ __align__(128) __nv_bfloat16 g_kl [T_TOK*HDIM];
__device__ __align__(128) __nv_bfloat16 g_vth[T_TOK*HDIM];  // [b,h,d,s]
__device__ __align__(128) __nv_bfloat16 g_vtl[T_TOK*HDIM];
__device__ __align__(128) __nv_bfloat16 g_oh [T_TOK*HDIM];
__device__ __align__(128) __nv_bfloat16 g_ol [T_TOK*HDIM];
__device__ __align__(128) __nv_bfloat16 g_xgh[(size_t)NEXP*T_TOK*HDIM];
__device__ __align__(128) __nv_bfloat16 g_xgl[(size_t)NEXP*T_TOK*HDIM];
__device__ __align__(128) __nv_bfloat16 g_hgh[(size_t)NEXP*T_TOK*IDIM];
__device__ __align__(128) __nv_bfloat16 g_hgl[(size_t)NEXP*T_TOK*IDIM];

// ---- bf16 hi/lo weights ([N,K] K-major; gate/up interleaved in 64-row groups) ----
__device__ __align__(128) __nv_bfloat16 g_wqkvh[2304*HDIM];
__device__ __align__(128) __nv_bfloat16 g_wqkvl[2304*HDIM];
__device__ __align__(128) __nv_bfloat16 g_woh[HDIM*HDIM];
__device__ __align__(128) __nv_bfloat16 g_wol[HDIM*HDIM];
__device__ __align__(128) __nv_bfloat16 g_wguh[(size_t)NEXP*2*IDIM*HDIM];
__device__ __align__(128) __nv_bfloat16 g_wgul[(size_t)NEXP*2*IDIM*HDIM];
__device__ __align__(128) __nv_bfloat16 g_wdnh[(size_t)NEXP*HDIM*IDIM];
__device__ __align__(128) __nv_bfloat16 g_wdnl[(size_t)NEXP*HDIM*IDIM];

// ================= helpers =================
__device__ __forceinline__ uint32_t s2u(const void* p) {
    uint32_t a;
    asm("{ .reg .u64 t; cvta.to.shared.u64 t, %1; cvt.u32.u64 %0, t; }" : "=r"(a) : "l"(p));
    return a;
}
__device__ __forceinline__ void split1(float v, __nv_bfloat16* hp, __nv_bfloat16* lp) {
    __nv_bfloat16 h = __float2bfloat16(v);
    *hp = h;
    *lp = __float2bfloat16(v - __bfloat162float(h));
}
__device__ __forceinline__ void packsplit(float a, float b, uint32_t* hi, uint32_t* lo) {
    __nv_bfloat16 ah = __float2bfloat16(a), bh = __float2bfloat16(b);
    __nv_bfloat16 alr = __float2bfloat16(a - __bfloat162float(ah));
    __nv_bfloat16 blr = __float2bfloat16(b - __bfloat162float(bh));
    __nv_bfloat162 h2; h2.x = ah; h2.y = bh;
    __nv_bfloat162 l2; l2.x = alr; l2.y = blr;
    *hi = *(uint32_t*)&h2; *lo = *(uint32_t*)&l2;
}

#define LDSM4(r, a) \
    asm volatile("ldmatrix.sync.aligned.m8n8.x4.shared.b16 {%0,%1,%2,%3}, [%4];" \
        : "=r"((r)[0]), "=r"((r)[1]), "=r"((r)[2]), "=r"((r)[3]) : "r"(a))
#define LDSM2(r, a) \
    asm volatile("ldmatrix.sync.aligned.m8n8.x2.shared.b16 {%0,%1}, [%2];" \
        : "=r"((r)[0]), "=r"((r)[1]) : "r"(a))
#define MMA_BF16(c, a, b) \
    asm volatile("mma.sync.aligned.m16n8k16.row.col.f32.bf16.bf16.f32 " \
        "{%0,%1,%2,%3}, {%4,%5,%6,%7}, {%8,%9}, {%0,%1,%2,%3};" \
        : "+f"((c)[0]), "+f"((c)[1]), "+f"((c)[2]), "+f"((c)[3]) \
        : "r"((a)[0]), "r"((a)[1]), "r"((a)[2]), "r"((a)[3]), "r"((b)[0]), "r"((b)[1]))
#define CP_ASYNC16(dst, src) \
    asm volatile("cp.async.cg.shared.global [%0], [%1], 16;" :: "r"(dst), "l"(src))

// ================= weight transpose + hi/lo split (fast) =================
// fp32 W[K,N] -> bf16 hi/lo [N,K]; mode 0 identity, 1 gate-interleave, 2 up-interleave.
// tile 64k x 64n, 256 threads, float4 loads, uint4 (8xbf16) stores.
__global__ __launch_bounds__(256) void wconv_kernel(
    const float* __restrict__ W, __nv_bfloat16* __restrict__ oh,
    __nv_bfloat16* __restrict__ ol, int K, int N,
    size_t inZ, size_t outZ, int mode, int dstOff)
{
    W  += (size_t)blockIdx.z * inZ;
    oh += (size_t)blockIdx.z * outZ;
    ol += (size_t)blockIdx.z * outZ;
    __shared__ float s[64][65];
    int n0 = blockIdx.x * 64, k0 = blockIdx.y * 64;
    int tid = threadIdx.x;
    int lr = tid >> 4;
    int lc = (tid & 15) * 4;
#pragma unroll
    for (int p = 0; p < 4; p++) {
        int kk = p * 16 + lr;
        float4 v = *(const float4*)(W + (size_t)(k0 + kk) * N + n0 + lc);
        s[lc + 0][kk] = v.x; s[lc + 1][kk] = v.y;
        s[lc + 2][kk] = v.z; s[lc + 3][kk] = v.w;
    }
    __syncthreads();
    int nl = tid >> 3;
    int kq = (tid & 7) * 8;
#pragma unroll
    for (int p = 0; p < 2; p++) {
        int nn = p * 32 + nl;
        int ng = n0 + nn;
        int nd = (mode == 0) ? ng : ((ng >> 6) * 128 + (ng & 63) + ((mode == 2) ? 64 : 0));
        nd += dstOff;
        __nv_bfloat16 hb[8], lb[8];
#pragma unroll
        for (int j = 0; j < 8; j++)
            split1(s[nn][kq + j], &hb[j], &lb[j]);
        *(uint4*)(oh + (size_t)nd * K + k0 + kq) = *(uint4*)hb;
        *(uint4*)(ol + (size_t)nd * K + k0 + kq) = *(uint4*)lb;
    }
}

// ================= mma.sync split-bf16 GEMM (batched; optional fused silu) ===========
#define TMMA_SMEM 81920

__global__ __launch_bounds__(256) void tmma_kernel(
    const __nv_bfloat16* __restrict__ Ah, const __nv_bfloat16* __restrict__ Al,
    const __nv_bfloat16* __restrict__ Bh, const __nv_bfloat16* __restrict__ Bl,
    float* __restrict__ C, int M, const int* __restrict__ cntArr,
    int N, int K, const float* __restrict__ Cadd,
    size_t zsA, size_t zsB, size_t zsC,
    __nv_bfloat16* __restrict__ SOh, __nv_bfloat16* __restrict__ SOl, int fuseSilu)
{
    int z = blockIdx.z;
    int m = cntArr ? cntArr[z] : M;
    int row0 = blockIdx.y * 128;
    if (row0 >= m) return;
    int col0 = blockIdx.x * 128;
    Ah += zsA * z; Al += zsA * z; Bh += zsB * z; Bl += zsB * z;
    if (fuseSilu) { SOh += zsC * z; SOl += zsC * z; } else { C += zsC * z; }

    extern __shared__ char sm[];
    uint32_t sbase = s2u(sm);
    int tid = threadIdx.x, lane = tid & 31, wid = tid >> 5;
    int wm = wid & 1, wn = wid >> 1;

    const __nv_bfloat16* sp[4];
    sp[0] = Ah + (size_t)row0 * K;
    sp[1] = Al + (size_t)row0 * K;
    sp[2] = Bh + (size_t)col0 * K;
    sp[3] = Bl + (size_t)col0 * K;

    float acc[4][4][4];
#pragma unroll
    for (int a = 0; a < 4; a++)
#pragma unroll
        for (int b = 0; b < 4; b++)
#pragma unroll
            for (int c = 0; c < 4; c++) acc[a][b][c] = 0.f;

    int NC = K >> 5;

#define LOAD_STAGE(cc, ss) do { \
    uint32_t _db = sbase + (ss) * 40960; \
    _Pragma("unroll") \
    for (int _t = 0; _t < 4; _t++) { \
        _Pragma("unroll") \
        for (int _i = 0; _i < 2; _i++) { \
            int _idx = tid + _i * 256; \
            int _r = _idx >> 2, _ch = _idx & 3; \
            uint32_t _dst = _db + _t * 10240 + _r * 80 + _ch * 16; \
            const void* _src = sp[_t] + (size_t)_r * K + (cc) * 32 + _ch * 8; \
            CP_ASYNC16(_dst, _src); \
        } \
    } \
    asm volatile("cp.async.commit_group;"); \
} while (0)

    LOAD_STAGE(0, 0);

    for (int c = 0; c < NC; c++) {
        if (c + 1 < NC) {
            LOAD_STAGE(c + 1, (c + 1) & 1);
            asm volatile("cp.async.wait_group 1;");
        } else {
            asm volatile("cp.async.wait_group 0;");
        }
        __syncthreads();

        uint32_t db = sbase + (c & 1) * 40960;
        uint32_t aH = db, aL = db + 10240, bH = db + 20480, bL = db + 30720;
#pragma unroll
        for (int ks = 0; ks < 2; ks++) {
            uint32_t ah[4][4], al[4][4], bh[4][2], bl[4][2];
            uint32_t aoff = (uint32_t)(wm * 64 + (lane & 15)) * 80 + ks * 32 + (lane >> 4) * 16;
            uint32_t boff = (uint32_t)(wn * 32 + (lane & 7)) * 80 + ks * 32 + ((lane >> 3) & 1) * 16;
#pragma unroll
            for (int mt = 0; mt < 4; mt++) {
                LDSM4(ah[mt], aH + aoff + mt * 1280);
                LDSM4(al[mt], aL + aoff + mt * 1280);
            }
#pragma unroll
            for (int nt = 0; nt < 4; nt++) {
                LDSM2(bh[nt], bH + boff + nt * 640);
                LDSM2(bl[nt], bL + boff + nt * 640);
            }
#pragma unroll
            for (int mt = 0; mt < 4; mt++)
#pragma unroll
                for (int nt = 0; nt < 4; nt++) {
                    MMA_BF16(acc[mt][nt], ah[mt], bh[nt]);
                    MMA_BF16(acc[mt][nt], ah[mt], bl[nt]);
                    MMA_BF16(acc[mt][nt], al[mt], bh[nt]);
                }
        }
        __syncthreads();
    }

    if (fuseSilu) {
        // stage 128x128 fp32 tile, compute silu(gate)*up, write bf16 hi/lo
        float* st = (float*)sm;   // row stride 132 floats
#pragma unroll
        for (int mt = 0; mt < 4; mt++) {
            int r = wm * 64 + mt * 16 + (lane >> 2);
            int cbase = wn * 32 + (lane & 3) * 2;
#pragma unroll
            for (int half = 0; half < 2; half++) {
#pragma unroll
                for (int nt = 0; nt < 4; nt++) {
                    float2 v; v.x = acc[mt][nt][half * 2 + 0]; v.y = acc[mt][nt][half * 2 + 1];
                    *(float2*)&st[(r + half * 8) * 132 + cbase + nt * 8] = v;
                }
            }
        }
        __syncthreads();
        int lr = tid >> 4;
        int lc = (tid & 15) * 4;
        int colg = blockIdx.x * 64 + lc;
#pragma unroll
        for (int p = 0; p < 8; p++) {
            int r = p * 16 + lr;
            int gr = row0 + r;
            if (gr < m) {
                float4 gv = *(float4*)&st[r * 132 + lc];
                float4 uv = *(float4*)&st[r * 132 + 64 + lc];
                float f0 = gv.x / (1.f + expf(-gv.x)) * uv.x;
                float f1 = gv.y / (1.f + expf(-gv.y)) * uv.y;
                float f2 = gv.z / (1.f + expf(-gv.z)) * uv.z;
                float f3 = gv.w / (1.f + expf(-gv.w)) * uv.w;
                uint32_t h0, l0, h1, l1;
                packsplit(f0, f1, &h0, &l0);
                packsplit(f2, f3, &h1, &l1);
                size_t o = (size_t)gr * IDIM + colg;
                uint2 hv; hv.x = h0; hv.y = h1;
                uint2 lv; lv.x = l0; lv.y = l1;
                *(uint2*)(SOh + o) = hv;
                *(uint2*)(SOl + o) = lv;
            }
        }
        return;
    }

#pragma unroll
    for (int mt = 0; mt < 4; mt++) {
        int rbase = row0 + wm * 64 + mt * 16 + (lane >> 2);
#pragma unroll
        for (int half = 0; half < 2; half++) {
            int rr = rbase + half * 8;
            if (rr < m) {
                size_t o = (size_t)rr * N + col0 + wn * 32 + (lane & 3) * 2;
#pragma unroll
                for (int nt = 0; nt < 4; nt++) {
                    float v0 = acc[mt][nt][half * 2 + 0];
                    float v1 = acc[mt][nt][half * 2 + 1];
                    size_t oo = o + nt * 8;
                    if (Cadd) {
                        float2 ad = *(const float2*)(Cadd + oo);
                        v0 += ad.x; v1 += ad.y;
                    }
                    float2 st2; st2.x = v0; st2.y = v1;
                    *(float2*)(C + oo) = st2;
                }
            }
        }
    }
}

// ================= RMSNorm =================
__device__ __forceinline__ float block_rms(const float* xr, int tid) {
    float s = 0.f;
    for (int c = tid; c < HDIM; c += 256) { float v = xr[c]; s += v * v; }
    __shared__ float red[8];
    for (int o = 16; o; o >>= 1) s += __shfl_xor_sync(0xffffffffu, s, o);
    if ((tid & 31) == 0) red[tid >> 5] = s;
    __syncthreads();
    if (tid < 8) {
        float v = red[tid];
        for (int o = 4; o; o >>= 1) v += __shfl_xor_sync(0xffu, v, o);
        if (tid == 0) red[0] = v;
    }
    __syncthreads();
    return rsqrtf(red[0] / (float)HDIM + 1e-6f);
}

__global__ void rmsnorm_bf16_kernel(const float* __restrict__ x, const float* __restrict__ w,
                                    __nv_bfloat16* __restrict__ oh, __nv_bfloat16* __restrict__ ol) {
    int row = blockIdx.x;
    const float* xr = x + (size_t)row * HDIM;
    float scale = block_rms(xr, threadIdx.x);
    for (int c = threadIdx.x; c < HDIM; c += 256) {
        float v = w[c] * xr[c] * scale;
        split1(v, &oh[(size_t)row * HDIM + c], &ol[(size_t)row * HDIM + c]);
    }
}

__global__ void rmsnorm_f32_kernel(const float* __restrict__ x, const float* __restrict__ w,
                                   float* __restrict__ out) {
    int row = blockIdx.x;
    if (row == 0 && threadIdx.x < NEXP) g_cnt[threadIdx.x] = 0;   // fold counter zeroing
    const float* xr = x + (size_t)row * HDIM;
    float scale = block_rms(xr, threadIdx.x);
    for (int c = threadIdx.x; c < HDIM; c += 256)
        out[(size_t)row * HDIM + c] = w[c] * xr[c] * scale;
}

// ================= RoPE =================
__global__ void rope_table_kernel() {
    int idx = blockIdx.x * blockDim.x + threadIdx.x;
    if (idx >= SEQ * 32) return;
    int i = idx & 31, s = idx >> 5;
    float inv = powf(10000.0f, -(float)i / 32.0f);
    float ang = (float)s * inv;
    g_cos[idx] = cosf(ang);
    g_sin[idx] = sinf(ang);
}

__global__ void rope_kernel() {
    int s = blockIdx.x, hh = blockIdx.y, bb = blockIdx.z, d = threadIdx.x;
    int t = bb * SEQ + s;
    const float* qkv = g_qkv + (size_t)t * 2304;
    int col  = hh * HEADD + d;
    int pcol = hh * HEADD + (d < 32 ? d + 32 : d - 32);
    float qv = qkv[col], kv = qkv[768 + col], vv = qkv[1536 + col];
    float qp = qkv[pcol], kp = qkv[768 + pcol];
    float cs = g_cos[s * 32 + (d & 31)], sn = g_sin[s * 32 + (d & 31)];
    float sgn = (d < 32) ? -1.f : 1.f;
    float qr = qv * cs + sgn * qp * sn;
    float kr = kv * cs + sgn * kp * sn;
    size_t dst = (((size_t)bb * NHEADS + hh) * SEQ + s) * HEADD + d;
    split1(qr, &g_qh[dst], &g_ql[dst]);
    split1(kr, &g_kh[dst], &g_kl[dst]);
    size_t vdst = (((size_t)bb * NHEADS + hh) * HEADD + d) * SEQ + s;
    split1(vv, &g_vth[vdst], &g_vtl[vdst]);
}

// ================= tensor-core flash attention =================
#define FROW 144
#define FTILE 9216
#define FLASH_SMEM (6*FTILE)

__global__ __launch_bounds__(128) void flashmma_kernel() {
    int qt = 31 - (int)blockIdx.x;
    int hh = blockIdx.y, bb = blockIdx.z;
    extern __shared__ char fsm[];
    uint32_t sb = s2u(fsm);
    uint32_t sQh = sb, sQl = sb + FTILE, sKh = sb + 2*FTILE, sKl = sb + 3*FTILE;
    uint32_t sVh = sb + 4*FTILE, sVl = sb + 5*FTILE;
    __nv_bfloat16* pQh = (__nv_bfloat16*)fsm;

    int tid = threadIdx.x, lane = tid & 31, w = tid >> 5;
    size_t hb = (size_t)bb * NHEADS + hh;
    const __nv_bfloat16* Qh = g_qh + hb * SEQ * HEADD;
    const __nv_bfloat16* Ql = g_ql + hb * SEQ * HEADD;
    const __nv_bfloat16* Kh = g_kh + hb * SEQ * HEADD;
    const __nv_bfloat16* Kl = g_kl + hb * SEQ * HEADD;
    const __nv_bfloat16* Vh = g_vth + hb * HEADD * SEQ;
    const __nv_bfloat16* Vl = g_vtl + hb * HEADD * SEQ;

    for (int i = tid; i < 512; i += 128) {
        int r = i >> 3, ch = i & 7;
        *(uint4*)((char*)pQh + r * FROW + ch * 16) =
            *(const uint4*)(Qh + (size_t)(qt * 64 + r) * HEADD + ch * 8);
        *(uint4*)((char*)pQh + FTILE + r * FROW + ch * 16) =
            *(const uint4*)(Ql + (size_t)(qt * 64 + r) * HEADD + ch * 8);
    }
    __syncthreads();

    uint32_t qfh[4][4], qfl[4][4];
#pragma unroll
    for (int ks = 0; ks < 4; ks++) {
        uint32_t ao = (uint32_t)(w * 16 + (lane & 15)) * FROW + ks * 32 + (lane >> 4) * 16;
        LDSM4(qfh[ks], sQh + ao);
        LDSM4(qfl[ks], sQl + ao);
    }

    float accO[8][4];
#pragma unroll
    for (int i = 0; i < 8; i++)
#pragma unroll
        for (int j = 0; j < 4; j++) accO[i][j] = 0.f;
    float mrow0 = -INFINITY, mrow1 = -INFINITY, lrow0 = 0.f, lrow1 = 0.f;
    const float SC = 0.125f * 1.44269504f;

    for (int kt = 0; kt <= qt; kt++) {
        __syncthreads();
        for (int i = tid; i < 512; i += 128) {
            int r = i >> 3, ch = i & 7;
            *(uint4*)((char*)pQh + 2*FTILE + r * FROW + ch * 16) =
                *(const uint4*)(Kh + (size_t)(kt * 64 + r) * HEADD + ch * 8);
            *(uint4*)((char*)pQh + 3*FTILE + r * FROW + ch * 16) =
                *(const uint4*)(Kl + (size_t)(kt * 64 + r) * HEADD + ch * 8);
            *(uint4*)((char*)pQh + 4*FTILE + r * FROW + ch * 16) =
                *(const uint4*)(Vh + (size_t)r * SEQ + kt * 64 + ch * 8);
            *(uint4*)((char*)pQh + 5*FTILE + r * FROW + ch * 16) =
                *(const uint4*)(Vl + (size_t)r * SEQ + kt * 64 + ch * 8);
        }
        __syncthreads();

        float sacc[8][4];
#pragma unroll
        for (int nt = 0; nt < 8; nt++)
#pragma unroll
            for (int j = 0; j < 4; j++) sacc[nt][j] = 0.f;
#pragma unroll
        for (int ks = 0; ks < 4; ks++) {
#pragma unroll
            for (int nt = 0; nt < 8; nt++) {
                uint32_t kh2[2], kl2[2];
                uint32_t bo = (uint32_t)(nt * 8 + (lane & 7)) * FROW + ks * 32 + ((lane >> 3) & 1) * 16;
                LDSM2(kh2, sKh + bo);
                LDSM2(kl2, sKl + bo);
                MMA_BF16(sacc[nt], qfh[ks], kh2);
                MMA_BF16(sacc[nt], qfh[ks], kl2);
                MMA_BF16(sacc[nt], qfl[ks], kh2);
            }
        }

        int grow = qt * 64 + w * 16 + (lane >> 2);
        if (kt == qt) {
#pragma unroll
            for (int nt = 0; nt < 8; nt++) {
                int cbase = kt * 64 + nt * 8 + (lane & 3) * 2;
                sacc[nt][0] = (cbase     <= grow    ) ? sacc[nt][0] * SC : -1e30f;
                sacc[nt][1] = (cbase + 1 <= grow    ) ? sacc[nt][1] * SC : -1e30f;
                sacc[nt][2] = (cbase     <= grow + 8) ? sacc[nt][2] * SC : -1e30f;
                sacc[nt][3] = (cbase + 1 <= grow + 8) ? sacc[nt][3] * SC : -1e30f;
            }
        } else {
#pragma unroll
            for (int nt = 0; nt < 8; nt++)
#pragma unroll
                for (int j = 0; j < 4; j++) sacc[nt][j] *= SC;
        }

        float mx0 = -INFINITY, mx1 = -INFINITY;
#pragma unroll
        for (int nt = 0; nt < 8; nt++) {
            mx0 = fmaxf(mx0, fmaxf(sacc[nt][0], sacc[nt][1]));
            mx1 = fmaxf(mx1, fmaxf(sacc[nt][2], sacc[nt][3]));
        }
        mx0 = fmaxf(mx0, __shfl_xor_sync(0xffffffffu, mx0, 1));
        mx0 = fmaxf(mx0, __shfl_xor_sync(0xffffffffu, mx0, 2));
        mx1 = fmaxf(mx1, __shfl_xor_sync(0xffffffffu, mx1, 1));
        mx1 = fmaxf(mx1, __shfl_xor_sync(0xffffffffu, mx1, 2));
        float mn0 = fmaxf(mrow0, mx0), mn1 = fmaxf(mrow1, mx1);
        float al0 = exp2f(mrow0 - mn0), al1 = exp2f(mrow1 - mn1);
        mrow0 = mn0; mrow1 = mn1;
#pragma unroll
        for (int nt = 0; nt < 8; nt++) {
            accO[nt][0] *= al0; accO[nt][1] *= al0;
            accO[nt][2] *= al1; accO[nt][3] *= al1;
        }
        lrow0 *= al0; lrow1 *= al1;

        float sum0 = 0.f, sum1 = 0.f;
#pragma unroll
        for (int ks = 0; ks < 4; ks++) {
            float p[2][4];
#pragma unroll
            for (int h2 = 0; h2 < 2; h2++) {
                int nt = ks * 2 + h2;
                p[h2][0] = exp2f(sacc[nt][0] - mn0);
                p[h2][1] = exp2f(sacc[nt][1] - mn0);
                p[h2][2] = exp2f(sacc[nt][2] - mn1);
                p[h2][3] = exp2f(sacc[nt][3] - mn1);
                sum0 += p[h2][0] + p[h2][1];
                sum1 += p[h2][2] + p[h2][3];
            }
            uint32_t pfh[4], pfl[4];
            packsplit(p[0][0], p[0][1], &pfh[0], &pfl[0]);
            packsplit(p[0][2], p[0][3], &pfh[1], &pfl[1]);
            packsplit(p[1][0], p[1][1], &pfh[2], &pfl[2]);
            packsplit(p[1][2], p[1][3], &pfh[3], &pfl[3]);
#pragma unroll
            for (int ntd = 0; ntd < 8; ntd++) {
                uint32_t vh2[2], vl2[2];
                uint32_t vo = (uint32_t)(ntd * 8 + (lane & 7)) * FROW + ks * 32 + ((lane >> 3) & 1) * 16;
                LDSM2(vh2, sVh + vo);
                LDSM2(vl2, sVl + vo);
                MMA_BF16(accO[ntd], pfh, vh2);
                MMA_BF16(accO[ntd], pfh, vl2);
                MMA_BF16(accO[ntd], pfl, vh2);
            }
        }
        sum0 += __shfl_xor_sync(0xffffffffu, sum0, 1);
        sum0 += __shfl_xor_sync(0xffffffffu, sum0, 2);
        sum1 += __shfl_xor_sync(0xffffffffu, sum1, 1);
        sum1 += __shfl_xor_sync(0xffffffffu, sum1, 2);
        lrow0 += sum0; lrow1 += sum1;
    }

    float inv0 = 1.f / lrow0, inv1 = 1.f / lrow1;
    int row0 = qt * 64 + w * 16 + (lane >> 2);
    size_t rb = ((size_t)bb * SEQ + row0) * HDIM + hh * HEADD + (lane & 3) * 2;
#pragma unroll
    for (int ntd = 0; ntd < 8; ntd++) {
        uint32_t h, l;
        packsplit(accO[ntd][0] * inv0, accO[ntd][1] * inv0, &h, &l);
        *(uint32_t*)(g_oh + rb + ntd * 8) = h;
        *(uint32_t*)(g_ol + rb + ntd * 8) = l;
        packsplit(accO[ntd][2] * inv1, accO[ntd][3] * inv1, &h, &l);
        *(uint32_t*)(g_oh + rb + 8 * HDIM + ntd * 8) = h;
        *(uint32_t*)(g_ol + rb + 8 * HDIM + ntd * 8) = l;
    }
}

// ================= MoE gating =================
__global__ void gate_kernel(const float* __restrict__ gw) {
    int t = blockIdx.x * 8 + (threadIdx.x >> 5);
    int lane = threadIdx.x & 31;
    const float* xr = g_x1n + (size_t)t * HDIM;
    float acc[8] = {0, 0, 0, 0, 0, 0, 0, 0};
    for (int j = lane; j < HDIM; j += 32) {
        float xv = xr[j];
        const float* gr = gw + j * 8;
        float4 g0 = *(const float4*)gr, g1 = *(const float4*)(gr + 4);
        acc[0] += xv * g0.x; acc[1] += xv * g0.y; acc[2] += xv * g0.z; acc[3] += xv * g0.w;
        acc[4] += xv * g1.x; acc[5] += xv * g1.y; acc[6] += xv * g1.z; acc[7] += xv * g1.w;
    }
#pragma unroll
    for (int e = 0; e < 8; e++)
        for (int o = 16; o; o >>= 1) acc[e] += __shfl_xor_sync(0xffffffffu, acc[e], o);
    if (lane == 0) {
        float mx = acc[0];
#pragma unroll
        for (int e = 1; e < 8; e++) mx = fmaxf(mx, acc[e]);
        float se = 0.f;
#pragma unroll
        for (int e = 0; e < 8; e++) se += expf(acc[e] - mx);
        float lse = mx + logf(se);
        g_lse2[t] = lse * lse;
        int i0 = 0; float v0 = acc[0];
#pragma unroll
        for (int e = 1; e < 8; e++) if (acc[e] > v0) { v0 = acc[e]; i0 = e; }
        int i1 = -1; float v1 = -INFINITY;
#pragma unroll
        for (int e = 0; e < 8; e++) if (e != i0 && acc[e] > v1) { v1 = acc[e]; i1 = e; }
        float w0 = 1.f / (1.f + expf(v1 - v0));
        float w1 = 1.f - w0;
        int p0 = atomicAdd(&g_cnt[i0], 1);
        g_rows[i0 * T_TOK + p0] = t;
        int p1 = atomicAdd(&g_cnt[i1], 1);
        g_rows[i1 * T_TOK + p1] = t;
        g_ie[2*t] = i0; g_islot[2*t] = p0; g_iw[2*t] = w0;
        g_ie[2*t+1] = i1; g_islot[2*t+1] = p1; g_iw[2*t+1] = w1;
    }
}

__global__ void aux_kernel(float* __restrict__ out) {
    __shared__ float red[32];
    float s = 0.f;
    for (int i = threadIdx.x; i < T_TOK; i += 1024) s += g_lse2[i];
    for (int o = 16; o; o >>= 1) s += __shfl_xor_sync(0xffffffffu, s, o);
    if ((threadIdx.x & 31) == 0) red[threadIdx.x >> 5] = s;
    __syncthreads();
    if (threadIdx.x < 32) {
        float v = red[threadIdx.x];
        for (int o = 16; o; o >>= 1) v += __shfl_xor_sync(0xffffffffu, v, o);
        if (threadIdx.x == 0) out[(size_t)T_TOK * HDIM] = 0.001f * v / (float)T_TOK;
    }
}

__global__ void gather_kernel() {
    int e = blockIdx.y, r = blockIdx.x;
    if (r >= g_cnt[e]) return;
    int t = g_rows[e * T_TOK + r];
    float4 v = ((const float4*)(g_x1n + (size_t)t * HDIM))[threadIdx.x];
    size_t o = ((size_t)e * T_TOK + r) * HDIM + threadIdx.x * 4;
    split1(v.x, &g_xgh[o + 0], &g_xgl[o + 0]);
    split1(v.y, &g_xgh[o + 1], &g_xgl[o + 1]);
    split1(v.z, &g_xgh[o + 2], &g_xgl[o + 2]);
    split1(v.w, &g_xgh[o + 3], &g_xgl[o + 3]);
}

__global__ void combine_kernel(float* __restrict__ out) {
    int t = blockIdx.x;
    int i0 = g_ie[2*t], i1 = g_ie[2*t+1];
    int p0 = g_islot[2*t], p1 = g_islot[2*t+1];
    float w0 = g_iw[2*t], w1 = g_iw[2*t+1];
    const float4* d0 = (const float4*)(g_dg + ((size_t)i0 * T_TOK + p0) * HDIM);
    const float4* d1 = (const float4*)(g_dg + ((size_t)i1 * T_TOK + p1) * HDIM);
    const float4* xr = (const float4*)(g_x1 + (size_t)t * HDIM);
    float4* o = (float4*)(out + (size_t)t * HDIM);
    int c = threadIdx.x;
    float4 a = xr[c], b0 = d0[c], b1 = d1[c];
    a.x += w0 * b0.x + w1 * b1.x;
    a.y += w0 * b0.y + w1 * b1.y;
    a.z += w0 * b0.z + w1 * b1.z;
    a.w += w0 * b0.w + w1 * b1.w;
    o[c] = a;
}

// ================= launch =================
#define GSA(var, sym) do { void* _p; cudaGetSymbolAddress(&_p, sym); var = (decltype(var))_p; } while (0)

extern "C" void kernel_launch(void* const* d_in, const int* in_sizes, int n_in,
                              void* d_out, int out_size) {
    const float* hidden = (const float*)d_in[0];
    const float* wq    = (const float*)d_in[2];
    const float* wk    = (const float*)d_in[3];
    const float* wv    = (const float*)d_in[4];
    const float* wo    = (const float*)d_in[5];
    const float* ln1   = (const float*)d_in[6];
    const float* ln2   = (const float*)d_in[7];
    const float* gw    = (const float*)d_in[8];
    const float* wgate = (const float*)d_in[9];
    const float* wup   = (const float*)d_in[10];
    const float* wdown = (const float*)d_in[11];
    float* out = (float*)d_out;

    float *qkv, *x1, *x1n, *dg;
    int* cnt;
    __nv_bfloat16 *ah, *al, *oh, *ol, *xgh, *xgl, *hgh, *hgl;
    __nv_bfloat16 *wqkvh, *wqkvl, *woh, *wol, *wguh, *wgul, *wdnh, *wdnl;
    GSA(qkv, g_qkv); GSA(x1, g_x1); GSA(x1n, g_x1n);
    GSA(dg, g_dg); GSA(cnt, g_cnt);
    GSA(ah, g_ah); GSA(al, g_al); GSA(oh, g_oh); GSA(ol, g_ol);
    GSA(xgh, g_xgh); GSA(xgl, g_xgl); GSA(hgh, g_hgh); GSA(hgl, g_hgl);
    GSA(wqkvh, g_wqkvh); GSA(wqkvl, g_wqkvl); GSA(woh, g_woh); GSA(wol, g_wol);
    GSA(wguh, g_wguh); GSA(wgul, g_wgul); GSA(wdnh, g_wdnh); GSA(wdnl, g_wdnl);

    cudaFuncSetAttribute((const void*)tmma_kernel,
                         cudaFuncAttributeMaxDynamicSharedMemorySize, TMMA_SMEM);
    cudaFuncSetAttribute((const void*)flashmma_kernel,
                         cudaFuncAttributeMaxDynamicSharedMemorySize, FLASH_SMEM);

    // weight conversion (fast path)
    wconv_kernel<<<dim3(12, 12, 1), 256>>>(wq, wqkvh, wqkvl, HDIM, HDIM, 0, 0, 0, 0);
    wconv_kernel<<<dim3(12, 12, 1), 256>>>(wk, wqkvh, wqkvl, HDIM, HDIM, 0, 0, 0, 768);
    wconv_kernel<<<dim3(12, 12, 1), 256>>>(wv, wqkvh, wqkvl, HDIM, HDIM, 0, 0, 0, 1536);
    wconv_kernel<<<dim3(12, 12, 1), 256>>>(wo, woh, wol, HDIM, HDIM, 0, 0, 0, 0);
    wconv_kernel<<<dim3(32, 12, NEXP), 256>>>(wgate, wguh, wgul, HDIM, IDIM,
                                              (size_t)HDIM*IDIM, (size_t)2*IDIM*HDIM, 1, 0);
    wconv_kernel<<<dim3(32, 12, NEXP), 256>>>(wup, wguh, wgul, HDIM, IDIM,
                                              (size_t)HDIM*IDIM, (size_t)2*IDIM*HDIM, 2, 0);
    wconv_kernel<<<dim3(12, 32, NEXP), 256>>>(wdown, wdnh, wdnl, IDIM, HDIM,
                                              (size_t)IDIM*HDIM, (size_t)HDIM*IDIM, 0, 0);

    // 1. RMSNorm -> bf16 hi/lo
    rmsnorm_bf16_kernel<<<T_TOK, 256>>>(hidden, ln1, ah, al);

    // 2. fused QKV projection
    tmma_kernel<<<dim3(18, 32, 1), 256, TMMA_SMEM>>>(ah, al, wqkvh, wqkvl, qkv,
        T_TOK, nullptr, 2304, HDIM, nullptr, 0, 0, 0, nullptr, nullptr, 0);

    // 3. RoPE
    rope_table_kernel<<<(SEQ * 32 + 255) / 256, 256>>>();
    rope_kernel<<<dim3(SEQ, NHEADS, BATCH), 64>>>();

    // 4. tensor-core causal flash attention
    flashmma_kernel<<<dim3(32, NHEADS, BATCH), 128, FLASH_SMEM>>>();

    // 5. output projection + residual
    tmma_kernel<<<dim3(6, 32, 1), 256, TMMA_SMEM>>>(oh, ol, woh, wol, x1,
        T_TOK, nullptr, HDIM, HDIM, hidden, 0, 0, 0, nullptr, nullptr, 0);

    // 6. post-attention RMSNorm (+ cnt zeroing)
    rmsnorm_f32_kernel<<<T_TOK, 256>>>(x1, ln2, x1n);

    // 7. gating + aux
    gate_kernel<<<T_TOK / 8, 256>>>(gw);
    aux_kernel<<<1, 1024>>>(out);

    // 8. batched MoE with fused silu
    gather_kernel<<<dim3(T_TOK, NEXP), 192>>>();
    tmma_kernel<<<dim3(32, 32, NEXP), 256, TMMA_SMEM>>>(xgh, xgl, wguh, wgul, nullptr,
        0, cnt, 2 * IDIM, HDIM, nullptr,
        (size_t)T_TOK * HDIM, (size_t)2 * IDIM * HDIM, (size_t)T_TOK * IDIM, hgh, hgl, 1);
    tmma_kernel<<<dim3(6, 32, NEXP), 256, TMMA_SMEM>>>(hgh, hgl, wdnh, wdnl, dg,
        0, cnt, HDIM, IDIM, nullptr,
        (size_t)T_TOK * IDIM, (size_t)HDIM * IDIM, (size_t)T_TOK * HDIM, nullptr, nullptr, 0);

    // 9. deterministic combine
    combine_kernel<<<T_TOK, 192>>>(out);
}

// round 6
// speedup vs baseline: 7.7673x; 2.2705x over previous
#include <cuda_runtime.h>
#include <cuda_fp16.h>
#include <math.h>
#include <stdint.h>

// ---- problem constants ----
#define T_TOK 4096      // B*S
#define SEQ   2048
#define BATCH 2
#define HDIM  768
#define NHEADS 12
#define HEADD 64
#define IDIM  2048
#define NEXP  8

// ---- fp32 scratch ----
__device__ __align__(128) float g_qkv [T_TOK*2304];
__device__ __align__(128) float g_x1  [T_TOK*HDIM];
__device__ __align__(128) float g_x1n [T_TOK*HDIM];
__device__ __align__(128) float g_dg  [(size_t)NEXP*T_TOK*HDIM];
__device__ float g_cos [SEQ*32];
__device__ float g_sin [SEQ*32];
__device__ float g_lse2[T_TOK];
__device__ int   g_cnt [NEXP];
__device__ int   g_rows[NEXP*T_TOK];
__device__ int   g_ie  [2*T_TOK];
__device__ int   g_islot[2*T_TOK];
__device__ float g_iw  [2*T_TOK];

// ---- fp16 activations (hi/lo split) ----
__device__ __align__(128) __half g_ah [T_TOK*HDIM];
__device__ __align__(128) __half g_al [T_TOK*HDIM];
__device__ __align__(128) __half g_qh [T_TOK*HDIM];   // [b,h,s,d] hi
__device__ __align__(128) __half g_ql [T_TOK*HDIM];   // lo
__device__ __align__(128) __half g_kh [T_TOK*HDIM];   // K hi only (B operand)
__device__ __align__(128) __half g_vth[T_TOK*HDIM];   // V^T hi only [b,h,d,s]
__device__ __align__(128) __half g_oh [T_TOK*HDIM];
__device__ __align__(128) __half g_ol [T_TOK*HDIM];
__device__ __align__(128) __half g_xgh[(size_t)NEXP*T_TOK*HDIM];
__device__ __align__(128) __half g_xgl[(size_t)NEXP*T_TOK*HDIM];
__device__ __align__(128) __half g_hgh[(size_t)NEXP*T_TOK*IDIM];
__device__ __align__(128) __half g_hgl[(size_t)NEXP*T_TOK*IDIM];

// ---- fp16 weights hi only ([N,K] K-major; gate/up interleaved 64-row groups) ----
__device__ __align__(128) __half g_wqkv[2304*HDIM];
__device__ __align__(128) __half g_wo  [HDIM*HDIM];
__device__ __align__(128) __half g_wgu [(size_t)NEXP*2*IDIM*HDIM];
__device__ __align__(128) __half g_wdn [(size_t)NEXP*HDIM*IDIM];

// ================= helpers =================
__device__ __forceinline__ uint32_t s2u(const void* p) {
    uint32_t a;
    asm("{ .reg .u64 t; cvta.to.shared.u64 t, %1; cvt.u32.u64 %0, t; }" : "=r"(a) : "l"(p));
    return a;
}
__device__ __forceinline__ void split1(float v, __half* hp, __half* lp) {
    __half h = __float2half_rn(v);
    *hp = h;
    *lp = __float2half_rn(v - __half2float(h));
}
__device__ __forceinline__ void packsplit(float a, float b, uint32_t* hi, uint32_t* lo) {
    __half ah = __float2half_rn(a), bh = __float2half_rn(b);
    __half al = __float2half_rn(a - __half2float(ah));
    __half bl = __float2half_rn(b - __half2float(bh));
    __half2 h2 = __halves2half2(ah, bh);
    __half2 l2 = __halves2half2(al, bl);
    *hi = *(uint32_t*)&h2; *lo = *(uint32_t*)&l2;
}

#define LDSM4(r, a) \
    asm volatile("ldmatrix.sync.aligned.m8n8.x4.shared.b16 {%0,%1,%2,%3}, [%4];" \
        : "=r"((r)[0]), "=r"((r)[1]), "=r"((r)[2]), "=r"((r)[3]) : "r"(a))
#define LDSM2(r, a) \
    asm volatile("ldmatrix.sync.aligned.m8n8.x2.shared.b16 {%0,%1}, [%2];" \
        : "=r"((r)[0]), "=r"((r)[1]) : "r"(a))
#define MMA_F16(c, a, b) \
    asm volatile("mma.sync.aligned.m16n8k16.row.col.f32.f16.f16.f32 " \
        "{%0,%1,%2,%3}, {%4,%5,%6,%7}, {%8,%9}, {%0,%1,%2,%3};" \
        : "+f"((c)[0]), "+f"((c)[1]), "+f"((c)[2]), "+f"((c)[3]) \
        : "r"((a)[0]), "r"((a)[1]), "r"((a)[2]), "r"((a)[3]), "r"((b)[0]), "r"((b)[1]))
#define CP_ASYNC16(dst, src) \
    asm volatile("cp.async.cg.shared.global [%0], [%1], 16;" :: "r"(dst), "l"(src))

// ================= weight transpose + fp16 round =================
// fp32 W[K,N] -> fp16 [N,K]; mode 0 identity, 1 gate-interleave, 2 up-interleave.
__global__ __launch_bounds__(256) void wconv_kernel(
    const float* __restrict__ W, __half* __restrict__ oh, int K, int N,
    size_t inZ, size_t outZ, int mode, int dstOff)
{
    W  += (size_t)blockIdx.z * inZ;
    oh += (size_t)blockIdx.z * outZ;
    __shared__ float s[64][65];
    int n0 = blockIdx.x * 64, k0 = blockIdx.y * 64;
    int tid = threadIdx.x;
    int lr = tid >> 4;
    int lc = (tid & 15) * 4;
#pragma unroll
    for (int p = 0; p < 4; p++) {
        int kk = p * 16 + lr;
        float4 v = *(const float4*)(W + (size_t)(k0 + kk) * N + n0 + lc);
        s[lc + 0][kk] = v.x; s[lc + 1][kk] = v.y;
        s[lc + 2][kk] = v.z; s[lc + 3][kk] = v.w;
    }
    __syncthreads();
    int nl = tid >> 3;
    int kq = (tid & 7) * 8;
#pragma unroll
    for (int p = 0; p < 2; p++) {
        int nn = p * 32 + nl;
        int ng = n0 + nn;
        int nd = (mode == 0) ? ng : ((ng >> 6) * 128 + (ng & 63) + ((mode == 2) ? 64 : 0));
        nd += dstOff;
        __half hb[8];
#pragma unroll
        for (int j = 0; j < 8; j++) hb[j] = __float2half_rn(s[nn][kq + j]);
        *(uint4*)(oh + (size_t)nd * K + k0 + kq) = *(uint4*)hb;
    }
}

// ================= mma.sync fp16 2-term GEMM (batched; optional fused silu) ===========
// C[M,N](fp32) = (Ah+Al)@B^T.  Ah/Al: [M,K] fp16 K-major; B: [N,K] fp16 K-major.
// Tile 128x128, K-chunk 32, cp.async double-buffer (3 tiles/stage), 8 warps.
#define TMMA_SMEM 67584

__global__ __launch_bounds__(256) void tmma_kernel(
    const __half* __restrict__ Ah, const __half* __restrict__ Al,
    const __half* __restrict__ B,
    float* __restrict__ C, int M, const int* __restrict__ cntArr,
    int N, int K, const float* __restrict__ Cadd,
    size_t zsA, size_t zsB, size_t zsC,
    __half* __restrict__ SOh, __half* __restrict__ SOl, int fuseSilu)
{
    int z = blockIdx.z;
    int m = cntArr ? cntArr[z] : M;
    int row0 = blockIdx.y * 128;
    if (row0 >= m) return;
    int col0 = blockIdx.x * 128;
    Ah += zsA * z; Al += zsA * z; B += zsB * z;
    if (fuseSilu) { SOh += zsC * z; SOl += zsC * z; } else { C += zsC * z; }

    extern __shared__ char sm[];
    uint32_t sbase = s2u(sm);
    int tid = threadIdx.x, lane = tid & 31, wid = tid >> 5;
    int wm = wid & 1, wn = wid >> 1;

    const __half* sp[3];
    sp[0] = Ah + (size_t)row0 * K;
    sp[1] = Al + (size_t)row0 * K;
    sp[2] = B  + (size_t)col0 * K;

    float acc[4][4][4];
#pragma unroll
    for (int a = 0; a < 4; a++)
#pragma unroll
        for (int b = 0; b < 4; b++)
#pragma unroll
            for (int c = 0; c < 4; c++) acc[a][b][c] = 0.f;

    int NC = K >> 5;

#define LOAD_STAGE(cc, ss) do { \
    uint32_t _db = sbase + (ss) * 30720; \
    _Pragma("unroll") \
    for (int _t = 0; _t < 3; _t++) { \
        _Pragma("unroll") \
        for (int _i = 0; _i < 2; _i++) { \
            int _idx = tid + _i * 256; \
            int _r = _idx >> 2, _ch = _idx & 3; \
            uint32_t _dst = _db + _t * 10240 + _r * 80 + _ch * 16; \
            const void* _src = sp[_t] + (size_t)_r * K + (cc) * 32 + _ch * 8; \
            CP_ASYNC16(_dst, _src); \
        } \
    } \
    asm volatile("cp.async.commit_group;"); \
} while (0)

    LOAD_STAGE(0, 0);

    for (int c = 0; c < NC; c++) {
        if (c + 1 < NC) {
            LOAD_STAGE(c + 1, (c + 1) & 1);
            asm volatile("cp.async.wait_group 1;");
        } else {
            asm volatile("cp.async.wait_group 0;");
        }
        __syncthreads();

        uint32_t db = sbase + (c & 1) * 30720;
        uint32_t aH = db, aL = db + 10240, bT = db + 20480;
#pragma unroll
        for (int ks = 0; ks < 2; ks++) {
            uint32_t ah[4][4], al[4][4], bf[4][2];
            uint32_t aoff = (uint32_t)(wm * 64 + (lane & 15)) * 80 + ks * 32 + (lane >> 4) * 16;
            uint32_t boff = (uint32_t)(wn * 32 + (lane & 7)) * 80 + ks * 32 + ((lane >> 3) & 1) * 16;
#pragma unroll
            for (int mt = 0; mt < 4; mt++) {
                LDSM4(ah[mt], aH + aoff + mt * 1280);
                LDSM4(al[mt], aL + aoff + mt * 1280);
            }
#pragma unroll
            for (int nt = 0; nt < 4; nt++)
                LDSM2(bf[nt], bT + boff + nt * 640);
#pragma unroll
            for (int mt = 0; mt < 4; mt++)
#pragma unroll
                for (int nt = 0; nt < 4; nt++) {
                    MMA_F16(acc[mt][nt], ah[mt], bf[nt]);
                    MMA_F16(acc[mt][nt], al[mt], bf[nt]);
                }
        }
        __syncthreads();
    }

    if (fuseSilu) {
        float* st = (float*)sm;   // 128 x 132 floats
#pragma unroll
        for (int mt = 0; mt < 4; mt++) {
            int r = wm * 64 + mt * 16 + (lane >> 2);
            int cbase = wn * 32 + (lane & 3) * 2;
#pragma unroll
            for (int half = 0; half < 2; half++) {
#pragma unroll
                for (int nt = 0; nt < 4; nt++) {
                    float2 v; v.x = acc[mt][nt][half * 2 + 0]; v.y = acc[mt][nt][half * 2 + 1];
                    *(float2*)&st[(r + half * 8) * 132 + cbase + nt * 8] = v;
                }
            }
        }
        __syncthreads();
        int lr = tid >> 4;
        int lc = (tid & 15) * 4;
        int colg = blockIdx.x * 64 + lc;
#pragma unroll
        for (int p = 0; p < 8; p++) {
            int r = p * 16 + lr;
            int gr = row0 + r;
            if (gr < m) {
                float4 gv = *(float4*)&st[r * 132 + lc];
                float4 uv = *(float4*)&st[r * 132 + 64 + lc];
                float f0 = gv.x / (1.f + expf(-gv.x)) * uv.x;
                float f1 = gv.y / (1.f + expf(-gv.y)) * uv.y;
                float f2 = gv.z / (1.f + expf(-gv.z)) * uv.z;
                float f3 = gv.w / (1.f + expf(-gv.w)) * uv.w;
                uint32_t h0, l0, h1, l1;
                packsplit(f0, f1, &h0, &l0);
                packsplit(f2, f3, &h1, &l1);
                size_t o = (size_t)gr * IDIM + colg;
                uint2 hv; hv.x = h0; hv.y = h1;
                uint2 lv; lv.x = l0; lv.y = l1;
                *(uint2*)(SOh + o) = hv;
                *(uint2*)(SOl + o) = lv;
            }
        }
        return;
    }

#pragma unroll
    for (int mt = 0; mt < 4; mt++) {
        int rbase = row0 + wm * 64 + mt * 16 + (lane >> 2);
#pragma unroll
        for (int half = 0; half < 2; half++) {
            int rr = rbase + half * 8;
            if (rr < m) {
                size_t o = (size_t)rr * N + col0 + wn * 32 + (lane & 3) * 2;
#pragma unroll
                for (int nt = 0; nt < 4; nt++) {
                    float v0 = acc[mt][nt][half * 2 + 0];
                    float v1 = acc[mt][nt][half * 2 + 1];
                    size_t oo = o + nt * 8;
                    if (Cadd) {
                        float2 ad = *(const float2*)(Cadd + oo);
                        v0 += ad.x; v1 += ad.y;
                    }
                    float2 st2; st2.x = v0; st2.y = v1;
                    *(float2*)(C + oo) = st2;
                }
            }
        }
    }
}

// ================= RMSNorm =================
__device__ __forceinline__ float block_rms(const float* xr, int tid) {
    float s = 0.f;
    for (int c = tid; c < HDIM; c += 256) { float v = xr[c]; s += v * v; }
    __shared__ float red[8];
    for (int o = 16; o; o >>= 1) s += __shfl_xor_sync(0xffffffffu, s, o);
    if ((tid & 31) == 0) red[tid >> 5] = s;
    __syncthreads();
    if (tid < 8) {
        float v = red[tid];
        for (int o = 4; o; o >>= 1) v += __shfl_xor_sync(0xffu, v, o);
        if (tid == 0) red[0] = v;
    }
    __syncthreads();
    return rsqrtf(red[0] / (float)HDIM + 1e-6f);
}

__global__ void rmsnorm_f16_kernel(const float* __restrict__ x, const float* __restrict__ w,
                                   __half* __restrict__ oh, __half* __restrict__ ol) {
    int row = blockIdx.x;
    const float* xr = x + (size_t)row * HDIM;
    float scale = block_rms(xr, threadIdx.x);
    for (int c = threadIdx.x; c < HDIM; c += 256) {
        float v = w[c] * xr[c] * scale;
        split1(v, &oh[(size_t)row * HDIM + c], &ol[(size_t)row * HDIM + c]);
    }
}

__global__ void rmsnorm_f32_kernel(const float* __restrict__ x, const float* __restrict__ w,
                                   float* __restrict__ out) {
    int row = blockIdx.x;
    if (row == 0 && threadIdx.x < NEXP) g_cnt[threadIdx.x] = 0;
    const float* xr = x + (size_t)row * HDIM;
    float scale = block_rms(xr, threadIdx.x);
    for (int c = threadIdx.x; c < HDIM; c += 256)
        out[(size_t)row * HDIM + c] = w[c] * xr[c] * scale;
}

// ================= RoPE =================
__global__ void rope_table_kernel() {
    int idx = blockIdx.x * blockDim.x + threadIdx.x;
    if (idx >= SEQ * 32) return;
    int i = idx & 31, s = idx >> 5;
    float inv = powf(10000.0f, -(float)i / 32.0f);
    float ang = (float)s * inv;
    g_cos[idx] = cosf(ang);
    g_sin[idx] = sinf(ang);
}

__global__ void rope_kernel() {
    int s = blockIdx.x, hh = blockIdx.y, bb = blockIdx.z, d = threadIdx.x;
    int t = bb * SEQ + s;
    const float* qkv = g_qkv + (size_t)t * 2304;
    int col  = hh * HEADD + d;
    int pcol = hh * HEADD + (d < 32 ? d + 32 : d - 32);
    float qv = qkv[col], kv = qkv[768 + col], vv = qkv[1536 + col];
    float qp = qkv[pcol], kp = qkv[768 + pcol];
    float cs = g_cos[s * 32 + (d & 31)], sn = g_sin[s * 32 + (d & 31)];
    float sgn = (d < 32) ? -1.f : 1.f;
    float qr = qv * cs + sgn * qp * sn;
    float kr = kv * cs + sgn * kp * sn;
    size_t dst = (((size_t)bb * NHEADS + hh) * SEQ + s) * HEADD + d;
    split1(qr, &g_qh[dst], &g_ql[dst]);
    g_kh[dst] = __float2half_rn(kr);
    size_t vdst = (((size_t)bb * NHEADS + hh) * HEADD + d) * SEQ + s;
    g_vth[vdst] = __float2half_rn(vv);
}

// ================= tensor-core flash attention (fp16, 2-term) =================
#define FROW 144
#define FTILE 9216
#define FLASH_SMEM (4*FTILE)

__global__ __launch_bounds__(128) void flashmma_kernel() {
    int qt = 31 - (int)blockIdx.x;
    int hh = blockIdx.y, bb = blockIdx.z;
    extern __shared__ char fsm[];
    uint32_t sb = s2u(fsm);
    uint32_t sQh = sb, sQl = sb + FTILE, sK = sb + 2*FTILE, sV = sb + 3*FTILE;
    char* pS = fsm;

    int tid = threadIdx.x, lane = tid & 31, w = tid >> 5;
    size_t hb = (size_t)bb * NHEADS + hh;
    const __half* Qh = g_qh + hb * SEQ * HEADD;
    const __half* Ql = g_ql + hb * SEQ * HEADD;
    const __half* Kh = g_kh + hb * SEQ * HEADD;
    const __half* Vh = g_vth + hb * HEADD * SEQ;

    for (int i = tid; i < 512; i += 128) {
        int r = i >> 3, ch = i & 7;
        *(uint4*)(pS + r * FROW + ch * 16) =
            *(const uint4*)(Qh + (size_t)(qt * 64 + r) * HEADD + ch * 8);
        *(uint4*)(pS + FTILE + r * FROW + ch * 16) =
            *(const uint4*)(Ql + (size_t)(qt * 64 + r) * HEADD + ch * 8);
    }
    __syncthreads();

    uint32_t qfh[4][4], qfl[4][4];
#pragma unroll
    for (int ks = 0; ks < 4; ks++) {
        uint32_t ao = (uint32_t)(w * 16 + (lane & 15)) * FROW + ks * 32 + (lane >> 4) * 16;
        LDSM4(qfh[ks], sQh + ao);
        LDSM4(qfl[ks], sQl + ao);
    }

    float accO[8][4];
#pragma unroll
    for (int i = 0; i < 8; i++)
#pragma unroll
        for (int j = 0; j < 4; j++) accO[i][j] = 0.f;
    float mrow0 = -INFINITY, mrow1 = -INFINITY, lrow0 = 0.f, lrow1 = 0.f;
    const float SC = 0.125f * 1.44269504f;

    for (int kt = 0; kt <= qt; kt++) {
        __syncthreads();
        for (int i = tid; i < 512; i += 128) {
            int r = i >> 3, ch = i & 7;
            *(uint4*)(pS + 2*FTILE + r * FROW + ch * 16) =
                *(const uint4*)(Kh + (size_t)(kt * 64 + r) * HEADD + ch * 8);
            *(uint4*)(pS + 3*FTILE + r * FROW + ch * 16) =
                *(const uint4*)(Vh + (size_t)r * SEQ + kt * 64 + ch * 8);
        }
        __syncthreads();

        float sacc[8][4];
#pragma unroll
        for (int nt = 0; nt < 8; nt++)
#pragma unroll
            for (int j = 0; j < 4; j++) sacc[nt][j] = 0.f;
#pragma unroll
        for (int ks = 0; ks < 4; ks++) {
#pragma unroll
            for (int nt = 0; nt < 8; nt++) {
                uint32_t k2[2];
                uint32_t bo = (uint32_t)(nt * 8 + (lane & 7)) * FROW + ks * 32 + ((lane >> 3) & 1) * 16;
                LDSM2(k2, sK + bo);
                MMA_F16(sacc[nt], qfh[ks], k2);
                MMA_F16(sacc[nt], qfl[ks], k2);
            }
        }

        int grow = qt * 64 + w * 16 + (lane >> 2);
        if (kt == qt) {
#pragma unroll
            for (int nt = 0; nt < 8; nt++) {
                int cbase = kt * 64 + nt * 8 + (lane & 3) * 2;
                sacc[nt][0] = (cbase     <= grow    ) ? sacc[nt][0] * SC : -1e30f;
                sacc[nt][1] = (cbase + 1 <= grow    ) ? sacc[nt][1] * SC : -1e30f;
                sacc[nt][2] = (cbase     <= grow + 8) ? sacc[nt][2] * SC : -1e30f;
                sacc[nt][3] = (cbase + 1 <= grow + 8) ? sacc[nt][3] * SC : -1e30f;
            }
        } else {
#pragma unroll
            for (int nt = 0; nt < 8; nt++)
#pragma unroll
                for (int j = 0; j < 4; j++) sacc[nt][j] *= SC;
        }

        float mx0 = -INFINITY, mx1 = -INFINITY;
#pragma unroll
        for (int nt = 0; nt < 8; nt++) {
            mx0 = fmaxf(mx0, fmaxf(sacc[nt][0], sacc[nt][1]));
            mx1 = fmaxf(mx1, fmaxf(sacc[nt][2], sacc[nt][3]));
        }
        mx0 = fmaxf(mx0, __shfl_xor_sync(0xffffffffu, mx0, 1));
        mx0 = fmaxf(mx0, __shfl_xor_sync(0xffffffffu, mx0, 2));
        mx1 = fmaxf(mx1, __shfl_xor_sync(0xffffffffu, mx1, 1));
        mx1 = fmaxf(mx1, __shfl_xor_sync(0xffffffffu, mx1, 2));
        float mn0 = fmaxf(mrow0, mx0), mn1 = fmaxf(mrow1, mx1);
        float al0 = exp2f(mrow0 - mn0), al1 = exp2f(mrow1 - mn1);
        mrow0 = mn0; mrow1 = mn1;
#pragma unroll
        for (int nt = 0; nt < 8; nt++) {
            accO[nt][0] *= al0; accO[nt][1] *= al0;
            accO[nt][2] *= al1; accO[nt][3] *= al1;
        }
        lrow0 *= al0; lrow1 *= al1;

        float sum0 = 0.f, sum1 = 0.f;
#pragma unroll
        for (int ks = 0; ks < 4; ks++) {
            float p[2][4];
#pragma unroll
            for (int h2 = 0; h2 < 2; h2++) {
                int nt = ks * 2 + h2;
                p[h2][0] = exp2f(sacc[nt][0] - mn0);
                p[h2][1] = exp2f(sacc[nt][1] - mn0);
                p[h2][2] = exp2f(sacc[nt][2] - mn1);
                p[h2][3] = exp2f(sacc[nt][3] - mn1);
                sum0 += p[h2][0] + p[h2][1];
                sum1 += p[h2][2] + p[h2][3];
            }
            uint32_t pfh[4], pfl[4];
            packsplit(p[0][0], p[0][1], &pfh[0], &pfl[0]);
            packsplit(p[0][2], p[0][3], &pfh[1], &pfl[1]);
            packsplit(p[1][0], p[1][1], &pfh[2], &pfl[2]);
            packsplit(p[1][2], p[1][3], &pfh[3], &pfl[3]);
#pragma unroll
            for (int ntd = 0; ntd < 8; ntd++) {
                uint32_t v2[2];
                uint32_t vo = (uint32_t)(ntd * 8 + (lane & 7)) * FROW + ks * 32 + ((lane >> 3) & 1) * 16;
                LDSM2(v2, sV + vo);
                MMA_F16(accO[ntd], pfh, v2);
                MMA_F16(accO[ntd], pfl, v2);
            }
        }
        sum0 += __shfl_xor_sync(0xffffffffu, sum0, 1);
        sum0 += __shfl_xor_sync(0xffffffffu, sum0, 2);
        sum1 += __shfl_xor_sync(0xffffffffu, sum1, 1);
        sum1 += __shfl_xor_sync(0xffffffffu, sum1, 2);
        lrow0 += sum0; lrow1 += sum1;
    }

    float inv0 = 1.f / lrow0, inv1 = 1.f / lrow1;
    int row0 = qt * 64 + w * 16 + (lane >> 2);
    size_t rb = ((size_t)bb * SEQ + row0) * HDIM + hh * HEADD + (lane & 3) * 2;
#pragma unroll
    for (int ntd = 0; ntd < 8; ntd++) {
        uint32_t h, l;
        packsplit(accO[ntd][0] * inv0, accO[ntd][1] * inv0, &h, &l);
        *(uint32_t*)(g_oh + rb + ntd * 8) = h;
        *(uint32_t*)(g_ol + rb + ntd * 8) = l;
        packsplit(accO[ntd][2] * inv1, accO[ntd][3] * inv1, &h, &l);
        *(uint32_t*)(g_oh + rb + 8 * HDIM + ntd * 8) = h;
        *(uint32_t*)(g_ol + rb + 8 * HDIM + ntd * 8) = l;
    }
}

// ================= MoE gating =================
__global__ void gate_kernel(const float* __restrict__ gw) {
    int t = blockIdx.x * 8 + (threadIdx.x >> 5);
    int lane = threadIdx.x & 31;
    const float* xr = g_x1n + (size_t)t * HDIM;
    float acc[8] = {0, 0, 0, 0, 0, 0, 0, 0};
    for (int j = lane; j < HDIM; j += 32) {
        float xv = xr[j];
        const float* gr = gw + j * 8;
        float4 g0 = *(const float4*)gr, g1 = *(const float4*)(gr + 4);
        acc[0] += xv * g0.x; acc[1] += xv * g0.y; acc[2] += xv * g0.z; acc[3] += xv * g0.w;
        acc[4] += xv * g1.x; acc[5] += xv * g1.y; acc[6] += xv * g1.z; acc[7] += xv * g1.w;
    }
#pragma unroll
    for (int e = 0; e < 8; e++)
        for (int o = 16; o; o >>= 1) acc[e] += __shfl_xor_sync(0xffffffffu, acc[e], o);
    if (lane == 0) {
        float mx = acc[0];
#pragma unroll
        for (int e = 1; e < 8; e++) mx = fmaxf(mx, acc[e]);
        float se = 0.f;
#pragma unroll
        for (int e = 0; e < 8; e++) se += expf(acc[e] - mx);
        float lse = mx + logf(se);
        g_lse2[t] = lse * lse;
        int i0 = 0; float v0 = acc[0];
#pragma unroll
        for (int e = 1; e < 8; e++) if (acc[e] > v0) { v0 = acc[e]; i0 = e; }
        int i1 = -1; float v1 = -INFINITY;
#pragma unroll
        for (int e = 0; e < 8; e++) if (e != i0 && acc[e] > v1) { v1 = acc[e]; i1 = e; }
        float w0 = 1.f / (1.f + expf(v1 - v0));
        float w1 = 1.f - w0;
        int p0 = atomicAdd(&g_cnt[i0], 1);
        g_rows[i0 * T_TOK + p0] = t;
        int p1 = atomicAdd(&g_cnt[i1], 1);
        g_rows[i1 * T_TOK + p1] = t;
        g_ie[2*t] = i0; g_islot[2*t] = p0; g_iw[2*t] = w0;
        g_ie[2*t+1] = i1; g_islot[2*t+1] = p1; g_iw[2*t+1] = w1;
    }
}

__global__ void aux_kernel(float* __restrict__ out) {
    __shared__ float red[32];
    float s = 0.f;
    for (int i = threadIdx.x; i < T_TOK; i += 1024) s += g_lse2[i];
    for (int o = 16; o; o >>= 1) s += __shfl_xor_sync(0xffffffffu, s, o);
    if ((threadIdx.x & 31) == 0) red[threadIdx.x >> 5] = s;
    __syncthreads();
    if (threadIdx.x < 32) {
        float v = red[threadIdx.x];
        for (int o = 16; o; o >>= 1) v += __shfl_xor_sync(0xffffffffu, v, o);
        if (threadIdx.x == 0) out[(size_t)T_TOK * HDIM] = 0.001f * v / (float)T_TOK;
    }
}

__global__ void gather_kernel() {
    int e = blockIdx.y, r = blockIdx.x;
    if (r >= g_cnt[e]) return;
    int t = g_rows[e * T_TOK + r];
    float4 v = ((const float4*)(g_x1n + (size_t)t * HDIM))[threadIdx.x];
    size_t o = ((size_t)e * T_TOK + r) * HDIM + threadIdx.x * 4;
    split1(v.x, &g_xgh[o + 0], &g_xgl[o + 0]);
    split1(v.y, &g_xgh[o + 1], &g_xgl[o + 1]);
    split1(v.z, &g_xgh[o + 2], &g_xgl[o + 2]);
    split1(v.w, &g_xgh[o + 3], &g_xgl[o + 3]);
}

__global__ void combine_kernel(float* __restrict__ out) {
    int t = blockIdx.x;
    int i0 = g_ie[2*t], i1 = g_ie[2*t+1];
    int p0 = g_islot[2*t], p1 = g_islot[2*t+1];
    float w0 = g_iw[2*t], w1 = g_iw[2*t+1];
    const float4* d0 = (const float4*)(g_dg + ((size_t)i0 * T_TOK + p0) * HDIM);
    const float4* d1 = (const float4*)(g_dg + ((size_t)i1 * T_TOK + p1) * HDIM);
    const float4* xr = (const float4*)(g_x1 + (size_t)t * HDIM);
    float4* o = (float4*)(out + (size_t)t * HDIM);
    int c = threadIdx.x;
    float4 a = xr[c], b0 = d0[c], b1 = d1[c];
    a.x += w0 * b0.x + w1 * b1.x;
    a.y += w0 * b0.y + w1 * b1.y;
    a.z += w0 * b0.z + w1 * b1.z;
    a.w += w0 * b0.w + w1 * b1.w;
    o[c] = a;
}

// ================= launch =================
#define GSA(var, sym) do { void* _p; cudaGetSymbolAddress(&_p, sym); var = (decltype(var))_p; } while (0)

extern "C" void kernel_launch(void* const* d_in, const int* in_sizes, int n_in,
                              void* d_out, int out_size) {
    const float* hidden = (const float*)d_in[0];
    const float* wq    = (const float*)d_in[2];
    const float* wk    = (const float*)d_in[3];
    const float* wv    = (const float*)d_in[4];
    const float* wo    = (const float*)d_in[5];
    const float* ln1   = (const float*)d_in[6];
    const float* ln2   = (const float*)d_in[7];
    const float* gw    = (const float*)d_in[8];
    const float* wgate = (const float*)d_in[9];
    const float* wup   = (const float*)d_in[10];
    const float* wdown = (const float*)d_in[11];
    float* out = (float*)d_out;

    float *qkv, *x1, *x1n, *dg;
    int* cnt;
    __half *ah, *al, *oh, *ol, *xgh, *xgl, *hgh, *hgl;
    __half *wqkvp, *wop, *wgup, *wdnp;
    GSA(qkv, g_qkv); GSA(x1, g_x1); GSA(x1n, g_x1n);
    GSA(dg, g_dg); GSA(cnt, g_cnt);
    GSA(ah, g_ah); GSA(al, g_al); GSA(oh, g_oh); GSA(ol, g_ol);
    GSA(xgh, g_xgh); GSA(xgl, g_xgl); GSA(hgh, g_hgh); GSA(hgl, g_hgl);
    GSA(wqkvp, g_wqkv); GSA(wop, g_wo); GSA(wgup, g_wgu); GSA(wdnp, g_wdn);

    cudaFuncSetAttribute((const void*)tmma_kernel,
                         cudaFuncAttributeMaxDynamicSharedMemorySize, TMMA_SMEM);
    cudaFuncSetAttribute((const void*)flashmma_kernel,
                         cudaFuncAttributeMaxDynamicSharedMemorySize, FLASH_SMEM);

    // weight conversion (fp16 hi only)
    wconv_kernel<<<dim3(12, 12, 1), 256>>>(wq, wqkvp, HDIM, HDIM, 0, 0, 0, 0);
    wconv_kernel<<<dim3(12, 12, 1), 256>>>(wk, wqkvp, HDIM, HDIM, 0, 0, 0, 768);
    wconv_kernel<<<dim3(12, 12, 1), 256>>>(wv, wqkvp, HDIM, HDIM, 0, 0, 0, 1536);
    wconv_kernel<<<dim3(12, 12, 1), 256>>>(wo, wop, HDIM, HDIM, 0, 0, 0, 0);
    wconv_kernel<<<dim3(32, 12, NEXP), 256>>>(wgate, wgup, HDIM, IDIM,
                                              (size_t)HDIM*IDIM, (size_t)2*IDIM*HDIM, 1, 0);
    wconv_kernel<<<dim3(32, 12, NEXP), 256>>>(wup, wgup, HDIM, IDIM,
                                              (size_t)HDIM*IDIM, (size_t)2*IDIM*HDIM, 2, 0);
    wconv_kernel<<<dim3(12, 32, NEXP), 256>>>(wdown, wdnp, IDIM, HDIM,
                                              (size_t)IDIM*HDIM, (size_t)HDIM*IDIM, 0, 0);

    // 1. RMSNorm -> fp16 hi/lo
    rmsnorm_f16_kernel<<<T_TOK, 256>>>(hidden, ln1, ah, al);

    // 2. fused QKV projection
    tmma_kernel<<<dim3(18, 32, 1), 256, TMMA_SMEM>>>(ah, al, wqkvp, qkv,
        T_TOK, nullptr, 2304, HDIM, nullptr, 0, 0, 0, nullptr, nullptr, 0);

    // 3. RoPE
    rope_table_kernel<<<(SEQ * 32 + 255) / 256, 256>>>();
    rope_kernel<<<dim3(SEQ, NHEADS, BATCH), 64>>>();

    // 4. tensor-core causal flash attention
    flashmma_kernel<<<dim3(32, NHEADS, BATCH), 128, FLASH_SMEM>>>();

    // 5. output projection + residual
    tmma_kernel<<<dim3(6, 32, 1), 256, TMMA_SMEM>>>(oh, ol, wop, x1,
        T_TOK, nullptr, HDIM, HDIM, hidden, 0, 0, 0, nullptr, nullptr, 0);

    // 6. post-attention RMSNorm (+ cnt zeroing)
    rmsnorm_f32_kernel<<<T_TOK, 256>>>(x1, ln2, x1n);

    // 7. gating + aux
    gate_kernel<<<T_TOK / 8, 256>>>(gw);
    aux_kernel<<<1, 1024>>>(out);

    // 8. batched MoE with fused silu
    gather_kernel<<<dim3(T_TOK, NEXP), 192>>>();
    tmma_kernel<<<dim3(32, 32, NEXP), 256, TMMA_SMEM>>>(xgh, xgl, wgup, nullptr,
        0, cnt, 2 * IDIM, HDIM, nullptr,
        (size_t)T_TOK * HDIM, (size_t)2 * IDIM * HDIM, (size_t)T_TOK * IDIM, hgh, hgl, 1);
    tmma_kernel<<<dim3(6, 32, NEXP), 256, TMMA_SMEM>>>(hgh, hgl, wdnp, dg,
        0, cnt, HDIM, IDIM, nullptr,
        (size_t)T_TOK * IDIM, (size_t)HDIM * IDIM, (size_t)T_TOK * HDIM, nullptr, nullptr, 0);

    // 9. deterministic combine
    combine_kernel<<<T_TOK, 192>>>(out);
}

// round 7
// speedup vs baseline: 11.4199x; 1.4703x over previous
#include <cuda_runtime.h>
#include <cuda_fp16.h>
#include <math.h>
#include <stdint.h>

// ---- problem constants ----
#define T_TOK 4096      // B*S
#define SEQ   2048
#define BATCH 2
#define HDIM  768
#define NHEADS 12
#define HEADD 64
#define IDIM  2048
#define NEXP  8

// ---- fp32 scratch ----
__device__ __align__(128) float g_qkv [T_TOK*2304];
__device__ __align__(128) float g_x1  [T_TOK*HDIM];
__device__ __align__(128) float g_x1n [T_TOK*HDIM];
__device__ __align__(128) float g_dg  [(size_t)NEXP*T_TOK*HDIM];
__device__ float g_cos [SEQ*32];
__device__ float g_sin [SEQ*32];
__device__ float g_lse2[T_TOK];
__device__ int   g_cnt [NEXP];
__device__ int   g_rows[NEXP*T_TOK];
__device__ int   g_ie  [2*T_TOK];
__device__ int   g_islot[2*T_TOK];
__device__ float g_iw  [2*T_TOK];

// ---- fp16 activations (single precision term) ----
__device__ __align__(128) __half g_ax [T_TOK*HDIM];
__device__ __align__(128) __half g_qx [T_TOK*HDIM];   // [b,h,s,d]
__device__ __align__(128) __half g_kx [T_TOK*HDIM];
__device__ __align__(128) __half g_vtx[T_TOK*HDIM];   // [b,h,d,s]
__device__ __align__(128) __half g_ox [T_TOK*HDIM];
__device__ __align__(128) __half g_xg [(size_t)NEXP*T_TOK*HDIM];
__device__ __align__(128) __half g_hg [(size_t)NEXP*T_TOK*IDIM];

// ---- fp16 weights ([N,K] K-major; gate/up interleaved 64-row groups) ----
__device__ __align__(128) __half g_wqkv[2304*HDIM];
__device__ __align__(128) __half g_wo  [HDIM*HDIM];
__device__ __align__(128) __half g_wgu [(size_t)NEXP*2*IDIM*HDIM];
__device__ __align__(128) __half g_wdn [(size_t)NEXP*HDIM*IDIM];

// ================= helpers =================
__device__ __forceinline__ uint32_t s2u(const void* p) {
    uint32_t a;
    asm("{ .reg .u64 t; cvta.to.shared.u64 t, %1; cvt.u32.u64 %0, t; }" : "=r"(a) : "l"(p));
    return a;
}
__device__ __forceinline__ uint32_t pack2(float a, float b) {
    __half2 h2 = __halves2half2(__float2half_rn(a), __float2half_rn(b));
    return *(uint32_t*)&h2;
}

#define LDSM4(r, a) \
    asm volatile("ldmatrix.sync.aligned.m8n8.x4.shared.b16 {%0,%1,%2,%3}, [%4];" \
        : "=r"((r)[0]), "=r"((r)[1]), "=r"((r)[2]), "=r"((r)[3]) : "r"(a))
#define LDSM2(r, a) \
    asm volatile("ldmatrix.sync.aligned.m8n8.x2.shared.b16 {%0,%1}, [%2];" \
        : "=r"((r)[0]), "=r"((r)[1]) : "r"(a))
#define MMA_F16(c, a, b) \
    asm volatile("mma.sync.aligned.m16n8k16.row.col.f32.f16.f16.f32 " \
        "{%0,%1,%2,%3}, {%4,%5,%6,%7}, {%8,%9}, {%0,%1,%2,%3};" \
        : "+f"((c)[0]), "+f"((c)[1]), "+f"((c)[2]), "+f"((c)[3]) \
        : "r"((a)[0]), "r"((a)[1]), "r"((a)[2]), "r"((a)[3]), "r"((b)[0]), "r"((b)[1]))
#define CP_ASYNC16(dst, src) \
    asm volatile("cp.async.cg.shared.global [%0], [%1], 16;" :: "r"(dst), "l"(src))

// ================= weight transpose + fp16 round =================
__global__ __launch_bounds__(256) void wconv_kernel(
    const float* __restrict__ W, __half* __restrict__ oh, int K, int N,
    size_t inZ, size_t outZ, int mode, int dstOff)
{
    W  += (size_t)blockIdx.z * inZ;
    oh += (size_t)blockIdx.z * outZ;
    __shared__ float s[64][65];
    int n0 = blockIdx.x * 64, k0 = blockIdx.y * 64;
    int tid = threadIdx.x;
    int lr = tid >> 4;
    int lc = (tid & 15) * 4;
#pragma unroll
    for (int p = 0; p < 4; p++) {
        int kk = p * 16 + lr;
        float4 v = *(const float4*)(W + (size_t)(k0 + kk) * N + n0 + lc);
        s[lc + 0][kk] = v.x; s[lc + 1][kk] = v.y;
        s[lc + 2][kk] = v.z; s[lc + 3][kk] = v.w;
    }
    __syncthreads();
    int nl = tid >> 3;
    int kq = (tid & 7) * 8;
#pragma unroll
    for (int p = 0; p < 2; p++) {
        int nn = p * 32 + nl;
        int ng = n0 + nn;
        int nd = (mode == 0) ? ng : ((ng >> 6) * 128 + (ng & 63) + ((mode == 2) ? 64 : 0));
        nd += dstOff;
        __half hb[8];
#pragma unroll
        for (int j = 0; j < 8; j++) hb[j] = __float2half_rn(s[nn][kq + j]);
        *(uint4*)(oh + (size_t)nd * K + k0 + kq) = *(uint4*)hb;
    }
}

// ================= mma.sync fp16 GEMM (batched; optional fused silu) ===========
// C[M,N](fp32) = A@B^T.  A: [M,K] fp16 K-major; B: [N,K] fp16 K-major.
// Tile 128x128, K-chunk 32, cp.async double-buffer (2 tiles/stage), 8 warps.
#define TMMA_SMEM_PLAIN 40960
#define TMMA_SMEM_SILU  67584

__global__ __launch_bounds__(256) void tmma_kernel(
    const __half* __restrict__ A, const __half* __restrict__ B,
    float* __restrict__ C, int M, const int* __restrict__ cntArr,
    int N, int K, const float* __restrict__ Cadd,
    size_t zsA, size_t zsB, size_t zsC,
    __half* __restrict__ SO, int fuseSilu)
{
    int z = blockIdx.z;
    int m = cntArr ? cntArr[z] : M;
    int row0 = blockIdx.y * 128;
    if (row0 >= m) return;
    int col0 = blockIdx.x * 128;
    A += zsA * z; B += zsB * z;
    if (fuseSilu) SO += zsC * z; else C += zsC * z;

    extern __shared__ char sm[];
    uint32_t sbase = s2u(sm);
    int tid = threadIdx.x, lane = tid & 31, wid = tid >> 5;
    int wm = wid & 1, wn = wid >> 1;

    const __half* sp[2];
    sp[0] = A + (size_t)row0 * K;
    sp[1] = B + (size_t)col0 * K;

    float acc[4][4][4];
#pragma unroll
    for (int a = 0; a < 4; a++)
#pragma unroll
        for (int b = 0; b < 4; b++)
#pragma unroll
            for (int c = 0; c < 4; c++) acc[a][b][c] = 0.f;

    int NC = K >> 5;

#define LOAD_STAGE(cc, ss) do { \
    uint32_t _db = sbase + (ss) * 20480; \
    _Pragma("unroll") \
    for (int _t = 0; _t < 2; _t++) { \
        _Pragma("unroll") \
        for (int _i = 0; _i < 2; _i++) { \
            int _idx = tid + _i * 256; \
            int _r = _idx >> 2, _ch = _idx & 3; \
            uint32_t _dst = _db + _t * 10240 + _r * 80 + _ch * 16; \
            const void* _src = sp[_t] + (size_t)_r * K + (cc) * 32 + _ch * 8; \
            CP_ASYNC16(_dst, _src); \
        } \
    } \
    asm volatile("cp.async.commit_group;"); \
} while (0)

    LOAD_STAGE(0, 0);

    for (int c = 0; c < NC; c++) {
        if (c + 1 < NC) {
            LOAD_STAGE(c + 1, (c + 1) & 1);
            asm volatile("cp.async.wait_group 1;");
        } else {
            asm volatile("cp.async.wait_group 0;");
        }
        __syncthreads();

        uint32_t db = sbase + (c & 1) * 20480;
        uint32_t aT = db, bT = db + 10240;
#pragma unroll
        for (int ks = 0; ks < 2; ks++) {
            uint32_t af[4][4], bf[4][2];
            uint32_t aoff = (uint32_t)(wm * 64 + (lane & 15)) * 80 + ks * 32 + (lane >> 4) * 16;
            uint32_t boff = (uint32_t)(wn * 32 + (lane & 7)) * 80 + ks * 32 + ((lane >> 3) & 1) * 16;
#pragma unroll
            for (int mt = 0; mt < 4; mt++)
                LDSM4(af[mt], aT + aoff + mt * 1280);
#pragma unroll
            for (int nt = 0; nt < 4; nt++)
                LDSM2(bf[nt], bT + boff + nt * 640);
#pragma unroll
            for (int mt = 0; mt < 4; mt++)
#pragma unroll
                for (int nt = 0; nt < 4; nt++)
                    MMA_F16(acc[mt][nt], af[mt], bf[nt]);
        }
        __syncthreads();
    }

    if (fuseSilu) {
        float* st = (float*)sm;   // 128 x 132 floats
#pragma unroll
        for (int mt = 0; mt < 4; mt++) {
            int r = wm * 64 + mt * 16 + (lane >> 2);
            int cbase = wn * 32 + (lane & 3) * 2;
#pragma unroll
            for (int half = 0; half < 2; half++) {
#pragma unroll
                for (int nt = 0; nt < 4; nt++) {
                    float2 v; v.x = acc[mt][nt][half * 2 + 0]; v.y = acc[mt][nt][half * 2 + 1];
                    *(float2*)&st[(r + half * 8) * 132 + cbase + nt * 8] = v;
                }
            }
        }
        __syncthreads();
        int lr = tid >> 4;
        int lc = (tid & 15) * 4;
        int colg = blockIdx.x * 64 + lc;
#pragma unroll
        for (int p = 0; p < 8; p++) {
            int r = p * 16 + lr;
            int gr = row0 + r;
            if (gr < m) {
                float4 gv = *(float4*)&st[r * 132 + lc];
                float4 uv = *(float4*)&st[r * 132 + 64 + lc];
                float f0 = gv.x / (1.f + expf(-gv.x)) * uv.x;
                float f1 = gv.y / (1.f + expf(-gv.y)) * uv.y;
                float f2 = gv.z / (1.f + expf(-gv.z)) * uv.z;
                float f3 = gv.w / (1.f + expf(-gv.w)) * uv.w;
                uint2 hv; hv.x = pack2(f0, f1); hv.y = pack2(f2, f3);
                *(uint2*)(SO + (size_t)gr * IDIM + colg) = hv;
            }
        }
        return;
    }

#pragma unroll
    for (int mt = 0; mt < 4; mt++) {
        int rbase = row0 + wm * 64 + mt * 16 + (lane >> 2);
#pragma unroll
        for (int half = 0; half < 2; half++) {
            int rr = rbase + half * 8;
            if (rr < m) {
                size_t o = (size_t)rr * N + col0 + wn * 32 + (lane & 3) * 2;
#pragma unroll
                for (int nt = 0; nt < 4; nt++) {
                    float v0 = acc[mt][nt][half * 2 + 0];
                    float v1 = acc[mt][nt][half * 2 + 1];
                    size_t oo = o + nt * 8;
                    if (Cadd) {
                        float2 ad = *(const float2*)(Cadd + oo);
                        v0 += ad.x; v1 += ad.y;
                    }
                    float2 st2; st2.x = v0; st2.y = v1;
                    *(float2*)(C + oo) = st2;
                }
            }
        }
    }
}

// ================= RMSNorm =================
__device__ __forceinline__ float block_rms(const float* xr, int tid) {
    float s = 0.f;
    for (int c = tid; c < HDIM; c += 256) { float v = xr[c]; s += v * v; }
    __shared__ float red[8];
    for (int o = 16; o; o >>= 1) s += __shfl_xor_sync(0xffffffffu, s, o);
    if ((tid & 31) == 0) red[tid >> 5] = s;
    __syncthreads();
    if (tid < 8) {
        float v = red[tid];
        for (int o = 4; o; o >>= 1) v += __shfl_xor_sync(0xffu, v, o);
        if (tid == 0) red[0] = v;
    }
    __syncthreads();
    return rsqrtf(red[0] / (float)HDIM + 1e-6f);
}

__global__ void rmsnorm_f16_kernel(const float* __restrict__ x, const float* __restrict__ w,
                                   __half* __restrict__ oh) {
    int row = blockIdx.x;
    const float* xr = x + (size_t)row * HDIM;
    float scale = block_rms(xr, threadIdx.x);
    for (int c = threadIdx.x; c < HDIM; c += 256)
        oh[(size_t)row * HDIM + c] = __float2half_rn(w[c] * xr[c] * scale);
}

__global__ void rmsnorm_f32_kernel(const float* __restrict__ x, const float* __restrict__ w,
                                   float* __restrict__ out) {
    int row = blockIdx.x;
    if (row == 0 && threadIdx.x < NEXP) g_cnt[threadIdx.x] = 0;
    const float* xr = x + (size_t)row * HDIM;
    float scale = block_rms(xr, threadIdx.x);
    for (int c = threadIdx.x; c < HDIM; c += 256)
        out[(size_t)row * HDIM + c] = w[c] * xr[c] * scale;
}

// ================= RoPE =================
__global__ void rope_table_kernel() {
    int idx = blockIdx.x * blockDim.x + threadIdx.x;
    if (idx >= SEQ * 32) return;
    int i = idx & 31, s = idx >> 5;
    float inv = powf(10000.0f, -(float)i / 32.0f);
    float ang = (float)s * inv;
    g_cos[idx] = cosf(ang);
    g_sin[idx] = sinf(ang);
}

__global__ void rope_kernel() {
    int s = blockIdx.x, hh = blockIdx.y, bb = blockIdx.z, d = threadIdx.x;
    int t = bb * SEQ + s;
    const float* qkv = g_qkv + (size_t)t * 2304;
    int col  = hh * HEADD + d;
    int pcol = hh * HEADD + (d < 32 ? d + 32 : d - 32);
    float qv = qkv[col], kv = qkv[768 + col], vv = qkv[1536 + col];
    float qp = qkv[pcol], kp = qkv[768 + pcol];
    float cs = g_cos[s * 32 + (d & 31)], sn = g_sin[s * 32 + (d & 31)];
    float sgn = (d < 32) ? -1.f : 1.f;
    float qr = qv * cs + sgn * qp * sn;
    float kr = kv * cs + sgn * kp * sn;
    size_t dst = (((size_t)bb * NHEADS + hh) * SEQ + s) * HEADD + d;
    g_qx[dst] = __float2half_rn(qr);
    g_kx[dst] = __float2half_rn(kr);
    size_t vdst = (((size_t)bb * NHEADS + hh) * HEADD + d) * SEQ + s;
    g_vtx[vdst] = __float2half_rn(vv);
}

// ================= tensor-core flash attention (fp16) =================
#define FROW 144
#define FTILE 9216
#define FLASH_SMEM (3*FTILE)

__global__ __launch_bounds__(128) void flashmma_kernel() {
    int qt = 31 - (int)blockIdx.x;
    int hh = blockIdx.y, bb = blockIdx.z;
    extern __shared__ char fsm[];
    uint32_t sb = s2u(fsm);
    uint32_t sQ = sb, sK = sb + FTILE, sV = sb + 2*FTILE;
    char* pS = fsm;

    int tid = threadIdx.x, lane = tid & 31, w = tid >> 5;
    size_t hb = (size_t)bb * NHEADS + hh;
    const __half* Qp = g_qx + hb * SEQ * HEADD;
    const __half* Kp = g_kx + hb * SEQ * HEADD;
    const __half* Vp = g_vtx + hb * HEADD * SEQ;

    for (int i = tid; i < 512; i += 128) {
        int r = i >> 3, ch = i & 7;
        *(uint4*)(pS + r * FROW + ch * 16) =
            *(const uint4*)(Qp + (size_t)(qt * 64 + r) * HEADD + ch * 8);
    }
    __syncthreads();

    uint32_t qf[4][4];
#pragma unroll
    for (int ks = 0; ks < 4; ks++) {
        uint32_t ao = (uint32_t)(w * 16 + (lane & 15)) * FROW + ks * 32 + (lane >> 4) * 16;
        LDSM4(qf[ks], sQ + ao);
    }

    float accO[8][4];
#pragma unroll
    for (int i = 0; i < 8; i++)
#pragma unroll
        for (int j = 0; j < 4; j++) accO[i][j] = 0.f;
    float mrow0 = -INFINITY, mrow1 = -INFINITY, lrow0 = 0.f, lrow1 = 0.f;
    const float SC = 0.125f * 1.44269504f;

    for (int kt = 0; kt <= qt; kt++) {
        __syncthreads();
        for (int i = tid; i < 512; i += 128) {
            int r = i >> 3, ch = i & 7;
            *(uint4*)(pS + FTILE + r * FROW + ch * 16) =
                *(const uint4*)(Kp + (size_t)(kt * 64 + r) * HEADD + ch * 8);
            *(uint4*)(pS + 2*FTILE + r * FROW + ch * 16) =
                *(const uint4*)(Vp + (size_t)r * SEQ + kt * 64 + ch * 8);
        }
        __syncthreads();

        float sacc[8][4];
#pragma unroll
        for (int nt = 0; nt < 8; nt++)
#pragma unroll
            for (int j = 0; j < 4; j++) sacc[nt][j] = 0.f;
#pragma unroll
        for (int ks = 0; ks < 4; ks++) {
#pragma unroll
            for (int nt = 0; nt < 8; nt++) {
                uint32_t k2[2];
                uint32_t bo = (uint32_t)(nt * 8 + (lane & 7)) * FROW + ks * 32 + ((lane >> 3) & 1) * 16;
                LDSM2(k2, sK + bo);
                MMA_F16(sacc[nt], qf[ks], k2);
            }
        }

        int grow = qt * 64 + w * 16 + (lane >> 2);
        if (kt == qt) {
#pragma unroll
            for (int nt = 0; nt < 8; nt++) {
                int cbase = kt * 64 + nt * 8 + (lane & 3) * 2;
                sacc[nt][0] = (cbase     <= grow    ) ? sacc[nt][0] * SC : -1e30f;
                sacc[nt][1] = (cbase + 1 <= grow    ) ? sacc[nt][1] * SC : -1e30f;
                sacc[nt][2] = (cbase     <= grow + 8) ? sacc[nt][2] * SC : -1e30f;
                sacc[nt][3] = (cbase + 1 <= grow + 8) ? sacc[nt][3] * SC : -1e30f;
            }
        } else {
#pragma unroll
            for (int nt = 0; nt < 8; nt++)
#pragma unroll
                for (int j = 0; j < 4; j++) sacc[nt][j] *= SC;
        }

        float mx0 = -INFINITY, mx1 = -INFINITY;
#pragma unroll
        for (int nt = 0; nt < 8; nt++) {
            mx0 = fmaxf(mx0, fmaxf(sacc[nt][0], sacc[nt][1]));
            mx1 = fmaxf(mx1, fmaxf(sacc[nt][2], sacc[nt][3]));
        }
        mx0 = fmaxf(mx0, __shfl_xor_sync(0xffffffffu, mx0, 1));
        mx0 = fmaxf(mx0, __shfl_xor_sync(0xffffffffu, mx0, 2));
        mx1 = fmaxf(mx1, __shfl_xor_sync(0xffffffffu, mx1, 1));
        mx1 = fmaxf(mx1, __shfl_xor_sync(0xffffffffu, mx1, 2));
        float mn0 = fmaxf(mrow0, mx0), mn1 = fmaxf(mrow1, mx1);
        float al0 = exp2f(mrow0 - mn0), al1 = exp2f(mrow1 - mn1);
        mrow0 = mn0; mrow1 = mn1;
#pragma unroll
        for (int nt = 0; nt < 8; nt++) {
            accO[nt][0] *= al0; accO[nt][1] *= al0;
            accO[nt][2] *= al1; accO[nt][3] *= al1;
        }
        lrow0 *= al0; lrow1 *= al1;

        float sum0 = 0.f, sum1 = 0.f;
#pragma unroll
        for (int ks = 0; ks < 4; ks++) {
            float p[2][4];
#pragma unroll
            for (int h2 = 0; h2 < 2; h2++) {
                int nt = ks * 2 + h2;
                p[h2][0] = exp2f(sacc[nt][0] - mn0);
                p[h2][1] = exp2f(sacc[nt][1] - mn0);
                p[h2][2] = exp2f(sacc[nt][2] - mn1);
                p[h2][3] = exp2f(sacc[nt][3] - mn1);
                sum0 += p[h2][0] + p[h2][1];
                sum1 += p[h2][2] + p[h2][3];
            }
            uint32_t pf[4];
            pf[0] = pack2(p[0][0], p[0][1]);
            pf[1] = pack2(p[0][2], p[0][3]);
            pf[2] = pack2(p[1][0], p[1][1]);
            pf[3] = pack2(p[1][2], p[1][3]);
#pragma unroll
            for (int ntd = 0; ntd < 8; ntd++) {
                uint32_t v2[2];
                uint32_t vo = (uint32_t)(ntd * 8 + (lane & 7)) * FROW + ks * 32 + ((lane >> 3) & 1) * 16;
                LDSM2(v2, sV + vo);
                MMA_F16(accO[ntd], pf, v2);
            }
        }
        sum0 += __shfl_xor_sync(0xffffffffu, sum0, 1);
        sum0 += __shfl_xor_sync(0xffffffffu, sum0, 2);
        sum1 += __shfl_xor_sync(0xffffffffu, sum1, 1);
        sum1 += __shfl_xor_sync(0xffffffffu, sum1, 2);
        lrow0 += sum0; lrow1 += sum1;
    }

    float inv0 = 1.f / lrow0, inv1 = 1.f / lrow1;
    int row0 = qt * 64 + w * 16 + (lane >> 2);
    size_t rb = ((size_t)bb * SEQ + row0) * HDIM + hh * HEADD + (lane & 3) * 2;
#pragma unroll
    for (int ntd = 0; ntd < 8; ntd++) {
        *(uint32_t*)(g_ox + rb + ntd * 8) = pack2(accO[ntd][0] * inv0, accO[ntd][1] * inv0);
        *(uint32_t*)(g_ox + rb + 8 * HDIM + ntd * 8) = pack2(accO[ntd][2] * inv1, accO[ntd][3] * inv1);
    }
}

// ================= MoE gating =================
__global__ void gate_kernel(const float* __restrict__ gw) {
    int t = blockIdx.x * 8 + (threadIdx.x >> 5);
    int lane = threadIdx.x & 31;
    const float* xr = g_x1n + (size_t)t * HDIM;
    float acc[8] = {0, 0, 0, 0, 0, 0, 0, 0};
    for (int j = lane; j < HDIM; j += 32) {
        float xv = xr[j];
        const float* gr = gw + j * 8;
        float4 g0 = *(const float4*)gr, g1 = *(const float4*)(gr + 4);
        acc[0] += xv * g0.x; acc[1] += xv * g0.y; acc[2] += xv * g0.z; acc[3] += xv * g0.w;
        acc[4] += xv * g1.x; acc[5] += xv * g1.y; acc[6] += xv * g1.z; acc[7] += xv * g1.w;
    }
#pragma unroll
    for (int e = 0; e < 8; e++)
        for (int o = 16; o; o >>= 1) acc[e] += __shfl_xor_sync(0xffffffffu, acc[e], o);
    if (lane == 0) {
        float mx = acc[0];
#pragma unroll
        for (int e = 1; e < 8; e++) mx = fmaxf(mx, acc[e]);
        float se = 0.f;
#pragma unroll
        for (int e = 0; e < 8; e++) se += expf(acc[e] - mx);
        float lse = mx + logf(se);
        g_lse2[t] = lse * lse;
        int i0 = 0; float v0 = acc[0];
#pragma unroll
        for (int e = 1; e < 8; e++) if (acc[e] > v0) { v0 = acc[e]; i0 = e; }
        int i1 = -1; float v1 = -INFINITY;
#pragma unroll
        for (int e = 0; e < 8; e++) if (e != i0 && acc[e] > v1) { v1 = acc[e]; i1 = e; }
        float w0 = 1.f / (1.f + expf(v1 - v0));
        float w1 = 1.f - w0;
        int p0 = atomicAdd(&g_cnt[i0], 1);
        g_rows[i0 * T_TOK + p0] = t;
        int p1 = atomicAdd(&g_cnt[i1], 1);
        g_rows[i1 * T_TOK + p1] = t;
        g_ie[2*t] = i0; g_islot[2*t] = p0; g_iw[2*t] = w0;
        g_ie[2*t+1] = i1; g_islot[2*t+1] = p1; g_iw[2*t+1] = w1;
    }
}

__global__ void aux_kernel(float* __restrict__ out) {
    __shared__ float red[32];
    float s = 0.f;
    for (int i = threadIdx.x; i < T_TOK; i += 1024) s += g_lse2[i];
    for (int o = 16; o; o >>= 1) s += __shfl_xor_sync(0xffffffffu, s, o);
    if ((threadIdx.x & 31) == 0) red[threadIdx.x >> 5] = s;
    __syncthreads();
    if (threadIdx.x < 32) {
        float v = red[threadIdx.x];
        for (int o = 16; o; o >>= 1) v += __shfl_xor_sync(0xffffffffu, v, o);
        if (threadIdx.x == 0) out[(size_t)T_TOK * HDIM] = 0.001f * v / (float)T_TOK;
    }
}

__global__ void gather_kernel() {
    int e = blockIdx.y, r = blockIdx.x;
    if (r >= g_cnt[e]) return;
    int t = g_rows[e * T_TOK + r];
    float4 v = ((const float4*)(g_x1n + (size_t)t * HDIM))[threadIdx.x];
    size_t o = ((size_t)e * T_TOK + r) * HDIM + threadIdx.x * 4;
    uint2 hv; hv.x = pack2(v.x, v.y); hv.y = pack2(v.z, v.w);
    *(uint2*)(g_xg + o) = hv;
}

__global__ void combine_kernel(float* __restrict__ out) {
    int t = blockIdx.x;
    int i0 = g_ie[2*t], i1 = g_ie[2*t+1];
    int p0 = g_islot[2*t], p1 = g_islot[2*t+1];
    float w0 = g_iw[2*t], w1 = g_iw[2*t+1];
    const float4* d0 = (const float4*)(g_dg + ((size_t)i0 * T_TOK + p0) * HDIM);
    const float4* d1 = (const float4*)(g_dg + ((size_t)i1 * T_TOK + p1) * HDIM);
    const float4* xr = (const float4*)(g_x1 + (size_t)t * HDIM);
    float4* o = (float4*)(out + (size_t)t * HDIM);
    int c = threadIdx.x;
    float4 a = xr[c], b0 = d0[c], b1 = d1[c];
    a.x += w0 * b0.x + w1 * b1.x;
    a.y += w0 * b0.y + w1 * b1.y;
    a.z += w0 * b0.z + w1 * b1.z;
    a.w += w0 * b0.w + w1 * b1.w;
    o[c] = a;
}

// ================= launch =================
#define GSA(var, sym) do { void* _p; cudaGetSymbolAddress(&_p, sym); var = (decltype(var))_p; } while (0)

extern "C" void kernel_launch(void* const* d_in, const int* in_sizes, int n_in,
                              void* d_out, int out_size) {
    const float* hidden = (const float*)d_in[0];
    const float* wq    = (const float*)d_in[2];
    const float* wk    = (const float*)d_in[3];
    const float* wv    = (const float*)d_in[4];
    const float* wo    = (const float*)d_in[5];
    const float* ln1   = (const float*)d_in[6];
    const float* ln2   = (const float*)d_in[7];
    const float* gw    = (const float*)d_in[8];
    const float* wgate = (const float*)d_in[9];
    const float* wup   = (const float*)d_in[10];
    const float* wdown = (const float*)d_in[11];
    float* out = (float*)d_out;

    float *qkv, *x1, *x1n, *dg;
    int* cnt;
    __half *ax, *ox, *xg, *hg;
    __half *wqkvp, *wop, *wgup, *wdnp;
    GSA(qkv, g_qkv); GSA(x1, g_x1); GSA(x1n, g_x1n);
    GSA(dg, g_dg); GSA(cnt, g_cnt);
    GSA(ax, g_ax); GSA(ox, g_ox); GSA(xg, g_xg); GSA(hg, g_hg);
    GSA(wqkvp, g_wqkv); GSA(wop, g_wo); GSA(wgup, g_wgu); GSA(wdnp, g_wdn);

    cudaFuncSetAttribute((const void*)tmma_kernel,
                         cudaFuncAttributeMaxDynamicSharedMemorySize, TMMA_SMEM_SILU);
    cudaFuncSetAttribute((const void*)flashmma_kernel,
                         cudaFuncAttributeMaxDynamicSharedMemorySize, FLASH_SMEM);

    // weight conversion
    wconv_kernel<<<dim3(12, 12, 1), 256>>>(wq, wqkvp, HDIM, HDIM, 0, 0, 0, 0);
    wconv_kernel<<<dim3(12, 12, 1), 256>>>(wk, wqkvp, HDIM, HDIM, 0, 0, 0, 768);
    wconv_kernel<<<dim3(12, 12, 1), 256>>>(wv, wqkvp, HDIM, HDIM, 0, 0, 0, 1536);
    wconv_kernel<<<dim3(12, 12, 1), 256>>>(wo, wop, HDIM, HDIM, 0, 0, 0, 0);
    wconv_kernel<<<dim3(32, 12, NEXP), 256>>>(wgate, wgup, HDIM, IDIM,
                                              (size_t)HDIM*IDIM, (size_t)2*IDIM*HDIM, 1, 0);
    wconv_kernel<<<dim3(32, 12, NEXP), 256>>>(wup, wgup, HDIM, IDIM,
                                              (size_t)HDIM*IDIM, (size_t)2*IDIM*HDIM, 2, 0);
    wconv_kernel<<<dim3(12, 32, NEXP), 256>>>(wdown, wdnp, IDIM, HDIM,
                                              (size_t)IDIM*HDIM, (size_t)HDIM*IDIM, 0, 0);

    // 1. RMSNorm -> fp16
    rmsnorm_f16_kernel<<<T_TOK, 256>>>(hidden, ln1, ax);

    // 2. fused QKV projection
    tmma_kernel<<<dim3(18, 32, 1), 256, TMMA_SMEM_PLAIN>>>(ax, wqkvp, qkv,
        T_TOK, nullptr, 2304, HDIM, nullptr, 0, 0, 0, nullptr, 0);

    // 3. RoPE
    rope_table_kernel<<<(SEQ * 32 + 255) / 256, 256>>>();
    rope_kernel<<<dim3(SEQ, NHEADS, BATCH), 64>>>();

    // 4. tensor-core causal flash attention
    flashmma_kernel<<<dim3(32, NHEADS, BATCH), 128, FLASH_SMEM>>>();

    // 5. output projection + residual
    tmma_kernel<<<dim3(6, 32, 1), 256, TMMA_SMEM_PLAIN>>>(ox, wop, x1,
        T_TOK, nullptr, HDIM, HDIM, hidden, 0, 0, 0, nullptr, 0);

    // 6. post-attention RMSNorm (+ cnt zeroing)
    rmsnorm_f32_kernel<<<T_TOK, 256>>>(x1, ln2, x1n);

    // 7. gating + aux
    gate_kernel<<<T_TOK / 8, 256>>>(gw);
    aux_kernel<<<1, 1024>>>(out);

    // 8. batched MoE with fused silu
    gather_kernel<<<dim3(T_TOK, NEXP), 192>>>();
    tmma_kernel<<<dim3(32, 32, NEXP), 256, TMMA_SMEM_SILU>>>(xg, wgup, nullptr,
        0, cnt, 2 * IDIM, HDIM, nullptr,
        (size_t)T_TOK * HDIM, (size_t)2 * IDIM * HDIM, (size_t)T_TOK * IDIM, hg, 1);
    tmma_kernel<<<dim3(6, 32, NEXP), 256, TMMA_SMEM_PLAIN>>>(hg, wdnp, dg,
        0, cnt, HDIM, IDIM, nullptr,
        (size_t)T_TOK * IDIM, (size_t)HDIM * IDIM, (size_t)T_TOK * HDIM, nullptr, 0);

    // 9. deterministic combine
    combine_kernel<<<T_TOK, 192>>>(out);
}

// round 8
// speedup vs baseline: 11.5127x; 1.0081x over previous
#include <cuda_runtime.h>
#include <cuda_fp16.h>
#include <math.h>
#include <stdint.h>

// ---- problem constants ----
#define T_TOK 4096      // B*S
#define SEQ   2048
#define BATCH 2
#define HDIM  768
#define NHEADS 12
#define HEADD 64
#define IDIM  2048
#define NEXP  8

// ---- fp32 scratch ----
__device__ __align__(128) float g_qkv [T_TOK*2304];
__device__ __align__(128) float g_x1  [T_TOK*HDIM];
__device__ __align__(128) float g_x1n [T_TOK*HDIM];
__device__ __align__(128) float g_dg  [(size_t)NEXP*T_TOK*HDIM];
__device__ float g_cos [SEQ*32];
__device__ float g_sin [SEQ*32];
__device__ float g_lse2[T_TOK];
__device__ int   g_cnt [NEXP];
__device__ int   g_rows[NEXP*T_TOK];
__device__ int   g_ie  [2*T_TOK];
__device__ int   g_islot[2*T_TOK];
__device__ float g_iw  [2*T_TOK];

// ---- fp16 activations ----
__device__ __align__(128) __half g_ax [T_TOK*HDIM];
__device__ __align__(128) __half g_qx [T_TOK*HDIM];   // [b,h,s,d]
__device__ __align__(128) __half g_kx [T_TOK*HDIM];
__device__ __align__(128) __half g_vtx[T_TOK*HDIM];   // [b,h,d,s]
__device__ __align__(128) __half g_ox [T_TOK*HDIM];
__device__ __align__(128) __half g_xg [(size_t)NEXP*T_TOK*HDIM];
__device__ __align__(128) __half g_hg [(size_t)NEXP*T_TOK*IDIM];

// ---- fp16 weights ([N,K] K-major; gate/up interleaved 64-row groups) ----
__device__ __align__(128) __half g_wqkv[2304*HDIM];
__device__ __align__(128) __half g_wo  [HDIM*HDIM];
__device__ __align__(128) __half g_wgu [(size_t)NEXP*2*IDIM*HDIM];
__device__ __align__(128) __half g_wdn [(size_t)NEXP*HDIM*IDIM];

// ================= helpers =================
__device__ __forceinline__ uint32_t s2u(const void* p) {
    uint32_t a;
    asm("{ .reg .u64 t; cvta.to.shared.u64 t, %1; cvt.u32.u64 %0, t; }" : "=r"(a) : "l"(p));
    return a;
}
__device__ __forceinline__ uint32_t pack2(float a, float b) {
    __half2 h2 = __halves2half2(__float2half_rn(a), __float2half_rn(b));
    return *(uint32_t*)&h2;
}

#define LDSM4(r, a) \
    asm volatile("ldmatrix.sync.aligned.m8n8.x4.shared.b16 {%0,%1,%2,%3}, [%4];" \
        : "=r"((r)[0]), "=r"((r)[1]), "=r"((r)[2]), "=r"((r)[3]) : "r"(a))
#define LDSM2(r, a) \
    asm volatile("ldmatrix.sync.aligned.m8n8.x2.shared.b16 {%0,%1}, [%2];" \
        : "=r"((r)[0]), "=r"((r)[1]) : "r"(a))
#define MMA_F16(c, a, b) \
    asm volatile("mma.sync.aligned.m16n8k16.row.col.f32.f16.f16.f32 " \
        "{%0,%1,%2,%3}, {%4,%5,%6,%7}, {%8,%9}, {%0,%1,%2,%3};" \
        : "+f"((c)[0]), "+f"((c)[1]), "+f"((c)[2]), "+f"((c)[3]) \
        : "r"((a)[0]), "r"((a)[1]), "r"((a)[2]), "r"((a)[3]), "r"((b)[0]), "r"((b)[1]))
#define CP_ASYNC16(dst, src) \
    asm volatile("cp.async.cg.shared.global [%0], [%1], 16;" :: "r"(dst), "l"(src))

// ================= weight transpose + fp16 round =================
__global__ __launch_bounds__(256) void wconv_kernel(
    const float* __restrict__ W, __half* __restrict__ oh, int K, int N,
    size_t inZ, size_t outZ, int mode, int dstOff)
{
    W  += (size_t)blockIdx.z * inZ;
    oh += (size_t)blockIdx.z * outZ;
    __shared__ float s[64][65];
    int n0 = blockIdx.x * 64, k0 = blockIdx.y * 64;
    int tid = threadIdx.x;
    int lr = tid >> 4;
    int lc = (tid & 15) * 4;
#pragma unroll
    for (int p = 0; p < 4; p++) {
        int kk = p * 16 + lr;
        float4 v = *(const float4*)(W + (size_t)(k0 + kk) * N + n0 + lc);
        s[lc + 0][kk] = v.x; s[lc + 1][kk] = v.y;
        s[lc + 2][kk] = v.z; s[lc + 3][kk] = v.w;
    }
    __syncthreads();
    int nl = tid >> 3;
    int kq = (tid & 7) * 8;
#pragma unroll
    for (int p = 0; p < 2; p++) {
        int nn = p * 32 + nl;
        int ng = n0 + nn;
        int nd = (mode == 0) ? ng : ((ng >> 6) * 128 + (ng & 63) + ((mode == 2) ? 64 : 0));
        nd += dstOff;
        __half hb[8];
#pragma unroll
        for (int j = 0; j < 8; j++) hb[j] = __float2half_rn(s[nn][kq + j]);
        *(uint4*)(oh + (size_t)nd * K + k0 + kq) = *(uint4*)hb;
    }
}

// ================= mma.sync fp16 GEMM (batched; optional fused silu) ===========
#define TMMA_SMEM_PLAIN 40960
#define TMMA_SMEM_SILU  67584

__global__ __launch_bounds__(256) void tmma_kernel(
    const __half* __restrict__ A, const __half* __restrict__ B,
    float* __restrict__ C, int M, const int* __restrict__ cntArr,
    int N, int K, const float* __restrict__ Cadd,
    size_t zsA, size_t zsB, size_t zsC,
    __half* __restrict__ SO, int fuseSilu)
{
    int z = blockIdx.z;
    int m = cntArr ? cntArr[z] : M;
    int row0 = blockIdx.y * 128;
    if (row0 >= m) return;
    int col0 = blockIdx.x * 128;
    A += zsA * z; B += zsB * z;
    if (fuseSilu) SO += zsC * z; else C += zsC * z;

    extern __shared__ char sm[];
    uint32_t sbase = s2u(sm);
    int tid = threadIdx.x, lane = tid & 31, wid = tid >> 5;
    int wm = wid & 1, wn = wid >> 1;

    const __half* sp[2];
    sp[0] = A + (size_t)row0 * K;
    sp[1] = B + (size_t)col0 * K;

    float acc[4][4][4];
#pragma unroll
    for (int a = 0; a < 4; a++)
#pragma unroll
        for (int b = 0; b < 4; b++)
#pragma unroll
            for (int c = 0; c < 4; c++) acc[a][b][c] = 0.f;

    int NC = K >> 5;

#define LOAD_STAGE(cc, ss) do { \
    uint32_t _db = sbase + (ss) * 20480; \
    _Pragma("unroll") \
    for (int _t = 0; _t < 2; _t++) { \
        _Pragma("unroll") \
        for (int _i = 0; _i < 2; _i++) { \
            int _idx = tid + _i * 256; \
            int _r = _idx >> 2, _ch = _idx & 3; \
            uint32_t _dst = _db + _t * 10240 + _r * 80 + _ch * 16; \
            const void* _src = sp[_t] + (size_t)_r * K + (cc) * 32 + _ch * 8; \
            CP_ASYNC16(_dst, _src); \
        } \
    } \
    asm volatile("cp.async.commit_group;"); \
} while (0)

    LOAD_STAGE(0, 0);

    for (int c = 0; c < NC; c++) {
        if (c + 1 < NC) {
            LOAD_STAGE(c + 1, (c + 1) & 1);
            asm volatile("cp.async.wait_group 1;");
        } else {
            asm volatile("cp.async.wait_group 0;");
        }
        __syncthreads();

        uint32_t db = sbase + (c & 1) * 20480;
        uint32_t aT = db, bT = db + 10240;
#pragma unroll
        for (int ks = 0; ks < 2; ks++) {
            uint32_t af[4][4], bf[4][2];
            uint32_t aoff = (uint32_t)(wm * 64 + (lane & 15)) * 80 + ks * 32 + (lane >> 4) * 16;
            uint32_t boff = (uint32_t)(wn * 32 + (lane & 7)) * 80 + ks * 32 + ((lane >> 3) & 1) * 16;
#pragma unroll
            for (int mt = 0; mt < 4; mt++)
                LDSM4(af[mt], aT + aoff + mt * 1280);
#pragma unroll
            for (int nt = 0; nt < 4; nt++)
                LDSM2(bf[nt], bT + boff + nt * 640);
#pragma unroll
            for (int mt = 0; mt < 4; mt++)
#pragma unroll
                for (int nt = 0; nt < 4; nt++)
                    MMA_F16(acc[mt][nt], af[mt], bf[nt]);
        }
        __syncthreads();
    }

    if (fuseSilu) {
        float* st = (float*)sm;   // 128 x 132 floats
#pragma unroll
        for (int mt = 0; mt < 4; mt++) {
            int r = wm * 64 + mt * 16 + (lane >> 2);
            int cbase = wn * 32 + (lane & 3) * 2;
#pragma unroll
            for (int half = 0; half < 2; half++) {
#pragma unroll
                for (int nt = 0; nt < 4; nt++) {
                    float2 v; v.x = acc[mt][nt][half * 2 + 0]; v.y = acc[mt][nt][half * 2 + 1];
                    *(float2*)&st[(r + half * 8) * 132 + cbase + nt * 8] = v;
                }
            }
        }
        __syncthreads();
        int lr = tid >> 4;
        int lc = (tid & 15) * 4;
        int colg = blockIdx.x * 64 + lc;
#pragma unroll
        for (int p = 0; p < 8; p++) {
            int r = p * 16 + lr;
            int gr = row0 + r;
            if (gr < m) {
                float4 gv = *(float4*)&st[r * 132 + lc];
                float4 uv = *(float4*)&st[r * 132 + 64 + lc];
                float f0 = gv.x / (1.f + expf(-gv.x)) * uv.x;
                float f1 = gv.y / (1.f + expf(-gv.y)) * uv.y;
                float f2 = gv.z / (1.f + expf(-gv.z)) * uv.z;
                float f3 = gv.w / (1.f + expf(-gv.w)) * uv.w;
                uint2 hv; hv.x = pack2(f0, f1); hv.y = pack2(f2, f3);
                *(uint2*)(SO + (size_t)gr * IDIM + colg) = hv;
            }
        }
        return;
    }

#pragma unroll
    for (int mt = 0; mt < 4; mt++) {
        int rbase = row0 + wm * 64 + mt * 16 + (lane >> 2);
#pragma unroll
        for (int half = 0; half < 2; half++) {
            int rr = rbase + half * 8;
            if (rr < m) {
                size_t o = (size_t)rr * N + col0 + wn * 32 + (lane & 3) * 2;
#pragma unroll
                for (int nt = 0; nt < 4; nt++) {
                    float v0 = acc[mt][nt][half * 2 + 0];
                    float v1 = acc[mt][nt][half * 2 + 1];
                    size_t oo = o + nt * 8;
                    if (Cadd) {
                        float2 ad = *(const float2*)(Cadd + oo);
                        v0 += ad.x; v1 += ad.y;
                    }
                    float2 st2; st2.x = v0; st2.y = v1;
                    *(float2*)(C + oo) = st2;
                }
            }
        }
    }
}

// ================= RMSNorm =================
__device__ __forceinline__ float block_rms(const float* xr, int tid) {
    float s = 0.f;
    for (int c = tid; c < HDIM; c += 256) { float v = xr[c]; s += v * v; }
    __shared__ float red[8];
    for (int o = 16; o; o >>= 1) s += __shfl_xor_sync(0xffffffffu, s, o);
    if ((tid & 31) == 0) red[tid >> 5] = s;
    __syncthreads();
    if (tid < 8) {
        float v = red[tid];
        for (int o = 4; o; o >>= 1) v += __shfl_xor_sync(0xffu, v, o);
        if (tid == 0) red[0] = v;
    }
    __syncthreads();
    return rsqrtf(red[0] / (float)HDIM + 1e-6f);
}

__global__ void rmsnorm_f16_kernel(const float* __restrict__ x, const float* __restrict__ w,
                                   __half* __restrict__ oh) {
    int row = blockIdx.x;
    const float* xr = x + (size_t)row * HDIM;
    float scale = block_rms(xr, threadIdx.x);
    for (int c = threadIdx.x; c < HDIM; c += 256)
        oh[(size_t)row * HDIM + c] = __float2half_rn(w[c] * xr[c] * scale);
}

__global__ void rmsnorm_f32_kernel(const float* __restrict__ x, const float* __restrict__ w,
                                   float* __restrict__ out) {
    int row = blockIdx.x;
    if (row == 0 && threadIdx.x < NEXP) g_cnt[threadIdx.x] = 0;
    const float* xr = x + (size_t)row * HDIM;
    float scale = block_rms(xr, threadIdx.x);
    for (int c = threadIdx.x; c < HDIM; c += 256)
        out[(size_t)row * HDIM + c] = w[c] * xr[c] * scale;
}

// ================= RoPE =================
__global__ void rope_table_kernel() {
    int idx = blockIdx.x * blockDim.x + threadIdx.x;
    if (idx >= SEQ * 32) return;
    int i = idx & 31, s = idx >> 5;
    float inv = powf(10000.0f, -(float)i / 32.0f);
    float ang = (float)s * inv;
    g_cos[idx] = cosf(ang);
    g_sin[idx] = sinf(ang);
}

__global__ void rope_kernel() {
    int s = blockIdx.x, hh = blockIdx.y, bb = blockIdx.z, d = threadIdx.x;
    int t = bb * SEQ + s;
    const float* qkv = g_qkv + (size_t)t * 2304;
    int col  = hh * HEADD + d;
    int pcol = hh * HEADD + (d < 32 ? d + 32 : d - 32);
    float qv = qkv[col], kv = qkv[768 + col], vv = qkv[1536 + col];
    float qp = qkv[pcol], kp = qkv[768 + pcol];
    float cs = g_cos[s * 32 + (d & 31)], sn = g_sin[s * 32 + (d & 31)];
    float sgn = (d < 32) ? -1.f : 1.f;
    float qr = qv * cs + sgn * qp * sn;
    float kr = kv * cs + sgn * kp * sn;
    size_t dst = (((size_t)bb * NHEADS + hh) * SEQ + s) * HEADD + d;
    g_qx[dst] = __float2half_rn(qr);
    g_kx[dst] = __float2half_rn(kr);
    size_t vdst = (((size_t)bb * NHEADS + hh) * HEADD + d) * SEQ + s;
    g_vtx[vdst] = __float2half_rn(vv);
}

// ================= tensor-core flash attention (fp16) =================
#define FROW 144
#define FTILE 9216
#define FLASH_SMEM (3*FTILE)

__global__ __launch_bounds__(128) void flashmma_kernel() {
    int qt = 31 - (int)blockIdx.x;
    int hh = blockIdx.y, bb = blockIdx.z;
    extern __shared__ char fsm[];
    uint32_t sb = s2u(fsm);
    uint32_t sQ = sb, sK = sb + FTILE, sV = sb + 2*FTILE;
    char* pS = fsm;

    int tid = threadIdx.x, lane = tid & 31, w = tid >> 5;
    size_t hb = (size_t)bb * NHEADS + hh;
    const __half* Qp = g_qx + hb * SEQ * HEADD;
    const __half* Kp = g_kx + hb * SEQ * HEADD;
    const __half* Vp = g_vtx + hb * HEADD * SEQ;

    for (int i = tid; i < 512; i += 128) {
        int r = i >> 3, ch = i & 7;
        *(uint4*)(pS + r * FROW + ch * 16) =
            *(const uint4*)(Qp + (size_t)(qt * 64 + r) * HEADD + ch * 8);
    }
    __syncthreads();

    uint32_t qf[4][4];
#pragma unroll
    for (int ks = 0; ks < 4; ks++) {
        uint32_t ao = (uint32_t)(w * 16 + (lane & 15)) * FROW + ks * 32 + (lane >> 4) * 16;
        LDSM4(qf[ks], sQ + ao);
    }

    float accO[8][4];
#pragma unroll
    for (int i = 0; i < 8; i++)
#pragma unroll
        for (int j = 0; j < 4; j++) accO[i][j] = 0.f;
    float mrow0 = -INFINITY, mrow1 = -INFINITY, lrow0 = 0.f, lrow1 = 0.f;
    const float SC = 0.125f * 1.44269504f;

    for (int kt = 0; kt <= qt; kt++) {
        __syncthreads();
        for (int i = tid; i < 512; i += 128) {
            int r = i >> 3, ch = i & 7;
            *(uint4*)(pS + FTILE + r * FROW + ch * 16) =
                *(const uint4*)(Kp + (size_t)(kt * 64 + r) * HEADD + ch * 8);
            *(uint4*)(pS + 2*FTILE + r * FROW + ch * 16) =
                *(const uint4*)(Vp + (size_t)r * SEQ + kt * 64 + ch * 8);
        }
        __syncthreads();

        float sacc[8][4];
#pragma unroll
        for (int nt = 0; nt < 8; nt++)
#pragma unroll
            for (int j = 0; j < 4; j++) sacc[nt][j] = 0.f;
#pragma unroll
        for (int ks = 0; ks < 4; ks++) {
#pragma unroll
            for (int nt = 0; nt < 8; nt++) {
                uint32_t k2[2];
                uint32_t bo = (uint32_t)(nt * 8 + (lane & 7)) * FROW + ks * 32 + ((lane >> 3) & 1) * 16;
                LDSM2(k2, sK + bo);
                MMA_F16(sacc[nt], qf[ks], k2);
            }
        }

        int grow = qt * 64 + w * 16 + (lane >> 2);
        if (kt == qt) {
#pragma unroll
            for (int nt = 0; nt < 8; nt++) {
                int cbase = kt * 64 + nt * 8 + (lane & 3) * 2;
                sacc[nt][0] = (cbase     <= grow    ) ? sacc[nt][0] * SC : -1e30f;
                sacc[nt][1] = (cbase + 1 <= grow    ) ? sacc[nt][1] * SC : -1e30f;
                sacc[nt][2] = (cbase     <= grow + 8) ? sacc[nt][2] * SC : -1e30f;
                sacc[nt][3] = (cbase + 1 <= grow + 8) ? sacc[nt][3] * SC : -1e30f;
            }
        } else {
#pragma unroll
            for (int nt = 0; nt < 8; nt++)
#pragma unroll
                for (int j = 0; j < 4; j++) sacc[nt][j] *= SC;
        }

        float mx0 = -INFINITY, mx1 = -INFINITY;
#pragma unroll
        for (int nt = 0; nt < 8; nt++) {
            mx0 = fmaxf(mx0, fmaxf(sacc[nt][0], sacc[nt][1]));
            mx1 = fmaxf(mx1, fmaxf(sacc[nt][2], sacc[nt][3]));
        }
        mx0 = fmaxf(mx0, __shfl_xor_sync(0xffffffffu, mx0, 1));
        mx0 = fmaxf(mx0, __shfl_xor_sync(0xffffffffu, mx0, 2));
        mx1 = fmaxf(mx1, __shfl_xor_sync(0xffffffffu, mx1, 1));
        mx1 = fmaxf(mx1, __shfl_xor_sync(0xffffffffu, mx1, 2));
        float mn0 = fmaxf(mrow0, mx0), mn1 = fmaxf(mrow1, mx1);
        float al0 = exp2f(mrow0 - mn0), al1 = exp2f(mrow1 - mn1);
        mrow0 = mn0; mrow1 = mn1;
#pragma unroll
        for (int nt = 0; nt < 8; nt++) {
            accO[nt][0] *= al0; accO[nt][1] *= al0;
            accO[nt][2] *= al1; accO[nt][3] *= al1;
        }
        lrow0 *= al0; lrow1 *= al1;

        float sum0 = 0.f, sum1 = 0.f;
#pragma unroll
        for (int ks = 0; ks < 4; ks++) {
            float p[2][4];
#pragma unroll
            for (int h2 = 0; h2 < 2; h2++) {
                int nt = ks * 2 + h2;
                p[h2][0] = exp2f(sacc[nt][0] - mn0);
                p[h2][1] = exp2f(sacc[nt][1] - mn0);
                p[h2][2] = exp2f(sacc[nt][2] - mn1);
                p[h2][3] = exp2f(sacc[nt][3] - mn1);
                sum0 += p[h2][0] + p[h2][1];
                sum1 += p[h2][2] + p[h2][3];
            }
            uint32_t pf[4];
            pf[0] = pack2(p[0][0], p[0][1]);
            pf[1] = pack2(p[0][2], p[0][3]);
            pf[2] = pack2(p[1][0], p[1][1]);
            pf[3] = pack2(p[1][2], p[1][3]);
#pragma unroll
            for (int ntd = 0; ntd < 8; ntd++) {
                uint32_t v2[2];
                uint32_t vo = (uint32_t)(ntd * 8 + (lane & 7)) * FROW + ks * 32 + ((lane >> 3) & 1) * 16;
                LDSM2(v2, sV + vo);
                MMA_F16(accO[ntd], pf, v2);
            }
        }
        sum0 += __shfl_xor_sync(0xffffffffu, sum0, 1);
        sum0 += __shfl_xor_sync(0xffffffffu, sum0, 2);
        sum1 += __shfl_xor_sync(0xffffffffu, sum1, 1);
        sum1 += __shfl_xor_sync(0xffffffffu, sum1, 2);
        lrow0 += sum0; lrow1 += sum1;
    }

    float inv0 = 1.f / lrow0, inv1 = 1.f / lrow1;
    int row0 = qt * 64 + w * 16 + (lane >> 2);
    size_t rb = ((size_t)bb * SEQ + row0) * HDIM + hh * HEADD + (lane & 3) * 2;
#pragma unroll
    for (int ntd = 0; ntd < 8; ntd++) {
        *(uint32_t*)(g_ox + rb + ntd * 8) = pack2(accO[ntd][0] * inv0, accO[ntd][1] * inv0);
        *(uint32_t*)(g_ox + rb + 8 * HDIM + ntd * 8) = pack2(accO[ntd][2] * inv1, accO[ntd][3] * inv1);
    }
}

// ================= MoE gating =================
__global__ void gate_kernel(const float* __restrict__ gw) {
    int t = blockIdx.x * 8 + (threadIdx.x >> 5);
    int lane = threadIdx.x & 31;
    const float* xr = g_x1n + (size_t)t * HDIM;
    float acc[8] = {0, 0, 0, 0, 0, 0, 0, 0};
    for (int j = lane; j < HDIM; j += 32) {
        float xv = xr[j];
        const float* gr = gw + j * 8;
        float4 g0 = *(const float4*)gr, g1 = *(const float4*)(gr + 4);
        acc[0] += xv * g0.x; acc[1] += xv * g0.y; acc[2] += xv * g0.z; acc[3] += xv * g0.w;
        acc[4] += xv * g1.x; acc[5] += xv * g1.y; acc[6] += xv * g1.z; acc[7] += xv * g1.w;
    }
#pragma unroll
    for (int e = 0; e < 8; e++)
        for (int o = 16; o; o >>= 1) acc[e] += __shfl_xor_sync(0xffffffffu, acc[e], o);
    if (lane == 0) {
        float mx = acc[0];
#pragma unroll
        for (int e = 1; e < 8; e++) mx = fmaxf(mx, acc[e]);
        float se = 0.f;
#pragma unroll
        for (int e = 0; e < 8; e++) se += expf(acc[e] - mx);
        float lse = mx + logf(se);
        g_lse2[t] = lse * lse;
        int i0 = 0; float v0 = acc[0];
#pragma unroll
        for (int e = 1; e < 8; e++) if (acc[e] > v0) { v0 = acc[e]; i0 = e; }
        int i1 = -1; float v1 = -INFINITY;
#pragma unroll
        for (int e = 0; e < 8; e++) if (e != i0 && acc[e] > v1) { v1 = acc[e]; i1 = e; }
        float w0 = 1.f / (1.f + expf(v1 - v0));
        float w1 = 1.f - w0;
        int p0 = atomicAdd(&g_cnt[i0], 1);
        g_rows[i0 * T_TOK + p0] = t;
        int p1 = atomicAdd(&g_cnt[i1], 1);
        g_rows[i1 * T_TOK + p1] = t;
        g_ie[2*t] = i0; g_islot[2*t] = p0; g_iw[2*t] = w0;
        g_ie[2*t+1] = i1; g_islot[2*t+1] = p1; g_iw[2*t+1] = w1;
    }
}

__global__ void aux_kernel(float* __restrict__ out) {
    __shared__ float red[32];
    float s = 0.f;
    for (int i = threadIdx.x; i < T_TOK; i += 1024) s += g_lse2[i];
    for (int o = 16; o; o >>= 1) s += __shfl_xor_sync(0xffffffffu, s, o);
    if ((threadIdx.x & 31) == 0) red[threadIdx.x >> 5] = s;
    __syncthreads();
    if (threadIdx.x < 32) {
        float v = red[threadIdx.x];
        for (int o = 16; o; o >>= 1) v += __shfl_xor_sync(0xffffffffu, v, o);
        if (threadIdx.x == 0) out[(size_t)T_TOK * HDIM] = 0.001f * v / (float)T_TOK;
    }
}

__global__ void gather_kernel() {
    int e = blockIdx.y, r = blockIdx.x;
    if (r >= g_cnt[e]) return;
    int t = g_rows[e * T_TOK + r];
    float4 v = ((const float4*)(g_x1n + (size_t)t * HDIM))[threadIdx.x];
    size_t o = ((size_t)e * T_TOK + r) * HDIM + threadIdx.x * 4;
    uint2 hv; hv.x = pack2(v.x, v.y); hv.y = pack2(v.z, v.w);
    *(uint2*)(g_xg + o) = hv;
}

__global__ void combine_kernel(float* __restrict__ out) {
    int t = blockIdx.x;
    int i0 = g_ie[2*t], i1 = g_ie[2*t+1];
    int p0 = g_islot[2*t], p1 = g_islot[2*t+1];
    float w0 = g_iw[2*t], w1 = g_iw[2*t+1];
    const float4* d0 = (const float4*)(g_dg + ((size_t)i0 * T_TOK + p0) * HDIM);
    const float4* d1 = (const float4*)(g_dg + ((size_t)i1 * T_TOK + p1) * HDIM);
    const float4* xr = (const float4*)(g_x1 + (size_t)t * HDIM);
    float4* o = (float4*)(out + (size_t)t * HDIM);
    int c = threadIdx.x;
    float4 a = xr[c], b0 = d0[c], b1 = d1[c];
    a.x += w0 * b0.x + w1 * b1.x;
    a.y += w0 * b0.y + w1 * b1.y;
    a.z += w0 * b0.z + w1 * b1.z;
    a.w += w0 * b0.w + w1 * b1.w;
    o[c] = a;
}

// ================= launch =================
#define GSA(var, sym) do { void* _p; cudaGetSymbolAddress(&_p, sym); var = (decltype(var))_p; } while (0)

extern "C" void kernel_launch(void* const* d_in, const int* in_sizes, int n_in,
                              void* d_out, int out_size) {
    const float* hidden = (const float*)d_in[0];
    const float* wq    = (const float*)d_in[2];
    const float* wk    = (const float*)d_in[3];
    const float* wv    = (const float*)d_in[4];
    const float* wo    = (const float*)d_in[5];
    const float* ln1   = (const float*)d_in[6];
    const float* ln2   = (const float*)d_in[7];
    const float* gw    = (const float*)d_in[8];
    const float* wgate = (const float*)d_in[9];
    const float* wup   = (const float*)d_in[10];
    const float* wdown = (const float*)d_in[11];
    float* out = (float*)d_out;

    float *qkv, *x1, *x1n, *dg;
    int* cnt;
    __half *ax, *ox, *xg, *hg;
    __half *wqkvp, *wop, *wgup, *wdnp;
    GSA(qkv, g_qkv); GSA(x1, g_x1); GSA(x1n, g_x1n);
    GSA(dg, g_dg); GSA(cnt, g_cnt);
    GSA(ax, g_ax); GSA(ox, g_ox); GSA(xg, g_xg); GSA(hg, g_hg);
    GSA(wqkvp, g_wqkv); GSA(wop, g_wo); GSA(wgup, g_wgu); GSA(wdnp, g_wdn);

    cudaFuncSetAttribute((const void*)tmma_kernel,
                         cudaFuncAttributeMaxDynamicSharedMemorySize, TMMA_SMEM_SILU);
    cudaFuncSetAttribute((const void*)flashmma_kernel,
                         cudaFuncAttributeMaxDynamicSharedMemorySize, FLASH_SMEM);

    // --- side stream + events (created once, before first capture) ---
    static cudaStream_t s1 = nullptr;
    static cudaEvent_t evFork = nullptr, evWo = nullptr, evWgu = nullptr;
    if (!s1) {
        cudaStreamCreateWithFlags(&s1, cudaStreamNonBlocking);
        cudaEventCreateWithFlags(&evFork, cudaEventDisableTiming);
        cudaEventCreateWithFlags(&evWo, cudaEventDisableTiming);
        cudaEventCreateWithFlags(&evWgu, cudaEventDisableTiming);
    }

    // fork: side stream handles O/MoE weight conversions in parallel
    cudaEventRecord(evFork, 0);
    cudaStreamWaitEvent(s1, evFork, 0);

    // side stream: wo first (needed earliest), then MoE weights
    wconv_kernel<<<dim3(12, 12, 1), 256, 0, s1>>>(wo, wop, HDIM, HDIM, 0, 0, 0, 0);
    cudaEventRecord(evWo, s1);
    wconv_kernel<<<dim3(32, 12, NEXP), 256, 0, s1>>>(wgate, wgup, HDIM, IDIM,
                                                     (size_t)HDIM*IDIM, (size_t)2*IDIM*HDIM, 1, 0);
    wconv_kernel<<<dim3(32, 12, NEXP), 256, 0, s1>>>(wup, wgup, HDIM, IDIM,
                                                     (size_t)HDIM*IDIM, (size_t)2*IDIM*HDIM, 2, 0);
    wconv_kernel<<<dim3(12, 32, NEXP), 256, 0, s1>>>(wdown, wdnp, IDIM, HDIM,
                                                     (size_t)IDIM*HDIM, (size_t)HDIM*IDIM, 0, 0);
    cudaEventRecord(evWgu, s1);

    // main stream: QKV weight conversion + attention chain
    wconv_kernel<<<dim3(12, 12, 1), 256>>>(wq, wqkvp, HDIM, HDIM, 0, 0, 0, 0);
    wconv_kernel<<<dim3(12, 12, 1), 256>>>(wk, wqkvp, HDIM, HDIM, 0, 0, 0, 768);
    wconv_kernel<<<dim3(12, 12, 1), 256>>>(wv, wqkvp, HDIM, HDIM, 0, 0, 0, 1536);

    rmsnorm_f16_kernel<<<T_TOK, 256>>>(hidden, ln1, ax);

    tmma_kernel<<<dim3(18, 32, 1), 256, TMMA_SMEM_PLAIN>>>(ax, wqkvp, qkv,
        T_TOK, nullptr, 2304, HDIM, nullptr, 0, 0, 0, nullptr, 0);

    rope_table_kernel<<<(SEQ * 32 + 255) / 256, 256>>>();
    rope_kernel<<<dim3(SEQ, NHEADS, BATCH), 64>>>();

    flashmma_kernel<<<dim3(32, NHEADS, BATCH), 128, FLASH_SMEM>>>();

    // join: need wo before output projection
    cudaStreamWaitEvent(0, evWo, 0);
    tmma_kernel<<<dim3(6, 32, 1), 256, TMMA_SMEM_PLAIN>>>(ox, wop, x1,
        T_TOK, nullptr, HDIM, HDIM, hidden, 0, 0, 0, nullptr, 0);

    rmsnorm_f32_kernel<<<T_TOK, 256>>>(x1, ln2, x1n);

    gate_kernel<<<T_TOK / 8, 256>>>(gw);
    aux_kernel<<<1, 1024>>>(out);

    gather_kernel<<<dim3(T_TOK, NEXP), 192>>>();

    // join: need MoE weights before expert GEMMs
    cudaStreamWaitEvent(0, evWgu, 0);
    tmma_kernel<<<dim3(32, 32, NEXP), 256, TMMA_SMEM_SILU>>>(xg, wgup, nullptr,
        0, cnt, 2 * IDIM, HDIM, nullptr,
        (size_t)T_TOK * HDIM, (size_t)2 * IDIM * HDIM, (size_t)T_TOK * IDIM, hg, 1);
    tmma_kernel<<<dim3(6, 32, NEXP), 256, TMMA_SMEM_PLAIN>>>(hg, wdnp, dg,
        0, cnt, HDIM, IDIM, nullptr,
        (size_t)T_TOK * IDIM, (size_t)HDIM * IDIM, (size_t)T_TOK * HDIM, nullptr, 0);

    combine_kernel<<<T_TOK, 192>>>(out);
}

// round 10
// speedup vs baseline: 11.5345x; 1.0019x over previous
#include <cuda_runtime.h>
#include <cuda_fp16.h>
#include <math.h>
#include <stdint.h>

// ---- problem constants ----
#define T_TOK 4096      // B*S
#define SEQ   2048
#define BATCH 2
#define HDIM  768
#define NHEADS 12
#define HEADD 64
#define IDIM  2048
#define NEXP  8

// ---- fp32 scratch ----
__device__ __align__(128) float g_x1  [T_TOK*HDIM];
__device__ __align__(128) float g_x1n [T_TOK*HDIM];
__device__ __align__(128) float g_dg  [(size_t)NEXP*T_TOK*HDIM];
__device__ float g_cos [SEQ*32];
__device__ float g_sin [SEQ*32];
__device__ float g_lse2[T_TOK];
__device__ int   g_cnt [NEXP];
__device__ int   g_ie  [2*T_TOK];
__device__ int   g_islot[2*T_TOK];
__device__ float g_iw  [2*T_TOK];

// ---- fp16 activations ----
__device__ __align__(128) __half g_ax  [T_TOK*HDIM];
__device__ __align__(128) __half g_qkvh[T_TOK*2304];
__device__ __align__(128) __half g_qx  [T_TOK*HDIM];   // [b,h,s,d]
__device__ __align__(128) __half g_kx  [T_TOK*HDIM];
__device__ __align__(128) __half g_vtx [T_TOK*HDIM];   // [b,h,d,s]
__device__ __align__(128) __half g_ox  [T_TOK*HDIM];
__device__ __align__(128) __half g_xg  [(size_t)NEXP*T_TOK*HDIM];
__device__ __align__(128) __half g_hg  [(size_t)NEXP*T_TOK*IDIM];

// ---- fp16 weights ([N,K] K-major; gate/up interleaved 64-row groups) ----
__device__ __align__(128) __half g_wqkv[2304*HDIM];
__device__ __align__(128) __half g_wo  [HDIM*HDIM];
__device__ __align__(128) __half g_wgu [(size_t)NEXP*2*IDIM*HDIM];
__device__ __align__(128) __half g_wdn [(size_t)NEXP*HDIM*IDIM];

// ================= helpers =================
__device__ __forceinline__ uint32_t s2u(const void* p) {
    uint32_t a;
    asm("{ .reg .u64 t; cvta.to.shared.u64 t, %1; cvt.u32.u64 %0, t; }" : "=r"(a) : "l"(p));
    return a;
}
__device__ __forceinline__ uint32_t pack2(float a, float b) {
    __half2 h2 = __halves2half2(__float2half_rn(a), __float2half_rn(b));
    return *(uint32_t*)&h2;
}

#define LDSM4(r, a) \
    asm volatile("ldmatrix.sync.aligned.m8n8.x4.shared.b16 {%0,%1,%2,%3}, [%4];" \
        : "=r"((r)[0]), "=r"((r)[1]), "=r"((r)[2]), "=r"((r)[3]) : "r"(a))
#define LDSM2(r, a) \
    asm volatile("ldmatrix.sync.aligned.m8n8.x2.shared.b16 {%0,%1}, [%2];" \
        : "=r"((r)[0]), "=r"((r)[1]) : "r"(a))
#define MMA_F16(c, a, b) \
    asm volatile("mma.sync.aligned.m16n8k16.row.col.f32.f16.f16.f32 " \
        "{%0,%1,%2,%3}, {%4,%5,%6,%7}, {%8,%9}, {%0,%1,%2,%3};" \
        : "+f"((c)[0]), "+f"((c)[1]), "+f"((c)[2]), "+f"((c)[3]) \
        : "r"((a)[0]), "r"((a)[1]), "r"((a)[2]), "r"((a)[3]), "r"((b)[0]), "r"((b)[1]))
#define CP_ASYNC16(dst, src) \
    asm volatile("cp.async.cg.shared.global [%0], [%1], 16;" :: "r"(dst), "l"(src))

// ================= weight transpose + fp16 round =================
__global__ __launch_bounds__(256) void wconv_kernel(
    const float* __restrict__ W, __half* __restrict__ oh, int K, int N,
    size_t inZ, size_t outZ, int mode, int dstOff)
{
    W  += (size_t)blockIdx.z * inZ;
    oh += (size_t)blockIdx.z * outZ;
    __shared__ float s[64][65];
    int n0 = blockIdx.x * 64, k0 = blockIdx.y * 64;
    int tid = threadIdx.x;
    int lr = tid >> 4;
    int lc = (tid & 15) * 4;
#pragma unroll
    for (int p = 0; p < 4; p++) {
        int kk = p * 16 + lr;
        float4 v = *(const float4*)(W + (size_t)(k0 + kk) * N + n0 + lc);
        s[lc + 0][kk] = v.x; s[lc + 1][kk] = v.y;
        s[lc + 2][kk] = v.z; s[lc + 3][kk] = v.w;
    }
    __syncthreads();
    int nl = tid >> 3;
    int kq = (tid & 7) * 8;
#pragma unroll
    for (int p = 0; p < 2; p++) {
        int nn = p * 32 + nl;
        int ng = n0 + nn;
        int nd = (mode == 0) ? ng : ((ng >> 6) * 128 + (ng & 63) + ((mode == 2) ? 64 : 0));
        nd += dstOff;
        __half hb[8];
#pragma unroll
        for (int j = 0; j < 8; j++) hb[j] = __float2half_rn(s[nn][kq + j]);
        *(uint4*)(oh + (size_t)nd * K + k0 + kq) = *(uint4*)hb;
    }
}

// ================= mma.sync fp16 GEMM (3-stage pipeline, batched) =================
// outMode: 0 = fp32 C (+Cadd), 1 = fused silu -> fp16 SO, 2 = plain fp16 SO
#define TMMA_SMEM_PLAIN 61440
#define TMMA_SMEM_SILU  67584

__global__ __launch_bounds__(256) void tmma_kernel(
    const __half* __restrict__ A, const __half* __restrict__ B,
    float* __restrict__ C, int M, const int* __restrict__ cntArr,
    int N, int K, const float* __restrict__ Cadd,
    size_t zsA, size_t zsB, size_t zsC,
    __half* __restrict__ SO, int outMode)
{
    int z = blockIdx.z;
    int m = cntArr ? cntArr[z] : M;
    int row0 = blockIdx.y * 128;
    if (row0 >= m) return;
    int col0 = blockIdx.x * 128;
    A += zsA * z; B += zsB * z;
    if (outMode == 0) C += zsC * z; else SO += zsC * z;

    extern __shared__ char sm[];
    uint32_t sbase = s2u(sm);
    int tid = threadIdx.x, lane = tid & 31, wid = tid >> 5;
    int wm = wid & 1, wn = wid >> 1;

    const __half* sp[2];
    sp[0] = A + (size_t)row0 * K;
    sp[1] = B + (size_t)col0 * K;

    float acc[4][4][4];
#pragma unroll
    for (int a = 0; a < 4; a++)
#pragma unroll
        for (int b = 0; b < 4; b++)
#pragma unroll
            for (int c = 0; c < 4; c++) acc[a][b][c] = 0.f;

    int NC = K >> 5;

#define LOAD_STAGE(cc, ss) do { \
    uint32_t _db = sbase + (ss) * 20480; \
    _Pragma("unroll") \
    for (int _t = 0; _t < 2; _t++) { \
        _Pragma("unroll") \
        for (int _i = 0; _i < 2; _i++) { \
            int _idx = tid + _i * 256; \
            int _r = _idx >> 2, _ch = _idx & 3; \
            uint32_t _dst = _db + _t * 10240 + _r * 80 + _ch * 16; \
            const void* _src = sp[_t] + (size_t)_r * K + (cc) * 32 + _ch * 8; \
            CP_ASYNC16(_dst, _src); \
        } \
    } \
    asm volatile("cp.async.commit_group;"); \
} while (0)

    LOAD_STAGE(0, 0);
    if (NC > 1) LOAD_STAGE(1, 1);

    int st = 0;
    for (int c = 0; c < NC; c++) {
        if (c + 2 < NC) {
            int s2 = st + 2; if (s2 >= 3) s2 -= 3;
            LOAD_STAGE(c + 2, s2);
            asm volatile("cp.async.wait_group 2;");
        } else if (c + 1 < NC) {
            asm volatile("cp.async.wait_group 1;");
        } else {
            asm volatile("cp.async.wait_group 0;");
        }
        __syncthreads();

        uint32_t db = sbase + st * 20480;
        uint32_t aT = db, bT = db + 10240;
#pragma unroll
        for (int ks = 0; ks < 2; ks++) {
            uint32_t af[4][4], bf[4][2];
            uint32_t aoff = (uint32_t)(wm * 64 + (lane & 15)) * 80 + ks * 32 + (lane >> 4) * 16;
            uint32_t boff = (uint32_t)(wn * 32 + (lane & 7)) * 80 + ks * 32 + ((lane >> 3) & 1) * 16;
#pragma unroll
            for (int mt = 0; mt < 4; mt++)
                LDSM4(af[mt], aT + aoff + mt * 1280);
#pragma unroll
            for (int nt = 0; nt < 4; nt++)
                LDSM2(bf[nt], bT + boff + nt * 640);
#pragma unroll
            for (int mt = 0; mt < 4; mt++)
#pragma unroll
                for (int nt = 0; nt < 4; nt++)
                    MMA_F16(acc[mt][nt], af[mt], bf[nt]);
        }
        __syncthreads();
        if (++st == 3) st = 0;
    }

    if (outMode == 1) {
        float* stg = (float*)sm;   // 128 x 132 floats
#pragma unroll
        for (int mt = 0; mt < 4; mt++) {
            int r = wm * 64 + mt * 16 + (lane >> 2);
            int cbase = wn * 32 + (lane & 3) * 2;
#pragma unroll
            for (int half = 0; half < 2; half++) {
#pragma unroll
                for (int nt = 0; nt < 4; nt++) {
                    float2 v; v.x = acc[mt][nt][half * 2 + 0]; v.y = acc[mt][nt][half * 2 + 1];
                    *(float2*)&stg[(r + half * 8) * 132 + cbase + nt * 8] = v;
                }
            }
        }
        __syncthreads();
        int lr = tid >> 4;
        int lc = (tid & 15) * 4;
        int colg = blockIdx.x * 64 + lc;
#pragma unroll
        for (int p = 0; p < 8; p++) {
            int r = p * 16 + lr;
            int gr = row0 + r;
            if (gr < m) {
                float4 gv = *(float4*)&stg[r * 132 + lc];
                float4 uv = *(float4*)&stg[r * 132 + 64 + lc];
                float f0 = gv.x / (1.f + expf(-gv.x)) * uv.x;
                float f1 = gv.y / (1.f + expf(-gv.y)) * uv.y;
                float f2 = gv.z / (1.f + expf(-gv.z)) * uv.z;
                float f3 = gv.w / (1.f + expf(-gv.w)) * uv.w;
                uint2 hv; hv.x = pack2(f0, f1); hv.y = pack2(f2, f3);
                *(uint2*)(SO + (size_t)gr * IDIM + colg) = hv;
            }
        }
        return;
    }

#pragma unroll
    for (int mt = 0; mt < 4; mt++) {
        int rbase = row0 + wm * 64 + mt * 16 + (lane >> 2);
#pragma unroll
        for (int half = 0; half < 2; half++) {
            int rr = rbase + half * 8;
            if (rr < m) {
                size_t o = (size_t)rr * N + col0 + wn * 32 + (lane & 3) * 2;
#pragma unroll
                for (int nt = 0; nt < 4; nt++) {
                    float v0 = acc[mt][nt][half * 2 + 0];
                    float v1 = acc[mt][nt][half * 2 + 1];
                    size_t oo = o + nt * 8;
                    if (outMode == 2) {
                        *(uint32_t*)(SO + oo) = pack2(v0, v1);
                    } else {
                        if (Cadd) {
                            float2 ad = *(const float2*)(Cadd + oo);
                            v0 += ad.x; v1 += ad.y;
                        }
                        float2 st2; st2.x = v0; st2.y = v1;
                        *(float2*)(C + oo) = st2;
                    }
                }
            }
        }
    }
}

// ================= RMSNorm =================
__device__ __forceinline__ float block_rms(const float* xr, int tid) {
    float s = 0.f;
    for (int c = tid; c < HDIM; c += 256) { float v = xr[c]; s += v * v; }
    __shared__ float red[8];
    for (int o = 16; o; o >>= 1) s += __shfl_xor_sync(0xffffffffu, s, o);
    if ((tid & 31) == 0) red[tid >> 5] = s;
    __syncthreads();
    if (tid < 8) {
        float v = red[tid];
        for (int o = 4; o; o >>= 1) v += __shfl_xor_sync(0xffu, v, o);
        if (tid == 0) red[0] = v;
    }
    __syncthreads();
    return rsqrtf(red[0] / (float)HDIM + 1e-6f);
}

__global__ void rmsnorm_f16_kernel(const float* __restrict__ x, const float* __restrict__ w,
                                   __half* __restrict__ oh) {
    int row = blockIdx.x;
    const float* xr = x + (size_t)row * HDIM;
    float scale = block_rms(xr, threadIdx.x);
    for (int c = threadIdx.x; c < HDIM; c += 256)
        oh[(size_t)row * HDIM + c] = __float2half_rn(w[c] * xr[c] * scale);
}

__global__ void rmsnorm_f32_kernel(const float* __restrict__ x, const float* __restrict__ w,
                                   float* __restrict__ out) {
    int row = blockIdx.x;
    if (row == 0 && threadIdx.x < NEXP) g_cnt[threadIdx.x] = 0;
    const float* xr = x + (size_t)row * HDIM;
    float scale = block_rms(xr, threadIdx.x);
    for (int c = threadIdx.x; c < HDIM; c += 256)
        out[(size_t)row * HDIM + c] = w[c] * xr[c] * scale;
}

// ================= RoPE =================
__global__ void rope_table_kernel() {
    int idx = blockIdx.x * blockDim.x + threadIdx.x;
    if (idx >= SEQ * 32) return;
    int i = idx & 31, s = idx >> 5;
    float inv = powf(10000.0f, -(float)i / 32.0f);
    float ang = (float)s * inv;
    g_cos[idx] = cosf(ang);
    g_sin[idx] = sinf(ang);
}

__global__ void rope_kernel() {
    int s = blockIdx.x, hh = blockIdx.y, bb = blockIdx.z, d = threadIdx.x;
    int t = bb * SEQ + s;
    const __half* qkv = g_qkvh + (size_t)t * 2304;
    int col  = hh * HEADD + d;
    int pcol = hh * HEADD + (d < 32 ? d + 32 : d - 32);
    float qv = __half2float(qkv[col]);
    float kv = __half2float(qkv[768 + col]);
    __half vv = qkv[1536 + col];
    float qp = __half2float(qkv[pcol]);
    float kp = __half2float(qkv[768 + pcol]);
    float cs = g_cos[s * 32 + (d & 31)], sn = g_sin[s * 32 + (d & 31)];
    float sgn = (d < 32) ? -1.f : 1.f;
    float qr = qv * cs + sgn * qp * sn;
    float kr = kv * cs + sgn * kp * sn;
    size_t dst = (((size_t)bb * NHEADS + hh) * SEQ + s) * HEADD + d;
    g_qx[dst] = __float2half_rn(qr);
    g_kx[dst] = __float2half_rn(kr);
    size_t vdst = (((size_t)bb * NHEADS + hh) * HEADD + d) * SEQ + s;
    g_vtx[vdst] = vv;
}

// ================= tensor-core flash attention (fp16) =================
#define FROW 144
#define FTILE 9216
#define FLASH_SMEM (3*FTILE)

__global__ __launch_bounds__(128) void flashmma_kernel() {
    int qt = 31 - (int)blockIdx.x;
    int hh = blockIdx.y, bb = blockIdx.z;
    extern __shared__ char fsm[];
    uint32_t sb = s2u(fsm);
    uint32_t sQ = sb, sK = sb + FTILE, sV = sb + 2*FTILE;
    char* pS = fsm;

    int tid = threadIdx.x, lane = tid & 31, w = tid >> 5;
    size_t hb = (size_t)bb * NHEADS + hh;
    const __half* Qp = g_qx + hb * SEQ * HEADD;
    const __half* Kp = g_kx + hb * SEQ * HEADD;
    const __half* Vp = g_vtx + hb * HEADD * SEQ;

    for (int i = tid; i < 512; i += 128) {
        int r = i >> 3, ch = i & 7;
        *(uint4*)(pS + r * FROW + ch * 16) =
            *(const uint4*)(Qp + (size_t)(qt * 64 + r) * HEADD + ch * 8);
    }
    __syncthreads();

    uint32_t qf[4][4];
#pragma unroll
    for (int ks = 0; ks < 4; ks++) {
        uint32_t ao = (uint32_t)(w * 16 + (lane & 15)) * FROW + ks * 32 + (lane >> 4) * 16;
        LDSM4(qf[ks], sQ + ao);
    }

    float accO[8][4];
#pragma unroll
    for (int i = 0; i < 8; i++)
#pragma unroll
        for (int j = 0; j < 4; j++) accO[i][j] = 0.f;
    float mrow0 = -INFINITY, mrow1 = -INFINITY, lrow0 = 0.f, lrow1 = 0.f;
    const float SC = 0.125f * 1.44269504f;

    for (int kt = 0; kt <= qt; kt++) {
        __syncthreads();
        for (int i = tid; i < 512; i += 128) {
            int r = i >> 3, ch = i & 7;
            *(uint4*)(pS + FTILE + r * FROW + ch * 16) =
                *(const uint4*)(Kp + (size_t)(kt * 64 + r) * HEADD + ch * 8);
            *(uint4*)(pS + 2*FTILE + r * FROW + ch * 16) =
                *(const uint4*)(Vp + (size_t)r * SEQ + kt * 64 + ch * 8);
        }
        __syncthreads();

        float sacc[8][4];
#pragma unroll
        for (int nt = 0; nt < 8; nt++)
#pragma unroll
            for (int j = 0; j < 4; j++) sacc[nt][j] = 0.f;
#pragma unroll
        for (int ks = 0; ks < 4; ks++) {
#pragma unroll
            for (int nt = 0; nt < 8; nt++) {
                uint32_t k2[2];
                uint32_t bo = (uint32_t)(nt * 8 + (lane & 7)) * FROW + ks * 32 + ((lane >> 3) & 1) * 16;
                LDSM2(k2, sK + bo);
                MMA_F16(sacc[nt], qf[ks], k2);
            }
        }

        int grow = qt * 64 + w * 16 + (lane >> 2);
        if (kt == qt) {
#pragma unroll
            for (int nt = 0; nt < 8; nt++) {
                int cbase = kt * 64 + nt * 8 + (lane & 3) * 2;
                sacc[nt][0] = (cbase     <= grow    ) ? sacc[nt][0] * SC : -1e30f;
                sacc[nt][1] = (cbase + 1 <= grow    ) ? sacc[nt][1] * SC : -1e30f;
                sacc[nt][2] = (cbase     <= grow + 8) ? sacc[nt][2] * SC : -1e30f;
                sacc[nt][3] = (cbase + 1 <= grow + 8) ? sacc[nt][3] * SC : -1e30f;
            }
        } else {
#pragma unroll
            for (int nt = 0; nt < 8; nt++)
#pragma unroll
                for (int j = 0; j < 4; j++) sacc[nt][j] *= SC;
        }

        float mx0 = -INFINITY, mx1 = -INFINITY;
#pragma unroll
        for (int nt = 0; nt < 8; nt++) {
            mx0 = fmaxf(mx0, fmaxf(sacc[nt][0], sacc[nt][1]));
            mx1 = fmaxf(mx1, fmaxf(sacc[nt][2], sacc[nt][3]));
        }
        mx0 = fmaxf(mx0, __shfl_xor_sync(0xffffffffu, mx0, 1));
        mx0 = fmaxf(mx0, __shfl_xor_sync(0xffffffffu, mx0, 2));
        mx1 = fmaxf(mx1, __shfl_xor_sync(0xffffffffu, mx1, 1));
        mx1 = fmaxf(mx1, __shfl_xor_sync(0xffffffffu, mx1, 2));
        float mn0 = fmaxf(mrow0, mx0), mn1 = fmaxf(mrow1, mx1);
        float al0 = exp2f(mrow0 - mn0), al1 = exp2f(mrow1 - mn1);
        mrow0 = mn0; mrow1 = mn1;
#pragma unroll
        for (int nt = 0; nt < 8; nt++) {
            accO[nt][0] *= al0; accO[nt][1] *= al0;
            accO[nt][2] *= al1; accO[nt][3] *= al1;
        }
        lrow0 *= al0; lrow1 *= al1;

        float sum0 = 0.f, sum1 = 0.f;
#pragma unroll
        for (int ks = 0; ks < 4; ks++) {
            float p[2][4];
#pragma unroll
            for (int h2 = 0; h2 < 2; h2++) {
                int nt = ks * 2 + h2;
                p[h2][0] = exp2f(sacc[nt][0] - mn0);
                p[h2][1] = exp2f(sacc[nt][1] - mn0);
                p[h2][2] = exp2f(sacc[nt][2] - mn1);
                p[h2][3] = exp2f(sacc[nt][3] - mn1);
                sum0 += p[h2][0] + p[h2][1];
                sum1 += p[h2][2] + p[h2][3];
            }
            uint32_t pf[4];
            pf[0] = pack2(p[0][0], p[0][1]);
            pf[1] = pack2(p[0][2], p[0][3]);
            pf[2] = pack2(p[1][0], p[1][1]);
            pf[3] = pack2(p[1][2], p[1][3]);
#pragma unroll
            for (int ntd = 0; ntd < 8; ntd++) {
                uint32_t v2[2];
                uint32_t vo = (uint32_t)(ntd * 8 + (lane & 7)) * FROW + ks * 32 + ((lane >> 3) & 1) * 16;
                LDSM2(v2, sV + vo);
                MMA_F16(accO[ntd], pf, v2);
            }
        }
        sum0 += __shfl_xor_sync(0xffffffffu, sum0, 1);
        sum0 += __shfl_xor_sync(0xffffffffu, sum0, 2);
        sum1 += __shfl_xor_sync(0xffffffffu, sum1, 1);
        sum1 += __shfl_xor_sync(0xffffffffu, sum1, 2);
        lrow0 += sum0; lrow1 += sum1;
    }

    float inv0 = 1.f / lrow0, inv1 = 1.f / lrow1;
    int row0 = qt * 64 + w * 16 + (lane >> 2);
    size_t rb = ((size_t)bb * SEQ + row0) * HDIM + hh * HEADD + (lane & 3) * 2;
#pragma unroll
    for (int ntd = 0; ntd < 8; ntd++) {
        *(uint32_t*)(g_ox + rb + ntd * 8) = pack2(accO[ntd][0] * inv0, accO[ntd][1] * inv0);
        *(uint32_t*)(g_ox + rb + 8 * HDIM + ntd * 8) = pack2(accO[ntd][2] * inv1, accO[ntd][3] * inv1);
    }
}

// ================= MoE gating =================
__global__ void gate_kernel(const float* __restrict__ gw) {
    int t = blockIdx.x * 8 + (threadIdx.x >> 5);
    int lane = threadIdx.x & 31;
    const float* xr = g_x1n + (size_t)t * HDIM;
    float acc[8] = {0, 0, 0, 0, 0, 0, 0, 0};
    for (int j = lane; j < HDIM; j += 32) {
        float xv = xr[j];
        const float* gr = gw + j * 8;
        float4 g0 = *(const float4*)gr, g1 = *(const float4*)(gr + 4);
        acc[0] += xv * g0.x; acc[1] += xv * g0.y; acc[2] += xv * g0.z; acc[3] += xv * g0.w;
        acc[4] += xv * g1.x; acc[5] += xv * g1.y; acc[6] += xv * g1.z; acc[7] += xv * g1.w;
    }
#pragma unroll
    for (int e = 0; e < 8; e++)
        for (int o = 16; o; o >>= 1) acc[e] += __shfl_xor_sync(0xffffffffu, acc[e], o);
    if (lane == 0) {
        float mx = acc[0];
#pragma unroll
        for (int e = 1; e < 8; e++) mx = fmaxf(mx, acc[e]);
        float se = 0.f;
#pragma unroll
        for (int e = 0; e < 8; e++) se += expf(acc[e] - mx);
        float lse = mx + logf(se);
        g_lse2[t] = lse * lse;
        int i0 = 0; float v0 = acc[0];
#pragma unroll
        for (int e = 1; e < 8; e++) if (acc[e] > v0) { v0 = acc[e]; i0 = e; }
        int i1 = -1; float v1 = -INFINITY;
#pragma unroll
        for (int e = 0; e < 8; e++) if (e != i0 && acc[e] > v1) { v1 = acc[e]; i1 = e; }
        float w0 = 1.f / (1.f + expf(v1 - v0));
        float w1 = 1.f - w0;
        int p0 = atomicAdd(&g_cnt[i0], 1);
        int p1 = atomicAdd(&g_cnt[i1], 1);
        g_ie[2*t] = i0; g_islot[2*t] = p0; g_iw[2*t] = w0;
        g_ie[2*t+1] = i1; g_islot[2*t+1] = p1; g_iw[2*t+1] = w1;
    }
}

__global__ void aux_kernel(float* __restrict__ out) {
    __shared__ float red[32];
    float s = 0.f;
    for (int i = threadIdx.x; i < T_TOK; i += 1024) s += g_lse2[i];
    for (int o = 16; o; o >>= 1) s += __shfl_xor_sync(0xffffffffu, s, o);
    if ((threadIdx.x & 31) == 0) red[threadIdx.x >> 5] = s;
    __syncthreads();
    if (threadIdx.x < 32) {
        float v = red[threadIdx.x];
        for (int o = 16; o; o >>= 1) v += __shfl_xor_sync(0xffffffffu, v, o);
        if (threadIdx.x == 0) out[(size_t)T_TOK * HDIM] = 0.001f * v / (float)T_TOK;
    }
}

// flat gather over 2*T_TOK assignments
__global__ void gather_kernel() {
    int i = blockIdx.x;
    int t = i >> 1;
    int e = g_ie[i], slot = g_islot[i];
    float4 v = ((const float4*)(g_x1n + (size_t)t * HDIM))[threadIdx.x];
    size_t o = ((size_t)e * T_TOK + slot) * HDIM + threadIdx.x * 4;
    uint2 hv; hv.x = pack2(v.x, v.y); hv.y = pack2(v.z, v.w);
    *(uint2*)(g_xg + o) = hv;
}

__global__ void combine_kernel(float* __restrict__ out) {
    int t = blockIdx.x;
    int i0 = g_ie[2*t], i1 = g_ie[2*t+1];
    int p0 = g_islot[2*t], p1 = g_islot[2*t+1];
    float w0 = g_iw[2*t], w1 = g_iw[2*t+1];
    const float4* d0 = (const float4*)(g_dg + ((size_t)i0 * T_TOK + p0) * HDIM);
    const float4* d1 = (const float4*)(g_dg + ((size_t)i1 * T_TOK + p1) * HDIM);
    const float4* xr = (const float4*)(g_x1 + (size_t)t * HDIM);
    float4* o = (float4*)(out + (size_t)t * HDIM);
    int c = threadIdx.x;
    float4 a = xr[c], b0 = d0[c], b1 = d1[c];
    a.x += w0 * b0.x + w1 * b1.x;
    a.y += w0 * b0.y + w1 * b1.y;
    a.z += w0 * b0.z + w1 * b1.z;
    a.w += w0 * b0.w + w1 * b1.w;
    o[c] = a;
}

// ================= launch =================
#define GSA(var, sym) do { void* _p; cudaGetSymbolAddress(&_p, sym); var = (decltype(var))_p; } while (0)

extern "C" void kernel_launch(void* const* d_in, const int* in_sizes, int n_in,
                              void* d_out, int out_size) {
    const float* hidden = (const float*)d_in[0];
    const float* wq    = (const float*)d_in[2];
    const float* wk    = (const float*)d_in[3];
    const float* wv    = (const float*)d_in[4];
    const float* wo    = (const float*)d_in[5];
    const float* ln1   = (const float*)d_in[6];
    const float* ln2   = (const float*)d_in[7];
    const float* gw    = (const float*)d_in[8];
    const float* wgate = (const float*)d_in[9];
    const float* wup   = (const float*)d_in[10];
    const float* wdown = (const float*)d_in[11];
    float* out = (float*)d_out;

    float *x1, *x1n, *dg;
    int* cnt;
    __half *ax, *qkvh, *ox, *xg, *hg;
    __half *wqkvp, *wop, *wgup, *wdnp;
    GSA(x1, g_x1); GSA(x1n, g_x1n);
    GSA(dg, g_dg); GSA(cnt, g_cnt);
    GSA(ax, g_ax); GSA(qkvh, g_qkvh); GSA(ox, g_ox); GSA(xg, g_xg); GSA(hg, g_hg);
    GSA(wqkvp, g_wqkv); GSA(wop, g_wo); GSA(wgup, g_wgu); GSA(wdnp, g_wdn);

    cudaFuncSetAttribute((const void*)tmma_kernel,
                         cudaFuncAttributeMaxDynamicSharedMemorySize, TMMA_SMEM_SILU);
    cudaFuncSetAttribute((const void*)flashmma_kernel,
                         cudaFuncAttributeMaxDynamicSharedMemorySize, FLASH_SMEM);

    // --- side stream + events (created once on first, uncaptured call) ---
    static cudaStream_t s1 = nullptr;
    static cudaEvent_t evFork = nullptr, evWo = nullptr, evWgu = nullptr;
    if (!s1) {
        cudaStream_t tmp = nullptr;
        if (cudaStreamCreateWithFlags(&tmp, cudaStreamNonBlocking) == cudaSuccess && tmp) {
            cudaEventCreateWithFlags(&evFork, cudaEventDisableTiming);
            cudaEventCreateWithFlags(&evWo, cudaEventDisableTiming);
            cudaEventCreateWithFlags(&evWgu, cudaEventDisableTiming);
            s1 = tmp;
        }
    }
    bool fork = (s1 != nullptr);

    if (fork) {
        cudaEventRecord(evFork, 0);
        cudaStreamWaitEvent(s1, evFork, 0);
        wconv_kernel<<<dim3(12, 12, 1), 256, 0, s1>>>(wo, wop, HDIM, HDIM, 0, 0, 0, 0);
        cudaEventRecord(evWo, s1);
        wconv_kernel<<<dim3(32, 12, NEXP), 256, 0, s1>>>(wgate, wgup, HDIM, IDIM,
                                                         (size_t)HDIM*IDIM, (size_t)2*IDIM*HDIM, 1, 0);
        wconv_kernel<<<dim3(32, 12, NEXP), 256, 0, s1>>>(wup, wgup, HDIM, IDIM,
                                                         (size_t)HDIM*IDIM, (size_t)2*IDIM*HDIM, 2, 0);
        wconv_kernel<<<dim3(12, 32, NEXP), 256, 0, s1>>>(wdown, wdnp, IDIM, HDIM,
                                                         (size_t)IDIM*HDIM, (size_t)HDIM*IDIM, 0, 0);
        cudaEventRecord(evWgu, s1);
    } else {
        wconv_kernel<<<dim3(12, 12, 1), 256>>>(wo, wop, HDIM, HDIM, 0, 0, 0, 0);
        wconv_kernel<<<dim3(32, 12, NEXP), 256>>>(wgate, wgup, HDIM, IDIM,
                                                  (size_t)HDIM*IDIM, (size_t)2*IDIM*HDIM, 1, 0);
        wconv_kernel<<<dim3(32, 12, NEXP), 256>>>(wup, wgup, HDIM, IDIM,
                                                  (size_t)HDIM*IDIM, (size_t)2*IDIM*HDIM, 2, 0);
        wconv_kernel<<<dim3(12, 32, NEXP), 256>>>(wdown, wdnp, IDIM, HDIM,
                                                  (size_t)IDIM*HDIM, (size_t)HDIM*IDIM, 0, 0);
    }

    wconv_kernel<<<dim3(12, 12, 1), 256>>>(wq, wqkvp, HDIM, HDIM, 0, 0, 0, 0);
    wconv_kernel<<<dim3(12, 12, 1), 256>>>(wk, wqkvp, HDIM, HDIM, 0, 0, 0, 768);
    wconv_kernel<<<dim3(12, 12, 1), 256>>>(wv, wqkvp, HDIM, HDIM, 0, 0, 0, 1536);

    rmsnorm_f16_kernel<<<T_TOK, 256>>>(hidden, ln1, ax);

    // QKV projection -> fp16
    tmma_kernel<<<dim3(18, 32, 1), 256, TMMA_SMEM_PLAIN>>>(ax, wqkvp, nullptr,
        T_TOK, nullptr, 2304, HDIM, nullptr, 0, 0, 0, qkvh, 2);

    rope_table_kernel<<<(SEQ * 32 + 255) / 256, 256>>>();
    rope_kernel<<<dim3(SEQ, NHEADS, BATCH), 64>>>();

    flashmma_kernel<<<dim3(32, NHEADS, BATCH), 128, FLASH_SMEM>>>();

    if (fork) cudaStreamWaitEvent(0, evWo, 0);
    tmma_kernel<<<dim3(6, 32, 1), 256, TMMA_SMEM_PLAIN>>>(ox, wop, x1,
        T_TOK, nullptr, HDIM, HDIM, hidden, 0, 0, 0, nullptr, 0);

    rmsnorm_f32_kernel<<<T_TOK, 256>>>(x1, ln2, x1n);

    gate_kernel<<<T_TOK / 8, 256>>>(gw);
    aux_kernel<<<1, 1024>>>(out);

    gather_kernel<<<2 * T_TOK, 192>>>();

    if (fork) cudaStreamWaitEvent(0, evWgu, 0);
    tmma_kernel<<<dim3(32, 32, NEXP), 256, TMMA_SMEM_SILU>>>(xg, wgup, nullptr,
        0, cnt, 2 * IDIM, HDIM, nullptr,
        (size_t)T_TOK * HDIM, (size_t)2 * IDIM * HDIM, (size_t)T_TOK * IDIM, hg, 1);
    tmma_kernel<<<dim3(6, 32, NEXP), 256, TMMA_SMEM_PLAIN>>>(hg, wdnp, dg,
        0, cnt, HDIM, IDIM, nullptr,
        (size_t)T_TOK * IDIM, (size_t)HDIM * IDIM, (size_t)T_TOK * HDIM, nullptr, 0);

    combine_kernel<<<T_TOK, 192>>>(out);
}